// round 1
// baseline (speedup 1.0000x reference)
#include <cuda_runtime.h>
#include <math.h>

#define BATCH 16
#define C512  512
#define L0    80000
#define L1    16000
#define L2    4000
#define L3    2000
#define L4    1000
#define L5    500
#define KSTEP 12
#define HID   256
#define G3    768

// ---------------- scratch (static device globals; no allocation) ----------------
__device__ float g_buf1[BATCH*C512*L1];   // conv1 out / bn1
__device__ float g_buf2[BATCH*C512*L2];
__device__ float g_buf3[BATCH*C512*L3];
__device__ float g_buf4[BATCH*C512*L4];
__device__ float g_buf5[BATCH*C512*L5];   // z in (b,d,t) layout
__device__ float g_zm  [BATCH*C512*L5];   // masked z
__device__ float g_gi  [BATCH*G3*L5];     // input gates [b][g][t]
__device__ float g_h   [2*BATCH*HID];     // ping-pong hidden
__device__ int   g_bar [BATCH];           // per-batch barrier counters
__device__ float g_scale[C512];
__device__ float g_shift[C512];
__device__ float g_ct  [BATCH*HID];
__device__ float g_enc [KSTEP*BATCH*C512];
__device__ float g_pred[KSTEP*BATCH*C512];
__device__ float g_total[KSTEP*BATCH*BATCH];

// ---------------- conv1: direct (Cin=1, K=10, S=5, P=3) ----------------
__global__ void conv1_kernel(const float* __restrict__ x, const float* __restrict__ w) {
    int b = blockIdx.x >> 9;
    int o = blockIdx.x & 511;
    float wr[10];
#pragma unroll
    for (int k = 0; k < 10; k++) wr[k] = w[o*10 + k];
    const float* xb = x + (size_t)b * L0;
    float* ob = g_buf1 + ((size_t)b*C512 + o)*L1;
    for (int t = threadIdx.x; t < L1; t += blockDim.x) {
        int p0 = 5*t - 3;
        float s = 0.f;
#pragma unroll
        for (int k = 0; k < 10; k++) {
            int p = p0 + k;
            float xv = (p >= 0 && p < L0) ? xb[p] : 0.f;
            s += xv * wr[k];
        }
        ob[t] = s;
    }
}

// ---------------- BN stats: one block per channel, fp64 accumulate ----------------
__global__ void bnstats_kernel(const float* __restrict__ buf, const float* __restrict__ gamma,
                               const float* __restrict__ beta, int L) {
    int c = blockIdx.x;
    int Bn = BATCH * L;
    double s = 0.0, s2 = 0.0;
    for (int i = threadIdx.x; i < Bn; i += blockDim.x) {
        int b = i / L, l = i - b*L;
        float v = buf[((size_t)b*C512 + c)*L + l];
        s += v; s2 += (double)v * v;
    }
    __shared__ double rs[256], rq[256];
    rs[threadIdx.x] = s; rq[threadIdx.x] = s2;
    __syncthreads();
    for (int o = 128; o > 0; o >>= 1) {
        if (threadIdx.x < o) { rs[threadIdx.x] += rs[threadIdx.x+o]; rq[threadIdx.x] += rq[threadIdx.x+o]; }
        __syncthreads();
    }
    if (threadIdx.x == 0) {
        double mean = rs[0] / Bn;
        double var  = rq[0] / Bn - mean*mean;
        double scd  = (double)gamma[c] / sqrt(var + 1e-5);
        g_scale[c] = (float)scd;
        g_shift[c] = beta[c] - (float)(mean * scd);
    }
}

// ---------------- BN apply + ReLU (in place, vectorized) ----------------
__global__ void bnapply_kernel(float* __restrict__ buf, int L, int total4) {
    int stride = gridDim.x * blockDim.x;
    for (int idx = blockIdx.x*blockDim.x + threadIdx.x; idx < total4; idx += stride) {
        float4 v = ((float4*)buf)[idx];
        int c = ((idx*4) / L) & (C512-1);
        float sc = g_scale[c], sh = g_shift[c];
        v.x = fmaxf(v.x*sc+sh, 0.f);
        v.y = fmaxf(v.y*sc+sh, 0.f);
        v.z = fmaxf(v.z*sc+sh, 0.f);
        v.w = fmaxf(v.w*sc+sh, 0.f);
        ((float4*)buf)[idx] = v;
    }
}

// ---------------- generic conv-as-GEMM: Out[b][o][t] = sum_{c,kw} W[o][c*KW+kw]*In[b][c][S*t-P+kw]
// Tiles: 128 (M=o) x 64 (N=(b,t)), BK=16, 256 threads, 8x4 microtile.
__global__ void convgemm_kernel(const float* __restrict__ In, const float* __restrict__ W,
                                float* __restrict__ Out,
                                int Cin, int Lin, int O, int KW, int S, int P, int Lout) {
    __shared__ __align__(16) float As[16][128];
    __shared__ __align__(16) float Bs[16][68];
    int tid = threadIdx.x;
    int tx = tid & 15, ty = tid >> 4;
    int m0 = blockIdx.x * 128;
    int n0 = blockIdx.y * 64;
    int Kd = Cin * KW;
    float acc[8][4];
#pragma unroll
    for (int i = 0; i < 8; i++)
#pragma unroll
        for (int j = 0; j < 4; j++) acc[i][j] = 0.f;

    int lm  = tid >> 1;          // A row (0..127)
    int lk8 = (tid & 1) * 8;     // A k offset
    int bk  = tid >> 4;          // B k (0..15)
    int bn4 = (tid & 15) * 4;    // B n offset

    for (int kc = 0; kc < Kd; kc += 16) {
        const float* wp = W + (size_t)(m0 + lm) * Kd + kc + lk8;
        float4 a0 = *(const float4*)wp;
        float4 a1 = *(const float4*)(wp + 4);
        As[lk8+0][lm] = a0.x; As[lk8+1][lm] = a0.y; As[lk8+2][lm] = a0.z; As[lk8+3][lm] = a0.w;
        As[lk8+4][lm] = a1.x; As[lk8+5][lm] = a1.y; As[lk8+6][lm] = a1.z; As[lk8+7][lm] = a1.w;

        int kk = kc + bk;
        int c  = kk / KW;
        int kw = kk - c * KW;
#pragma unroll
        for (int i = 0; i < 4; i++) {
            int n = n0 + bn4 + i;
            int b = n / Lout;
            int t = n - b * Lout;
            int p = S * t - P + kw;
            float v = 0.f;
            if (p >= 0 && p < Lin) v = In[((size_t)b*Cin + c)*Lin + p];
            Bs[bk][bn4 + i] = v;
        }
        __syncthreads();
#pragma unroll
        for (int k = 0; k < 16; k++) {
            float4 av0 = *(const float4*)&As[k][ty*4];
            float4 av1 = *(const float4*)&As[k][64 + ty*4];
            float4 bv  = *(const float4*)&Bs[k][tx*4];
            float a[8] = {av0.x,av0.y,av0.z,av0.w,av1.x,av1.y,av1.z,av1.w};
            float bb[4] = {bv.x,bv.y,bv.z,bv.w};
#pragma unroll
            for (int i = 0; i < 8; i++)
#pragma unroll
                for (int j = 0; j < 4; j++)
                    acc[i][j] += a[i]*bb[j];
        }
        __syncthreads();
    }
#pragma unroll
    for (int i = 0; i < 8; i++) {
        int o = m0 + (i < 4 ? (ty*4 + i) : (64 + ty*4 + (i-4)));
#pragma unroll
        for (int j = 0; j < 4; j++) {
            int n = n0 + tx*4 + j;
            int b = n / Lout;
            int t = n - b*Lout;
            Out[((size_t)b*O + o)*Lout + t] = acc[i][j];
        }
    }
}

// ---------------- mask z (t <= t_samples[b]) ----------------
__global__ void maskz_kernel(const int* __restrict__ ts) {
    int idx = blockIdx.x*blockDim.x + threadIdx.x;
    if (idx >= BATCH*C512*L5) return;
    int t = idx % L5;
    int b = idx / (C512*L5);
    g_zm[idx] = (t <= ts[b]) ? g_buf5[idx] : 0.f;
}

// ---------------- GRU init ----------------
__global__ void gruinit_kernel(const float* __restrict__ hidden) {
    int i = blockIdx.x*blockDim.x + threadIdx.x;
    if (i < BATCH*HID) g_h[i] = hidden[i];
    if (i < BATCH)     g_bar[i] = 0;
}

// ---------------- persistent GRU: 128 blocks = 16 batches x 8 row-groups ----------------
// Whh chunk (96 rows x 256) resident in smem. Ping-pong hidden in L2 (.cg), per-batch spin barriers.
__global__ void gru_kernel(const float* __restrict__ gi, const float* __restrict__ whh,
                           const float* __restrict__ bih, const float* __restrict__ bhh,
                           const int* __restrict__ ts, float* __restrict__ out) {
    extern __shared__ float sm[];
    float* Ws   = sm;                 // 96*256 floats, layout [gate][k/4][j][k%4]
    float* h_s  = sm + 96*256;        // 256
    float* gh_s = h_s + 256;          // 96
    int b  = blockIdx.x >> 3;
    int j0 = (blockIdx.x & 7) * 32;
    int tid = threadIdx.x;
    int warp = tid >> 5, lane = tid & 31;

    for (int e = tid; e < 96*256; e += 128) {
        int gate = e >> 13;
        int rem  = e & 8191;
        int j    = rem >> 8;
        int k    = rem & 255;
        Ws[((gate*64 + (k>>2))*32 + j)*4 + (k&3)] = whh[((size_t)(gate*256 + j0 + j))*256 + k];
    }
    int tsb = ts[b];
    float bihr=0.f,bihz=0.f,bihn=0.f,bhhr=0.f,bhhz=0.f,bhhn=0.f;
    if (warp == 0) {
        bihr = bih[j0+lane]; bihz = bih[256+j0+lane]; bihn = bih[512+j0+lane];
        bhhr = bhh[j0+lane]; bhhz = bhh[256+j0+lane]; bhhn = bhh[512+j0+lane];
    }
    __syncthreads();

    for (int t = 0; t < L5; t++) {
        const float* hsrc = g_h + ((size_t)((t & 1)*BATCH + b))*HID;
        for (int e = tid; e < HID; e += 128) h_s[e] = __ldcg(hsrc + e);
        __syncthreads();
        if (warp < 3) {
            const float4* wp = (const float4*)Ws + warp*2048 + lane;
            const float4* hp = (const float4*)h_s;
            float acc = 0.f;
#pragma unroll
            for (int k4 = 0; k4 < 64; k4++) {
                float4 w = wp[k4*32];
                float4 h = hp[k4];
                acc += w.x*h.x + w.y*h.y + w.z*h.z + w.w*h.w;
            }
            gh_s[warp*32 + lane] = acc;
        }
        __syncthreads();
        if (warp == 0) {
            int j = j0 + lane;
            const float* gb = gi + (size_t)b*G3*L5 + t;
            float gir = gb[(size_t)j*L5]       + bihr;
            float giz = gb[(size_t)(256+j)*L5] + bihz;
            float gin = gb[(size_t)(512+j)*L5] + bihn;
            float ghr = gh_s[lane]    + bhhr;
            float ghz = gh_s[32+lane] + bhhz;
            float ghn = gh_s[64+lane] + bhhn;
            float r   = 1.f/(1.f + expf(-(gir+ghr)));
            float zg  = 1.f/(1.f + expf(-(giz+ghz)));
            float n   = tanhf(gin + r*ghn);
            float hold = h_s[j];
            float hnew = (1.f - zg)*n + zg*hold;
            __stcg(&g_h[((size_t)(((t+1)&1)*BATCH + b))*HID + j], hnew);
            if (t == tsb)   g_ct[b*HID + j] = hnew;
            if (t == L5-1)  out[2 + b*HID + j] = hnew;
            __threadfence();
        }
        __syncthreads();
        if (tid == 0) {
            atomicAdd(&g_bar[b], 1);
            int target = (t+1) << 3;
            while (*(volatile int*)&g_bar[b] < target) { }
        }
        __syncthreads();
    }
}

// ---------------- enc gather: enc[k][b][d] = z[b][ts[b]+k+1][d] ----------------
__global__ void enc_kernel(const int* __restrict__ ts) {
    int idx = blockIdx.x*blockDim.x + threadIdx.x;
    if (idx >= KSTEP*BATCH*C512) return;
    int d = idx & 511;
    int b = (idx >> 9) & 15;
    int k = idx >> 13;
    int t = ts[b] + k + 1;
    g_enc[idx] = g_buf5[((size_t)b*C512 + d)*L5 + t];
}

// ---------------- pred[k][b][d] = c_t[b] . Wk_w[k][d] + Wk_b[k][d] ----------------
__global__ void pred_kernel(const float* __restrict__ wkw, const float* __restrict__ wkb) {
    int k = blockIdx.x >> 4;
    int b = blockIdx.x & 15;
    __shared__ float cs[HID];
    if (threadIdx.x < HID) cs[threadIdx.x] = g_ct[b*HID + threadIdx.x];
    __syncthreads();
    int d = threadIdx.x; // 512 threads
    const float* wr = wkw + ((size_t)k*C512 + d)*HID;
    float acc = wkb[k*C512 + d];
#pragma unroll 8
    for (int h = 0; h < HID; h++) acc += cs[h]*wr[h];
    g_pred[(k*BATCH + b)*C512 + d] = acc;
}

// ---------------- total[k][b][c] = enc[k][b] . pred[k][c] ----------------
__global__ void total_kernel() {
    int k = blockIdx.x >> 4;
    int b = blockIdx.x & 15;
    int c = threadIdx.x;
    if (c < BATCH) {
        const float* e = g_enc  + ((size_t)(k*BATCH + b))*C512;
        const float* p = g_pred + ((size_t)(k*BATCH + c))*C512;
        float acc = 0.f;
        for (int d = 0; d < C512; d++) acc += e[d]*p[d];
        g_total[(k*BATCH + b)*BATCH + c] = acc;
    }
}

// ---------------- nce + accuracy ----------------
__global__ void final_kernel(float* __restrict__ out) {
    __shared__ float red[192];
    __shared__ float lse11[16];
    __shared__ float corr[16];
    int tid = threadIdx.x;  // exactly 192
    int k = tid >> 4, b = tid & 15;
    float contrib;
    {
        const float* row = g_total + tid*16;
        float mx = row[0];
        for (int c = 1; c < 16; c++) mx = fmaxf(mx, row[c]);
        float s = 0.f;
        for (int c = 0; c < 16; c++) s += expf(row[c]-mx);
        float lse = mx + logf(s);
        contrib = row[b] - lse;
        if (k == KSTEP-1) lse11[b] = lse;
    }
    red[tid] = contrib;
    __syncthreads();
    if (tid < 16) {
        int c = tid;
        const float* t11 = g_total + (KSTEP-1)*BATCH*BATCH;
        float best = -1e30f; int arg = -1;
        for (int bb = 0; bb < 16; bb++) {
            float v = expf(t11[bb*16 + c] - lse11[bb]);
            if (v > best) { best = v; arg = bb; }
        }
        corr[c] = (arg == c) ? 1.f : 0.f;
    }
    __syncthreads();
    if (tid == 0) {
        float s = 0.f;
        for (int i = 0; i < 192; i++) s += red[i];
        out[1] = s / (-1.f * BATCH * KSTEP);
        float a = 0.f;
        for (int i = 0; i < 16; i++) a += corr[i];
        out[0] = a / (float)BATCH;
    }
}

// ---------------- host ----------------
extern "C" void kernel_launch(void* const* d_in, const int* in_sizes, int n_in,
                              void* d_out, int out_size) {
    const float* x      = (const float*)d_in[0];
    const float* hidden = (const float*)d_in[1];
    const int*   ts     = (const int*)d_in[3];
    const float* w1     = (const float*)d_in[4];
    const float* w2     = (const float*)d_in[5];
    const float* w345   = (const float*)d_in[6];
    const float* gamma  = (const float*)d_in[7];
    const float* beta   = (const float*)d_in[8];
    const float* wih    = (const float*)d_in[9];
    const float* whh    = (const float*)d_in[10];
    const float* bih    = (const float*)d_in[11];
    const float* bhh    = (const float*)d_in[12];
    const float* wkw    = (const float*)d_in[13];
    const float* wkb    = (const float*)d_in[14];
    float* out = (float*)d_out;

    float *buf1, *buf2, *buf3, *buf4, *buf5, *zm, *gi;
    cudaGetSymbolAddress((void**)&buf1, g_buf1);
    cudaGetSymbolAddress((void**)&buf2, g_buf2);
    cudaGetSymbolAddress((void**)&buf3, g_buf3);
    cudaGetSymbolAddress((void**)&buf4, g_buf4);
    cudaGetSymbolAddress((void**)&buf5, g_buf5);
    cudaGetSymbolAddress((void**)&zm,   g_zm);
    cudaGetSymbolAddress((void**)&gi,   g_gi);

    // conv1 + bn0
    conv1_kernel<<<BATCH*C512, 256>>>(x, w1);
    bnstats_kernel<<<C512, 256>>>(buf1, gamma + 0*C512, beta + 0*C512, L1);
    bnapply_kernel<<<2048, 256>>>(buf1, L1, BATCH*C512*L1/4);

    // conv2 + bn1
    convgemm_kernel<<<dim3(4, BATCH*L2/64), 256>>>(buf1, w2, buf2, 512, L1, 512, 8, 4, 2, L2);
    bnstats_kernel<<<C512, 256>>>(buf2, gamma + 1*C512, beta + 1*C512, L2);
    bnapply_kernel<<<1024, 256>>>(buf2, L2, BATCH*C512*L2/4);

    // conv3 + bn2
    convgemm_kernel<<<dim3(4, BATCH*L3/64), 256>>>(buf2, w345 + 0*(512*512*4), buf3, 512, L2, 512, 4, 2, 1, L3);
    bnstats_kernel<<<C512, 256>>>(buf3, gamma + 2*C512, beta + 2*C512, L3);
    bnapply_kernel<<<512, 256>>>(buf3, L3, BATCH*C512*L3/4);

    // conv4 + bn3
    convgemm_kernel<<<dim3(4, BATCH*L4/64), 256>>>(buf3, w345 + 1*(512*512*4), buf4, 512, L3, 512, 4, 2, 1, L4);
    bnstats_kernel<<<C512, 256>>>(buf4, gamma + 3*C512, beta + 3*C512, L4);
    bnapply_kernel<<<256, 256>>>(buf4, L4, BATCH*C512*L4/4);

    // conv5 + bn4
    convgemm_kernel<<<dim3(4, BATCH*L5/64), 256>>>(buf4, w345 + 2*(512*512*4), buf5, 512, L4, 512, 4, 2, 1, L5);
    bnstats_kernel<<<C512, 256>>>(buf5, gamma + 4*C512, beta + 4*C512, L5);
    bnapply_kernel<<<128, 256>>>(buf5, L5, BATCH*C512*L5/4);

    // masked z -> input gates (GEMM with KW=1)
    maskz_kernel<<<(BATCH*C512*L5 + 255)/256, 256>>>(ts);
    convgemm_kernel<<<dim3(6, BATCH*L5/64), 256>>>(zm, wih, gi, 512, L5, G3, 1, 1, 0, L5);

    // GRU
    gruinit_kernel<<<16, 256>>>(hidden);
    int smem = (96*256 + 256 + 96) * (int)sizeof(float);
    cudaFuncSetAttribute(gru_kernel, cudaFuncAttributeMaxDynamicSharedMemorySize, smem);
    gru_kernel<<<128, 128, smem>>>(gi, whh, bih, bhh, ts, out);

    // head
    enc_kernel<<<(KSTEP*BATCH*C512 + 255)/256, 256>>>(ts);
    pred_kernel<<<KSTEP*BATCH, 512>>>(wkw, wkb);
    total_kernel<<<KSTEP*BATCH, 32>>>();
    final_kernel<<<1, 192>>>(out);
}

// round 4
// speedup vs baseline: 1.5772x; 1.5772x over previous
#include <cuda_runtime.h>
#include <cuda_bf16.h>
#include <math.h>
#include <stdint.h>

#define BATCH 16
#define C512  512
#define L0    80000
#define L1    16000
#define L2    4000
#define L3    2000
#define L4    1000
#define L5    500
#define KSTEP 12
#define HID   256
#define G3    768

// ---------------- scratch (static device globals; no allocation) ----------------
__device__ float g_buf1[BATCH*C512*L1];   // conv1 raw out
__device__ float g_buf2[BATCH*C512*L2];
__device__ float g_buf3[BATCH*C512*L3];
__device__ float g_buf4[BATCH*C512*L4];
__device__ float g_buf5[BATCH*C512*L5];   // conv5 raw out (z before bn4)
__device__ float g_gi  [BATCH*G3*L5];     // input gates [b][g][t]
__device__ float g_h   [2*BATCH*HID];     // ping-pong hidden
__device__ int   g_bar [BATCH];
__device__ float g_scales[5*C512];
__device__ float g_shifts[5*C512];
__device__ float g_ct  [BATCH*HID];
__device__ float g_enc [KSTEP*BATCH*C512];
__device__ float g_pred[KSTEP*BATCH*C512];
__device__ float g_total[KSTEP*BATCH*BATCH];

// bf16 hi/lo split weights (conv2 @0, conv3 @2M, conv4 @3M, conv5 @4M, wih @5M)
__device__ __nv_bfloat16 g_wh[6*1024*1024];
__device__ __nv_bfloat16 g_wl[6*1024*1024];
#define WOFF2   0
#define WOFF3   2097152
#define WOFF4   3145728
#define WOFF5   4194304
#define WOFFIH  5242880

// ================= weight split fp32 -> bf16 hi + lo =================
__global__ void wcvt_kernel(const float* __restrict__ W, __nv_bfloat16* __restrict__ Wh,
                            __nv_bfloat16* __restrict__ Wl, int n) {
    int i = blockIdx.x*blockDim.x + threadIdx.x;
    if (i < n) {
        float v = W[i];
        __nv_bfloat16 h = __float2bfloat16(v);
        Wh[i] = h;
        Wl[i] = __float2bfloat16(v - __bfloat162float(h));
    }
}

// ================= conv1: direct (Cin=1, K=10, S=5, P=3) =================
__global__ void conv1_kernel(const float* __restrict__ x, const float* __restrict__ w) {
    int b = blockIdx.x >> 9;
    int o = blockIdx.x & 511;
    float wr[10];
#pragma unroll
    for (int k = 0; k < 10; k++) wr[k] = w[o*10 + k];
    const float* xb = x + (size_t)b * L0;
    float* ob = g_buf1 + ((size_t)b*C512 + o)*L1;
    for (int t = threadIdx.x; t < L1; t += blockDim.x) {
        int p0 = 5*t - 3;
        float s = 0.f;
#pragma unroll
        for (int k = 0; k < 10; k++) {
            int p = p0 + k;
            float xv = (p >= 0 && p < L0) ? xb[p] : 0.f;
            s += xv * wr[k];
        }
        ob[t] = s;
    }
}

// ================= BN stats (fp64, exact) =================
__global__ void bnstats_kernel(const float* __restrict__ buf, const float* __restrict__ gamma,
                               const float* __restrict__ beta, int L, int layer) {
    int c = blockIdx.x;
    int Bn = BATCH * L;
    double s = 0.0, s2 = 0.0;
    for (int i = threadIdx.x; i < Bn; i += blockDim.x) {
        int b = i / L, l = i - b*L;
        float v = buf[((size_t)b*C512 + c)*L + l];
        s += v; s2 += (double)v * v;
    }
    __shared__ double rs[256], rq[256];
    rs[threadIdx.x] = s; rq[threadIdx.x] = s2;
    __syncthreads();
    for (int o = 128; o > 0; o >>= 1) {
        if (threadIdx.x < o) { rs[threadIdx.x] += rs[threadIdx.x+o]; rq[threadIdx.x] += rq[threadIdx.x+o]; }
        __syncthreads();
    }
    if (threadIdx.x == 0) {
        double mean = rs[0] / Bn;
        double var  = rq[0] / Bn - mean*mean;
        double scd  = (double)gamma[c] / sqrt(var + 1e-5);
        g_scales[layer*C512 + c] = (float)scd;
        g_shifts[layer*C512 + c] = beta[c] - (float)(mean * scd);
    }
}

// ================= mma.sync helpers =================
#define MMA16816(d, a, b) \
    asm volatile( \
        "mma.sync.aligned.m16n8k16.row.col.f32.bf16.bf16.f32 " \
        "{%0,%1,%2,%3}, {%4,%5,%6,%7}, {%8,%9}, {%0,%1,%2,%3};" \
        : "+f"((d)[0]), "+f"((d)[1]), "+f"((d)[2]), "+f"((d)[3]) \
        : "r"((a)[0]), "r"((a)[1]), "r"((a)[2]), "r"((a)[3]), \
          "r"((b)[0]), "r"((b)[1]))

// ================= tensor-core conv-as-GEMM (mma.sync bf16, 3-term) =================
// D[m=o][n=(b,t)] = sum_{k=(c,kw)} W[o][k] * bnrelu(In[b][c][S*t-P+kw])
// Block tile 128x128, K-chunk 32. 8 warps (2m x 4n), warp tile 64x32.
// Terms: AhBh + AlBh + AhBl (missing AlBl ~ 2^-18 relative).
#define SMSTRIDE 34

template<int KW, int S, int P, bool MASK>
__global__ void __launch_bounds__(256, 2) mmaconv_kernel(
    const float* __restrict__ In, const __nv_bfloat16* __restrict__ Wh,
    const __nv_bfloat16* __restrict__ Wl, float* __restrict__ Out,
    const int* __restrict__ ts, int bnlayer,
    int Cin, int Lin, int O, int Lout, int Kd, int Ntot)
{
    __shared__ __nv_bfloat16 sAh[128][SMSTRIDE];
    __shared__ __nv_bfloat16 sAl[128][SMSTRIDE];
    __shared__ __nv_bfloat16 sBh[128][SMSTRIDE];
    __shared__ __nv_bfloat16 sBl[128][SMSTRIDE];

    const int tid  = threadIdx.x;
    const int lane = tid & 31, w = tid >> 5;
    const int wm = (w >> 2) * 64, wn = (w & 3) * 32;
    const int m0 = blockIdx.x * 128, n0 = blockIdx.y * 128;
    const float* __restrict__ scale = g_scales + bnlayer*C512;
    const float* __restrict__ shift = g_shifts + bnlayer*C512;

    const int g = lane >> 2, tig = lane & 3;
    const int arow = tid >> 1, ak0 = (tid & 1) * 16;
    const int nchunks = Kd >> 5;

    float acc[4][4][4];
#pragma unroll
    for (int i = 0; i < 4; i++)
#pragma unroll
        for (int j = 0; j < 4; j++)
#pragma unroll
            for (int q = 0; q < 4; q++) acc[i][j][q] = 0.f;

    for (int c = 0; c < nchunks; c++) {
        const int k0 = c << 5;

        // ---- A tile: copy precomputed hi/lo weights into smem ----
        {
            const size_t go = (size_t)(m0 + arow)*Kd + k0 + ak0;
            uint4 ha = *(const uint4*)(Wh + go);
            uint4 hb = *(const uint4*)(Wh + go + 8);
            uint4 la = *(const uint4*)(Wl + go);
            uint4 lb = *(const uint4*)(Wl + go + 8);
            uint32_t* dh = (uint32_t*)&sAh[arow][ak0];
            uint32_t* dl = (uint32_t*)&sAl[arow][ak0];
            dh[0]=ha.x; dh[1]=ha.y; dh[2]=ha.z; dh[3]=ha.w;
            dh[4]=hb.x; dh[5]=hb.y; dh[6]=hb.z; dh[7]=hb.w;
            dl[0]=la.x; dl[1]=la.y; dl[2]=la.z; dl[3]=la.w;
            dl[4]=lb.x; dl[5]=lb.y; dl[6]=lb.z; dl[7]=lb.w;
        }

        // ---- B tile: im2col gather + BN/ReLU (+mask), hi/lo split ----
        {
            const int c0 = k0 / KW;
            const int ITS = 16 / KW;     // (128 * (32/KW)) / 256
#pragma unroll
            for (int it = 0; it < ITS; it++) {
                int idx = it*256 + tid;
                int nn = idx & 127;
                int cl = idx >> 7;
                int cch = c0 + cl;
                int n = n0 + nn;
                bool vn = (n < Ntot);
                int b = 0, t = 0;
                if (vn) { b = n / Lout; t = n - b*Lout; }
                const float* ip = In + ((size_t)(b*Cin + cch))*Lin;
                float sc = __ldg(scale + cch), sh = __ldg(shift + cch);
                bool ok = vn;
                if (MASK && ok) ok = (t <= __ldg(ts + b));
                const int pb = S*t - P;
                if (KW == 1) {
                    float v = 0.f;
                    if (ok) v = fmaxf(__ldg(ip + t)*sc + sh, 0.f);
                    __nv_bfloat16 hb16 = __float2bfloat16(v);
                    sBh[nn][cl] = hb16;
                    sBl[nn][cl] = __float2bfloat16(v - __bfloat162float(hb16));
                } else {
                    float v[KW > 1 ? KW : 2];
#pragma unroll
                    for (int kw = 0; kw < KW; kw++) {
                        int p = pb + kw;
                        float xv = 0.f;
                        if (ok && p >= 0 && p < Lin) xv = fmaxf(__ldg(ip + p)*sc + sh, 0.f);
                        v[kw] = xv;
                    }
#pragma unroll
                    for (int q = 0; q < KW/2; q++) {
                        __nv_bfloat162 h2, l2;
                        h2.x = __float2bfloat16(v[2*q]);
                        h2.y = __float2bfloat16(v[2*q+1]);
                        l2.x = __float2bfloat16(v[2*q]   - __bfloat162float(h2.x));
                        l2.y = __float2bfloat16(v[2*q+1] - __bfloat162float(h2.y));
                        *(__nv_bfloat162*)&sBh[nn][cl*KW + 2*q] = h2;
                        *(__nv_bfloat162*)&sBl[nn][cl*KW + 2*q] = l2;
                    }
                }
            }
        }
        __syncthreads();

        // ---- compute: 2 k16 steps x (AhBh, AlBh, AhBl) ----
#pragma unroll
        for (int ks = 0; ks < 32; ks += 16) {
            const int cb = ks + tig*2;
            uint32_t ah[4][4], al[4][4], bh[4][2];
#pragma unroll
            for (int mt = 0; mt < 4; mt++) {
                int r = wm + mt*16 + g;
                ah[mt][0] = *(const uint32_t*)&sAh[r][cb];
                ah[mt][1] = *(const uint32_t*)&sAh[r+8][cb];
                ah[mt][2] = *(const uint32_t*)&sAh[r][cb+8];
                ah[mt][3] = *(const uint32_t*)&sAh[r+8][cb+8];
                al[mt][0] = *(const uint32_t*)&sAl[r][cb];
                al[mt][1] = *(const uint32_t*)&sAl[r+8][cb];
                al[mt][2] = *(const uint32_t*)&sAl[r][cb+8];
                al[mt][3] = *(const uint32_t*)&sAl[r+8][cb+8];
            }
#pragma unroll
            for (int nt = 0; nt < 4; nt++) {
                int rn = wn + nt*8 + g;
                bh[nt][0] = *(const uint32_t*)&sBh[rn][cb];
                bh[nt][1] = *(const uint32_t*)&sBh[rn][cb+8];
            }
#pragma unroll
            for (int mt = 0; mt < 4; mt++)
#pragma unroll
                for (int nt = 0; nt < 4; nt++) MMA16816(acc[mt][nt], ah[mt], bh[nt]);
#pragma unroll
            for (int mt = 0; mt < 4; mt++)
#pragma unroll
                for (int nt = 0; nt < 4; nt++) MMA16816(acc[mt][nt], al[mt], bh[nt]);
            uint32_t bl[4][2];
#pragma unroll
            for (int nt = 0; nt < 4; nt++) {
                int rn = wn + nt*8 + g;
                bl[nt][0] = *(const uint32_t*)&sBl[rn][cb];
                bl[nt][1] = *(const uint32_t*)&sBl[rn][cb+8];
            }
#pragma unroll
            for (int mt = 0; mt < 4; mt++)
#pragma unroll
                for (int nt = 0; nt < 4; nt++) MMA16816(acc[mt][nt], ah[mt], bl[nt]);
        }
        __syncthreads();
    }

    // ---- epilogue ----
#pragma unroll
    for (int mt = 0; mt < 4; mt++) {
        int r = m0 + wm + mt*16 + g;
#pragma unroll
        for (int nt = 0; nt < 4; nt++) {
            int cc = n0 + wn + nt*8 + tig*2;
#pragma unroll
            for (int q = 0; q < 4; q++) {
                int n  = cc + (q & 1);
                int rr = r + (q >> 1)*8;
                if (n < Ntot) {
                    int b = n / Lout, t = n - b*Lout;
                    Out[((size_t)(b*O + rr))*Lout + t] = acc[mt][nt][q];
                }
            }
        }
    }
}

// ================= GRU =================
__global__ void gruinit_kernel(const float* __restrict__ hidden) {
    int i = blockIdx.x*blockDim.x + threadIdx.x;
    if (i < BATCH*HID) g_h[i] = hidden[i];
    if (i < BATCH)     g_bar[i] = 0;
}

__global__ void gru_kernel(const float* __restrict__ gi, const float* __restrict__ whh,
                           const float* __restrict__ bih, const float* __restrict__ bhh,
                           const int* __restrict__ ts, float* __restrict__ out) {
    extern __shared__ float smg[];
    float* Ws   = smg;                 // 96*256
    float* h_s  = smg + 96*256;        // 256
    float* gh_s = h_s + 256;           // 96
    int b  = blockIdx.x >> 3;
    int j0 = (blockIdx.x & 7) * 32;
    int tid = threadIdx.x;
    int warp = tid >> 5, lane = tid & 31;

    for (int e = tid; e < 96*256; e += 128) {
        int gate = e >> 13;
        int rem  = e & 8191;
        int j    = rem >> 8;
        int k    = rem & 255;
        Ws[((gate*64 + (k>>2))*32 + j)*4 + (k&3)] = whh[((size_t)(gate*256 + j0 + j))*256 + k];
    }
    int tsb = ts[b];
    float bihr=0.f,bihz=0.f,bihn=0.f,bhhr=0.f,bhhz=0.f,bhhn=0.f;
    if (warp == 0) {
        bihr = bih[j0+lane]; bihz = bih[256+j0+lane]; bihn = bih[512+j0+lane];
        bhhr = bhh[j0+lane]; bhhz = bhh[256+j0+lane]; bhhn = bhh[512+j0+lane];
    }
    __syncthreads();

    for (int t = 0; t < L5; t++) {
        const float* hsrc = g_h + ((size_t)((t & 1)*BATCH + b))*HID;
        for (int e = tid; e < HID; e += 128) h_s[e] = __ldcg(hsrc + e);
        __syncthreads();
        if (warp < 3) {
            const float4* wp = (const float4*)Ws + warp*2048 + lane;
            const float4* hp = (const float4*)h_s;
            float acc = 0.f;
#pragma unroll
            for (int k4 = 0; k4 < 64; k4++) {
                float4 w = wp[k4*32];
                float4 h = hp[k4];
                acc += w.x*h.x + w.y*h.y + w.z*h.z + w.w*h.w;
            }
            gh_s[warp*32 + lane] = acc;
        }
        __syncthreads();
        if (warp == 0) {
            int j = j0 + lane;
            const float* gb = gi + (size_t)b*G3*L5 + t;
            float gir = gb[(size_t)j*L5]       + bihr;
            float giz = gb[(size_t)(256+j)*L5] + bihz;
            float gin = gb[(size_t)(512+j)*L5] + bihn;
            float ghr = gh_s[lane]    + bhhr;
            float ghz = gh_s[32+lane] + bhhz;
            float ghn = gh_s[64+lane] + bhhn;
            float r   = 1.f/(1.f + expf(-(gir+ghr)));
            float zg  = 1.f/(1.f + expf(-(giz+ghz)));
            float n   = tanhf(gin + r*ghn);
            float hold = h_s[j];
            float hnew = (1.f - zg)*n + zg*hold;
            __stcg(&g_h[((size_t)(((t+1)&1)*BATCH + b))*HID + j], hnew);
            if (t == tsb)   g_ct[b*HID + j] = hnew;
            if (t == L5-1)  out[2 + b*HID + j] = hnew;
            __threadfence();
        }
        __syncthreads();
        if (tid == 0) {
            atomicAdd(&g_bar[b], 1);
            int target = (t+1) << 3;
            while (*(volatile int*)&g_bar[b] < target) { }
        }
        __syncthreads();
    }
}

// ================= head =================
__global__ void enc_kernel(const int* __restrict__ ts) {
    int idx = blockIdx.x*blockDim.x + threadIdx.x;
    if (idx >= KSTEP*BATCH*C512) return;
    int d = idx & 511;
    int b = (idx >> 9) & 15;
    int k = idx >> 13;
    int t = ts[b] + k + 1;
    float v = g_buf5[((size_t)b*C512 + d)*L5 + t];
    g_enc[idx] = fmaxf(v*g_scales[4*C512 + d] + g_shifts[4*C512 + d], 0.f);
}

__global__ void pred_kernel(const float* __restrict__ wkw, const float* __restrict__ wkb) {
    int k = blockIdx.x >> 4;
    int b = blockIdx.x & 15;
    __shared__ float cs[HID];
    if (threadIdx.x < HID) cs[threadIdx.x] = g_ct[b*HID + threadIdx.x];
    __syncthreads();
    int d = threadIdx.x; // 512 threads
    const float* wr = wkw + ((size_t)k*C512 + d)*HID;
    float acc = wkb[k*C512 + d];
#pragma unroll 8
    for (int h = 0; h < HID; h++) acc += cs[h]*wr[h];
    g_pred[(k*BATCH + b)*C512 + d] = acc;
}

__global__ void total_kernel() {
    int k = blockIdx.x >> 4;
    int b = blockIdx.x & 15;
    int c = threadIdx.x;
    if (c < BATCH) {
        const float* e = g_enc  + ((size_t)(k*BATCH + b))*C512;
        const float* p = g_pred + ((size_t)(k*BATCH + c))*C512;
        float acc = 0.f;
        for (int d = 0; d < C512; d++) acc += e[d]*p[d];
        g_total[(k*BATCH + b)*BATCH + c] = acc;
    }
}

__global__ void final_kernel(float* __restrict__ out) {
    __shared__ float red[192];
    __shared__ float lse11[16];
    __shared__ float corr[16];
    int tid = threadIdx.x;  // 192
    int k = tid >> 4, b = tid & 15;
    float contrib;
    {
        const float* row = g_total + tid*16;
        float mx = row[0];
        for (int c = 1; c < 16; c++) mx = fmaxf(mx, row[c]);
        float s = 0.f;
        for (int c = 0; c < 16; c++) s += expf(row[c]-mx);
        float lse = mx + logf(s);
        contrib = row[b] - lse;
        if (k == KSTEP-1) lse11[b] = lse;
    }
    red[tid] = contrib;
    __syncthreads();
    if (tid < 16) {
        int c = tid;
        const float* t11 = g_total + (KSTEP-1)*BATCH*BATCH;
        float best = -1e30f; int arg = -1;
        for (int bb = 0; bb < 16; bb++) {
            float v = expf(t11[bb*16 + c] - lse11[bb]);
            if (v > best) { best = v; arg = bb; }
        }
        corr[c] = (arg == c) ? 1.f : 0.f;
    }
    __syncthreads();
    if (tid == 0) {
        float s = 0.f;
        for (int i = 0; i < 192; i++) s += red[i];
        out[1] = s / (-1.f * BATCH * KSTEP);
        float a = 0.f;
        for (int i = 0; i < 16; i++) a += corr[i];
        out[0] = a / (float)BATCH;
    }
}

// ================= host =================
extern "C" void kernel_launch(void* const* d_in, const int* in_sizes, int n_in,
                              void* d_out, int out_size) {
    const float* x      = (const float*)d_in[0];
    const float* hidden = (const float*)d_in[1];
    const int*   ts     = (const int*)d_in[3];
    const float* w1     = (const float*)d_in[4];
    const float* w2     = (const float*)d_in[5];
    const float* w345   = (const float*)d_in[6];
    const float* gamma  = (const float*)d_in[7];
    const float* beta   = (const float*)d_in[8];
    const float* wih    = (const float*)d_in[9];
    const float* whh    = (const float*)d_in[10];
    const float* bih    = (const float*)d_in[11];
    const float* bhh    = (const float*)d_in[12];
    const float* wkw    = (const float*)d_in[13];
    const float* wkb    = (const float*)d_in[14];
    float* out = (float*)d_out;

    float *buf1, *buf2, *buf3, *buf4, *buf5, *gi;
    __nv_bfloat16 *wh, *wl;
    cudaGetSymbolAddress((void**)&buf1, g_buf1);
    cudaGetSymbolAddress((void**)&buf2, g_buf2);
    cudaGetSymbolAddress((void**)&buf3, g_buf3);
    cudaGetSymbolAddress((void**)&buf4, g_buf4);
    cudaGetSymbolAddress((void**)&buf5, g_buf5);
    cudaGetSymbolAddress((void**)&gi,   g_gi);
    cudaGetSymbolAddress((void**)&wh,   g_wh);
    cudaGetSymbolAddress((void**)&wl,   g_wl);

    // split weights to bf16 hi/lo
    wcvt_kernel<<<8192, 256>>>(w2,                  wh + WOFF2,  wl + WOFF2,  512*4096);
    wcvt_kernel<<<4096, 256>>>(w345 + 0*(512*512*4), wh + WOFF3,  wl + WOFF3,  512*2048);
    wcvt_kernel<<<4096, 256>>>(w345 + 1*(512*512*4), wh + WOFF4,  wl + WOFF4,  512*2048);
    wcvt_kernel<<<4096, 256>>>(w345 + 2*(512*512*4), wh + WOFF5,  wl + WOFF5,  512*2048);
    wcvt_kernel<<<1536, 256>>>(wih,                 wh + WOFFIH, wl + WOFFIH, 768*512);

    // conv1 (direct) + bn0 stats
    conv1_kernel<<<BATCH*C512, 256>>>(x, w1);
    bnstats_kernel<<<C512, 256>>>(buf1, gamma + 0*C512, beta + 0*C512, L1, 0);

    // conv2..5 (mma.sync bf16 3-term, BN of prev layer fused into gather)
    mmaconv_kernel<8,4,2,false><<<dim3(4,500), 256>>>(buf1, wh + WOFF2, wl + WOFF2, buf2, ts, 0, 512, L1, 512, L2, 4096, BATCH*L2);
    bnstats_kernel<<<C512, 256>>>(buf2, gamma + 1*C512, beta + 1*C512, L2, 1);

    mmaconv_kernel<4,2,1,false><<<dim3(4,250), 256>>>(buf2, wh + WOFF3, wl + WOFF3, buf3, ts, 1, 512, L2, 512, L3, 2048, BATCH*L3);
    bnstats_kernel<<<C512, 256>>>(buf3, gamma + 2*C512, beta + 2*C512, L3, 2);

    mmaconv_kernel<4,2,1,false><<<dim3(4,125), 256>>>(buf3, wh + WOFF4, wl + WOFF4, buf4, ts, 2, 512, L3, 512, L4, 2048, BATCH*L4);
    bnstats_kernel<<<C512, 256>>>(buf4, gamma + 3*C512, beta + 3*C512, L4, 3);

    mmaconv_kernel<4,2,1,false><<<dim3(4,63), 256>>>(buf4, wh + WOFF5, wl + WOFF5, buf5, ts, 3, 512, L4, 512, L5, 2048, BATCH*L5);
    bnstats_kernel<<<C512, 256>>>(buf5, gamma + 4*C512, beta + 4*C512, L5, 4);

    // input gates: gi = Wih . bnrelu(z)*mask   (KW=1 GEMM, bn4 + mask fused)
    mmaconv_kernel<1,1,0,true><<<dim3(6,63), 256>>>(buf5, wh + WOFFIH, wl + WOFFIH, gi, ts, 4, 512, L5, G3, L5, 512, BATCH*L5);

    // GRU
    gruinit_kernel<<<16, 256>>>(hidden);
    int smg = (96*256 + 256 + 96) * (int)sizeof(float);
    cudaFuncSetAttribute(gru_kernel, cudaFuncAttributeMaxDynamicSharedMemorySize, smg);
    gru_kernel<<<128, 128, smg>>>(gi, whh, bih, bhh, ts, out);

    // head
    enc_kernel<<<(KSTEP*BATCH*C512 + 255)/256, 256>>>(ts);
    pred_kernel<<<KSTEP*BATCH, 512>>>(wkw, wkb);
    total_kernel<<<KSTEP*BATCH, 32>>>();
    final_kernel<<<1, 192>>>(out);
}

// round 5
// speedup vs baseline: 1.6948x; 1.0745x over previous
#include <cuda_runtime.h>
#include <cuda_bf16.h>
#include <math.h>
#include <stdint.h>

#define BATCH 16
#define C512  512
#define L0    80000
#define L1    16000
#define L2    4000
#define L3    2000
#define L4    1000
#define L5    500
#define KSTEP 12
#define HID   256
#define G3    768

// ---------------- scratch (static device globals; no allocation) ----------------
__device__ float g_buf1[BATCH*C512*L1];   // conv1 raw out
__device__ float g_buf2[BATCH*C512*L2];
__device__ float g_buf3[BATCH*C512*L3];
__device__ float g_buf4[BATCH*C512*L4];
__device__ float g_buf5[BATCH*C512*L5];   // conv5 raw out (z before bn4)
__device__ float g_gi  [BATCH*L5*G3];     // input gates [b][t][g]  (transposed!)
__device__ float g_scales[5*C512];
__device__ float g_shifts[5*C512];
__device__ float g_ct  [BATCH*HID];
__device__ float g_enc [KSTEP*BATCH*C512];
__device__ float g_pred[KSTEP*BATCH*C512];
__device__ float g_total[KSTEP*BATCH*BATCH];

// bf16 hi/lo split weights (conv2 @0, conv3 @2M, conv4 @3M, conv5 @4M, wih @5M)
__device__ __nv_bfloat16 g_wh[6*1024*1024];
__device__ __nv_bfloat16 g_wl[6*1024*1024];
#define WOFF2   0
#define WOFF3   2097152
#define WOFF4   3145728
#define WOFF5   4194304
#define WOFFIH  5242880

// ================= weight split fp32 -> bf16 hi + lo =================
__global__ void wcvt_kernel(const float* __restrict__ W, __nv_bfloat16* __restrict__ Wh,
                            __nv_bfloat16* __restrict__ Wl, int n) {
    int i = blockIdx.x*blockDim.x + threadIdx.x;
    if (i < n) {
        float v = W[i];
        __nv_bfloat16 h = __float2bfloat16(v);
        Wh[i] = h;
        Wl[i] = __float2bfloat16(v - __bfloat162float(h));
    }
}

// ================= conv1: smem-staged direct conv (Cin=1, K=10, S=5, P=3) =================
#define C1_TCHUNK 250
__global__ void conv1_kernel(const float* __restrict__ x, const float* __restrict__ w) {
    __shared__ float xs[C1_TCHUNK*5 + 10];
    __shared__ float ws[512*10];
    int t0 = blockIdx.x * C1_TCHUNK;
    int b  = blockIdx.y;
    int tid = threadIdx.x;
    const float* xb = x + (size_t)b*L0;
    int pbase = 5*t0 - 3;
    for (int i = tid; i < C1_TCHUNK*5 + 10; i += 256) {
        int p = pbase + i;
        xs[i] = (p >= 0 && p < L0) ? xb[p] : 0.f;
    }
    for (int i = tid; i < 5120; i += 256) ws[i] = w[i];
    __syncthreads();
    if (tid < C1_TCHUNK) {
        float* ob = g_buf1 + ((size_t)b*C512)*L1 + t0 + tid;
        const float* xp = xs + 5*tid;
        float xr[10];
#pragma unroll
        for (int k = 0; k < 10; k++) xr[k] = xp[k];
        for (int o = 0; o < 512; o++) {
            const float* wr = ws + o*10;
            float s = 0.f;
#pragma unroll
            for (int k = 0; k < 10; k++) s += xr[k]*wr[k];
            ob[(size_t)o*L1] = s;
        }
    }
}

// ================= BN stats (fp64, exact) =================
__global__ void bnstats_kernel(const float* __restrict__ buf, const float* __restrict__ gamma,
                               const float* __restrict__ beta, int L, int layer) {
    int c = blockIdx.x;
    int Bn = BATCH * L;
    double s = 0.0, s2 = 0.0;
    for (int i = threadIdx.x; i < Bn; i += blockDim.x) {
        int b = i / L, l = i - b*L;
        float v = buf[((size_t)b*C512 + c)*L + l];
        s += v; s2 += (double)v * v;
    }
    __shared__ double rs[256], rq[256];
    rs[threadIdx.x] = s; rq[threadIdx.x] = s2;
    __syncthreads();
    for (int o = 128; o > 0; o >>= 1) {
        if (threadIdx.x < o) { rs[threadIdx.x] += rs[threadIdx.x+o]; rq[threadIdx.x] += rq[threadIdx.x+o]; }
        __syncthreads();
    }
    if (threadIdx.x == 0) {
        double mean = rs[0] / Bn;
        double var  = rq[0] / Bn - mean*mean;
        double scd  = (double)gamma[c] / sqrt(var + 1e-5);
        g_scales[layer*C512 + c] = (float)scd;
        g_shifts[layer*C512 + c] = beta[c] - (float)(mean * scd);
    }
}

// ================= mma.sync helpers =================
#define MMA16816(d, a, b) \
    asm volatile( \
        "mma.sync.aligned.m16n8k16.row.col.f32.bf16.bf16.f32 " \
        "{%0,%1,%2,%3}, {%4,%5,%6,%7}, {%8,%9}, {%0,%1,%2,%3};" \
        : "+f"((d)[0]), "+f"((d)[1]), "+f"((d)[2]), "+f"((d)[3]) \
        : "r"((a)[0]), "r"((a)[1]), "r"((a)[2]), "r"((a)[3]), \
          "r"((b)[0]), "r"((b)[1]))

// ================= tensor-core conv-as-GEMM (mma.sync bf16, 3-term) =================
#define SMSTRIDE 34

template<int KW, int S, int P, bool MASK, bool TRANSP>
__global__ void __launch_bounds__(256, 2) mmaconv_kernel(
    const float* __restrict__ In, const __nv_bfloat16* __restrict__ Wh,
    const __nv_bfloat16* __restrict__ Wl, float* __restrict__ Out,
    const int* __restrict__ ts, int bnlayer,
    int Cin, int Lin, int O, int Lout, int Kd, int Ntot)
{
    __shared__ __nv_bfloat16 sAh[128][SMSTRIDE];
    __shared__ __nv_bfloat16 sAl[128][SMSTRIDE];
    __shared__ __nv_bfloat16 sBh[128][SMSTRIDE];
    __shared__ __nv_bfloat16 sBl[128][SMSTRIDE];

    const int tid  = threadIdx.x;
    const int lane = tid & 31, w = tid >> 5;
    const int wm = (w >> 2) * 64, wn = (w & 3) * 32;
    const int m0 = blockIdx.x * 128, n0 = blockIdx.y * 128;
    const float* __restrict__ scale = g_scales + bnlayer*C512;
    const float* __restrict__ shift = g_shifts + bnlayer*C512;

    const int g = lane >> 2, tig = lane & 3;
    const int arow = tid >> 1, ak0 = (tid & 1) * 16;
    const int nchunks = Kd >> 5;

    float acc[4][4][4];
#pragma unroll
    for (int i = 0; i < 4; i++)
#pragma unroll
        for (int j = 0; j < 4; j++)
#pragma unroll
            for (int q = 0; q < 4; q++) acc[i][j][q] = 0.f;

    for (int c = 0; c < nchunks; c++) {
        const int k0 = c << 5;

        // ---- A tile: copy precomputed hi/lo weights ----
        {
            const size_t go = (size_t)(m0 + arow)*Kd + k0 + ak0;
            uint4 ha = *(const uint4*)(Wh + go);
            uint4 hb = *(const uint4*)(Wh + go + 8);
            uint4 la = *(const uint4*)(Wl + go);
            uint4 lb = *(const uint4*)(Wl + go + 8);
            uint32_t* dh = (uint32_t*)&sAh[arow][ak0];
            uint32_t* dl = (uint32_t*)&sAl[arow][ak0];
            dh[0]=ha.x; dh[1]=ha.y; dh[2]=ha.z; dh[3]=ha.w;
            dh[4]=hb.x; dh[5]=hb.y; dh[6]=hb.z; dh[7]=hb.w;
            dl[0]=la.x; dl[1]=la.y; dl[2]=la.z; dl[3]=la.w;
            dl[4]=lb.x; dl[5]=lb.y; dl[6]=lb.z; dl[7]=lb.w;
        }

        // ---- B tile: im2col gather + BN/ReLU (+mask), hi/lo split ----
        {
            const int c0 = k0 / KW;
            const int ITS = 16 / KW;
#pragma unroll
            for (int it = 0; it < ITS; it++) {
                int idx = it*256 + tid;
                int nn = idx & 127;
                int cl = idx >> 7;
                int cch = c0 + cl;
                int n = n0 + nn;
                bool vn = (n < Ntot);
                int b = 0, t = 0;
                if (vn) { b = n / Lout; t = n - b*Lout; }
                const float* ip = In + ((size_t)(b*Cin + cch))*Lin;
                float sc = __ldg(scale + cch), sh = __ldg(shift + cch);
                bool ok = vn;
                if (MASK && ok) ok = (t <= __ldg(ts + b));
                const int pb = S*t - P;
                if (KW == 1) {
                    float v = 0.f;
                    if (ok) v = fmaxf(__ldg(ip + t)*sc + sh, 0.f);
                    __nv_bfloat16 hb16 = __float2bfloat16(v);
                    sBh[nn][cl] = hb16;
                    sBl[nn][cl] = __float2bfloat16(v - __bfloat162float(hb16));
                } else {
                    float v[KW > 1 ? KW : 2];
#pragma unroll
                    for (int kw = 0; kw < KW; kw++) {
                        int p = pb + kw;
                        float xv = 0.f;
                        if (ok && p >= 0 && p < Lin) xv = fmaxf(__ldg(ip + p)*sc + sh, 0.f);
                        v[kw] = xv;
                    }
#pragma unroll
                    for (int q = 0; q < KW/2; q++) {
                        __nv_bfloat162 h2, l2;
                        h2.x = __float2bfloat16(v[2*q]);
                        h2.y = __float2bfloat16(v[2*q+1]);
                        l2.x = __float2bfloat16(v[2*q]   - __bfloat162float(h2.x));
                        l2.y = __float2bfloat16(v[2*q+1] - __bfloat162float(h2.y));
                        *(__nv_bfloat162*)&sBh[nn][cl*KW + 2*q] = h2;
                        *(__nv_bfloat162*)&sBl[nn][cl*KW + 2*q] = l2;
                    }
                }
            }
        }
        __syncthreads();

        // ---- compute: 2 k16 steps x (AhBh, AlBh, AhBl) ----
#pragma unroll
        for (int ks = 0; ks < 32; ks += 16) {
            const int cb = ks + tig*2;
            uint32_t ah[4][4], al[4][4], bh[4][2];
#pragma unroll
            for (int mt = 0; mt < 4; mt++) {
                int r = wm + mt*16 + g;
                ah[mt][0] = *(const uint32_t*)&sAh[r][cb];
                ah[mt][1] = *(const uint32_t*)&sAh[r+8][cb];
                ah[mt][2] = *(const uint32_t*)&sAh[r][cb+8];
                ah[mt][3] = *(const uint32_t*)&sAh[r+8][cb+8];
                al[mt][0] = *(const uint32_t*)&sAl[r][cb];
                al[mt][1] = *(const uint32_t*)&sAl[r+8][cb];
                al[mt][2] = *(const uint32_t*)&sAl[r][cb+8];
                al[mt][3] = *(const uint32_t*)&sAl[r+8][cb+8];
            }
#pragma unroll
            for (int nt = 0; nt < 4; nt++) {
                int rn = wn + nt*8 + g;
                bh[nt][0] = *(const uint32_t*)&sBh[rn][cb];
                bh[nt][1] = *(const uint32_t*)&sBh[rn][cb+8];
            }
#pragma unroll
            for (int mt = 0; mt < 4; mt++)
#pragma unroll
                for (int nt = 0; nt < 4; nt++) MMA16816(acc[mt][nt], ah[mt], bh[nt]);
#pragma unroll
            for (int mt = 0; mt < 4; mt++)
#pragma unroll
                for (int nt = 0; nt < 4; nt++) MMA16816(acc[mt][nt], al[mt], bh[nt]);
            uint32_t bl[4][2];
#pragma unroll
            for (int nt = 0; nt < 4; nt++) {
                int rn = wn + nt*8 + g;
                bl[nt][0] = *(const uint32_t*)&sBl[rn][cb];
                bl[nt][1] = *(const uint32_t*)&sBl[rn][cb+8];
            }
#pragma unroll
            for (int mt = 0; mt < 4; mt++)
#pragma unroll
                for (int nt = 0; nt < 4; nt++) MMA16816(acc[mt][nt], ah[mt], bl[nt]);
        }
        __syncthreads();
    }

    // ---- epilogue ----
#pragma unroll
    for (int mt = 0; mt < 4; mt++) {
        int r = m0 + wm + mt*16 + g;
#pragma unroll
        for (int nt = 0; nt < 4; nt++) {
            int cc = n0 + wn + nt*8 + tig*2;
#pragma unroll
            for (int q = 0; q < 4; q++) {
                int n  = cc + (q & 1);
                int rr = r + (q >> 1)*8;
                if (n < Ntot) {
                    int b = n / Lout, t = n - b*Lout;
                    if (TRANSP) Out[((size_t)b*Lout + t)*O + rr] = acc[mt][nt][q];
                    else        Out[((size_t)(b*O + rr))*Lout + t] = acc[mt][nt][q];
                }
            }
        }
    }
}

// ================= GRU: 8-CTA cluster per batch, DSMEM h exchange =================
static __device__ __forceinline__ uint32_t smem_u32(const void* p) {
    return (uint32_t)__cvta_generic_to_shared(p);
}
static __device__ __forceinline__ void dsmem_store(uint32_t laddr, uint32_t rank, float v) {
    uint32_t dst;
    asm volatile("mapa.shared::cluster.u32 %0, %1, %2;" : "=r"(dst) : "r"(laddr), "r"(rank));
    asm volatile("st.shared::cluster.f32 [%0], %1;" :: "r"(dst), "f"(v) : "memory");
}
#define CLUSTER_SYNC() do { \
    asm volatile("barrier.cluster.arrive.aligned;" ::: "memory"); \
    asm volatile("barrier.cluster.wait.aligned;" ::: "memory"); } while(0)

__global__ void __cluster_dims__(8,1,1) gru_kernel(
    const float* __restrict__ gi, const float* __restrict__ whh,
    const float* __restrict__ bih, const float* __restrict__ bhh,
    const int* __restrict__ ts, const float* __restrict__ hidden,
    float* __restrict__ out)
{
    extern __shared__ float smg[];
    float* Ws   = smg;                 // 96*256, layout [gate][k/4][j][k%4]
    float* hs   = smg + 96*256;        // 2 x 256 ping-pong
    float* gh_s = hs + 512;            // 96
    uint32_t rank;
    asm("mov.u32 %0, %%cluster_ctarank;" : "=r"(rank));
    int b  = blockIdx.x >> 3;
    int j0 = rank * 32;
    int tid = threadIdx.x;             // 128
    int warp = tid >> 5, lane = tid & 31;

    for (int e = tid; e < 96*256; e += 128) {
        int gate = e >> 13;
        int rem  = e & 8191;
        int j    = rem >> 8;
        int k    = rem & 255;
        Ws[((gate*64 + (k>>2))*32 + j)*4 + (k&3)] = whh[((size_t)(gate*256 + j0 + j))*256 + k];
    }
    for (int e = tid; e < HID; e += 128) hs[e] = hidden[b*HID + e];
    int tsb = ts[b];
    float bihr=0.f,bihz=0.f,bihn=0.f,bhhr=0.f,bhhz=0.f,bhhn=0.f;
    if (warp == 0) {
        bihr = bih[j0+lane]; bihz = bih[256+j0+lane]; bihn = bih[512+j0+lane];
        bhhr = bhh[j0+lane]; bhhz = bhh[256+j0+lane]; bhhn = bhh[512+j0+lane];
    }
    __syncthreads();
    CLUSTER_SYNC();

    for (int t = 0; t < L5; t++) {
        const float* hcur = hs + (t & 1)*256;
        if (warp < 3) {
            const float4* wp = (const float4*)Ws + warp*2048 + lane;
            const float4* hp = (const float4*)hcur;
            float acc = 0.f;
#pragma unroll
            for (int k4 = 0; k4 < 64; k4++) {
                float4 w = wp[k4*32];
                float4 h = hp[k4];
                acc += w.x*h.x + w.y*h.y + w.z*h.z + w.w*h.w;
            }
            gh_s[warp*32 + lane] = acc;
        }
        __syncthreads();
        if (warp == 0) {
            int j = j0 + lane;
            const float* gb = gi + ((size_t)b*L5 + t)*G3;
            float gir = gb[j]       + bihr;
            float giz = gb[256 + j] + bihz;
            float gin = gb[512 + j] + bihn;
            float ghr = gh_s[lane]    + bhhr;
            float ghz = gh_s[32+lane] + bhhz;
            float ghn = gh_s[64+lane] + bhhn;
            float r   = 1.f/(1.f + expf(-(gir+ghr)));
            float zg  = 1.f/(1.f + expf(-(giz+ghz)));
            float n   = tanhf(gin + r*ghn);
            float hold = hcur[j];
            float hnew = (1.f - zg)*n + zg*hold;
            uint32_t laddr = smem_u32(hs + ((t+1)&1)*256 + j);
#pragma unroll
            for (int r2 = 0; r2 < 8; r2++) dsmem_store(laddr, (uint32_t)r2, hnew);
            if (t == tsb)   g_ct[b*HID + j] = hnew;
            if (t == L5-1)  out[2 + b*HID + j] = hnew;
        }
        CLUSTER_SYNC();
    }
}

// ================= head =================
__global__ void enc_kernel(const int* __restrict__ ts) {
    int idx = blockIdx.x*blockDim.x + threadIdx.x;
    if (idx >= KSTEP*BATCH*C512) return;
    int d = idx & 511;
    int b = (idx >> 9) & 15;
    int k = idx >> 13;
    int t = ts[b] + k + 1;
    float v = g_buf5[((size_t)b*C512 + d)*L5 + t];
    g_enc[idx] = fmaxf(v*g_scales[4*C512 + d] + g_shifts[4*C512 + d], 0.f);
}

__global__ void pred_kernel(const float* __restrict__ wkw, const float* __restrict__ wkb) {
    int k = blockIdx.x >> 4;
    int b = blockIdx.x & 15;
    __shared__ float cs[HID];
    if (threadIdx.x < HID) cs[threadIdx.x] = g_ct[b*HID + threadIdx.x];
    __syncthreads();
    int d = threadIdx.x; // 512 threads
    const float* wr = wkw + ((size_t)k*C512 + d)*HID;
    float acc = wkb[k*C512 + d];
#pragma unroll 8
    for (int h = 0; h < HID; h++) acc += cs[h]*wr[h];
    g_pred[(k*BATCH + b)*C512 + d] = acc;
}

__global__ void total_kernel() {
    int k = blockIdx.x >> 4;
    int b = blockIdx.x & 15;
    int c = threadIdx.x;
    if (c < BATCH) {
        const float* e = g_enc  + ((size_t)(k*BATCH + b))*C512;
        const float* p = g_pred + ((size_t)(k*BATCH + c))*C512;
        float acc = 0.f;
        for (int d = 0; d < C512; d++) acc += e[d]*p[d];
        g_total[(k*BATCH + b)*BATCH + c] = acc;
    }
}

__global__ void final_kernel(float* __restrict__ out) {
    __shared__ float red[192];
    __shared__ float lse11[16];
    __shared__ float corr[16];
    int tid = threadIdx.x;  // 192
    int k = tid >> 4, b = tid & 15;
    float contrib;
    {
        const float* row = g_total + tid*16;
        float mx = row[0];
        for (int c = 1; c < 16; c++) mx = fmaxf(mx, row[c]);
        float s = 0.f;
        for (int c = 0; c < 16; c++) s += expf(row[c]-mx);
        float lse = mx + logf(s);
        contrib = row[b] - lse;
        if (k == KSTEP-1) lse11[b] = lse;
    }
    red[tid] = contrib;
    __syncthreads();
    if (tid < 16) {
        int c = tid;
        const float* t11 = g_total + (KSTEP-1)*BATCH*BATCH;
        float best = -1e30f; int arg = -1;
        for (int bb = 0; bb < 16; bb++) {
            float v = expf(t11[bb*16 + c] - lse11[bb]);
            if (v > best) { best = v; arg = bb; }
        }
        corr[c] = (arg == c) ? 1.f : 0.f;
    }
    __syncthreads();
    if (tid == 0) {
        float s = 0.f;
        for (int i = 0; i < 192; i++) s += red[i];
        out[1] = s / (-1.f * BATCH * KSTEP);
        float a = 0.f;
        for (int i = 0; i < 16; i++) a += corr[i];
        out[0] = a / (float)BATCH;
    }
}

// ================= host =================
extern "C" void kernel_launch(void* const* d_in, const int* in_sizes, int n_in,
                              void* d_out, int out_size) {
    const float* x      = (const float*)d_in[0];
    const float* hidden = (const float*)d_in[1];
    const int*   ts     = (const int*)d_in[3];
    const float* w1     = (const float*)d_in[4];
    const float* w2     = (const float*)d_in[5];
    const float* w345   = (const float*)d_in[6];
    const float* gamma  = (const float*)d_in[7];
    const float* beta   = (const float*)d_in[8];
    const float* wih    = (const float*)d_in[9];
    const float* whh    = (const float*)d_in[10];
    const float* bih    = (const float*)d_in[11];
    const float* bhh    = (const float*)d_in[12];
    const float* wkw    = (const float*)d_in[13];
    const float* wkb    = (const float*)d_in[14];
    float* out = (float*)d_out;

    float *buf1, *buf2, *buf3, *buf4, *buf5, *gi;
    __nv_bfloat16 *wh, *wl;
    cudaGetSymbolAddress((void**)&buf1, g_buf1);
    cudaGetSymbolAddress((void**)&buf2, g_buf2);
    cudaGetSymbolAddress((void**)&buf3, g_buf3);
    cudaGetSymbolAddress((void**)&buf4, g_buf4);
    cudaGetSymbolAddress((void**)&buf5, g_buf5);
    cudaGetSymbolAddress((void**)&gi,   g_gi);
    cudaGetSymbolAddress((void**)&wh,   g_wh);
    cudaGetSymbolAddress((void**)&wl,   g_wl);

    // launches 0-2: weight split (w345 is contiguous for conv3/4/5)
    wcvt_kernel<<<8192, 256>>>(w2,   wh + WOFF2,  wl + WOFF2,  512*4096);
    wcvt_kernel<<<12288, 256>>>(w345, wh + WOFF3, wl + WOFF3,  3*512*2048);
    wcvt_kernel<<<1536, 256>>>(wih,  wh + WOFFIH, wl + WOFFIH, 768*512);

    // launch 3: conv1 ; launch 4: bn0 stats
    conv1_kernel<<<dim3(64, BATCH), 256>>>(x, w1);
    bnstats_kernel<<<C512, 256>>>(buf1, gamma + 0*C512, beta + 0*C512, L1, 0);

    // launch 5: conv2 (ncu capture lands here)
    mmaconv_kernel<8,4,2,false,false><<<dim3(4,500), 256>>>(buf1, wh + WOFF2, wl + WOFF2, buf2, ts, 0, 512, L1, 512, L2, 4096, BATCH*L2);
    bnstats_kernel<<<C512, 256>>>(buf2, gamma + 1*C512, beta + 1*C512, L2, 1);

    mmaconv_kernel<4,2,1,false,false><<<dim3(4,250), 256>>>(buf2, wh + WOFF3, wl + WOFF3, buf3, ts, 1, 512, L2, 512, L3, 2048, BATCH*L3);
    bnstats_kernel<<<C512, 256>>>(buf3, gamma + 2*C512, beta + 2*C512, L3, 2);

    mmaconv_kernel<4,2,1,false,false><<<dim3(4,125), 256>>>(buf3, wh + WOFF4, wl + WOFF4, buf4, ts, 2, 512, L3, 512, L4, 2048, BATCH*L4);
    bnstats_kernel<<<C512, 256>>>(buf4, gamma + 3*C512, beta + 3*C512, L4, 3);

    mmaconv_kernel<4,2,1,false,false><<<dim3(4,63), 256>>>(buf4, wh + WOFF5, wl + WOFF5, buf5, ts, 3, 512, L4, 512, L5, 2048, BATCH*L5);
    bnstats_kernel<<<C512, 256>>>(buf5, gamma + 4*C512, beta + 4*C512, L5, 4);

    // input gates: gi[b][t][g] = Wih . bnrelu(z)*mask  (bn4 + mask fused, transposed out)
    mmaconv_kernel<1,1,0,true,true><<<dim3(6,63), 256>>>(buf5, wh + WOFFIH, wl + WOFFIH, gi, ts, 4, 512, L5, G3, L5, 512, BATCH*L5);

    // GRU (16 clusters of 8 CTAs; DSMEM h exchange)
    int smg = (96*256 + 512 + 96) * (int)sizeof(float);
    cudaFuncSetAttribute(gru_kernel, cudaFuncAttributeMaxDynamicSharedMemorySize, smg);
    gru_kernel<<<128, 128, smg>>>(gi, whh, bih, bhh, ts, hidden, out);

    // head
    enc_kernel<<<(KSTEP*BATCH*C512 + 255)/256, 256>>>(ts);
    pred_kernel<<<KSTEP*BATCH, 512>>>(wkw, wkb);
    total_kernel<<<KSTEP*BATCH, 32>>>();
    final_kernel<<<1, 192>>>(out);
}

// round 7
// speedup vs baseline: 1.8506x; 1.0920x over previous
#include <cuda_runtime.h>
#include <cuda_bf16.h>
#include <math.h>
#include <stdint.h>

#define BATCH 16
#define C512  512
#define L0    80000
#define L1    16000
#define L2    4000
#define L3    2000
#define L4    1000
#define L5    500
#define KSTEP 12
#define HID   256
#define G3    768

// ---------------- scratch ----------------
__device__ float g_buf1[BATCH*C512*L1];
__device__ float g_buf2[BATCH*C512*L2];
__device__ float g_buf3[BATCH*C512*L3];
__device__ float g_buf4[BATCH*C512*L4];
__device__ float g_buf5[BATCH*C512*L5];
__device__ float g_gi  [BATCH*L5*G3];     // [b][t][g]
__device__ float g_scales[5*C512];
__device__ float g_shifts[5*C512];
__device__ float g_ct  [BATCH*HID];
__device__ float g_enc [KSTEP*BATCH*C512];
__device__ float g_pred[KSTEP*BATCH*C512];
__device__ float g_total[KSTEP*BATCH*BATCH];

// bf16 hi/lo weights (w2 @0, w345 @2M contiguous, wih @5M)
__device__ __nv_bfloat16 g_wh[6*1024*1024];
__device__ __nv_bfloat16 g_wl[6*1024*1024];
#define WOFF2   0
#define WOFF3   2097152
#define WOFF4   3145728
#define WOFF5   4194304
#define WOFFIH  5242880

// padded bf16 hi/lo activations: layer1 pad 4 (shift 2), layers 2-4 pad 2 (shift 1)
#define L1P (L1+4)
#define L2P (L2+2)
#define L3P (L3+2)
#define L4P (L4+2)
__device__ __nv_bfloat16 g_a1h[BATCH*C512*L1P];
__device__ __nv_bfloat16 g_a1l[BATCH*C512*L1P];
__device__ __nv_bfloat16 g_a2h[BATCH*C512*L2P];
__device__ __nv_bfloat16 g_a2l[BATCH*C512*L2P];
__device__ __nv_bfloat16 g_a3h[BATCH*C512*L3P];
__device__ __nv_bfloat16 g_a3l[BATCH*C512*L3P];
__device__ __nv_bfloat16 g_a4h[BATCH*C512*L4P];
__device__ __nv_bfloat16 g_a4l[BATCH*C512*L4P];

static __device__ __forceinline__ uint32_t smem_u32(const void* p) {
    return (uint32_t)__cvta_generic_to_shared(p);
}

// ================= prep: wcvt (all weights) + conv1 fused =================
#define C1_TCHUNK 250
#define WCVT_N 5636096
__global__ void prep_kernel(const float* __restrict__ x, const float* __restrict__ w1,
                            const float* __restrict__ w2, const float* __restrict__ w345,
                            const float* __restrict__ wih) {
    int bx = blockIdx.x;
    int tid = threadIdx.x;
    if (bx < 1024) {
        __shared__ float xs[C1_TCHUNK*5 + 10];
        __shared__ float ws[512*10];
        int b  = bx >> 6;
        int t0 = (bx & 63) * C1_TCHUNK;
        const float* xb = x + (size_t)b*L0;
        int pbase = 5*t0 - 3;
        for (int i = tid; i < C1_TCHUNK*5 + 10; i += 256) {
            int p = pbase + i;
            xs[i] = (p >= 0 && p < L0) ? xb[p] : 0.f;
        }
        for (int i = tid; i < 5120; i += 256) ws[i] = w1[i];
        __syncthreads();
        if (tid < C1_TCHUNK) {
            float* ob = g_buf1 + ((size_t)b*C512)*L1 + t0 + tid;
            const float* xp = xs + 5*tid;
            float xr[10];
#pragma unroll
            for (int k = 0; k < 10; k++) xr[k] = xp[k];
            for (int o = 0; o < 512; o++) {
                const float* wr = ws + o*10;
                float s = 0.f;
#pragma unroll
                for (int k = 0; k < 10; k++) s += xr[k]*wr[k];
                ob[(size_t)o*L1] = s;
            }
        }
    } else {
        int i = (bx - 1024)*256 + tid;
        if (i < WCVT_N) {
            float v = (i < 2097152) ? w2[i]
                    : (i < 5242880) ? w345[i - 2097152]
                                    : wih[i - 5242880];
            __nv_bfloat16 h = __float2bfloat16(v);
            g_wh[i] = h;
            g_wl[i] = __float2bfloat16(v - __bfloat162float(h));
        }
    }
}

// ================= BN stats (fp64, exact) =================
__global__ void bnstats_kernel(const float* __restrict__ buf, const float* __restrict__ gamma,
                               const float* __restrict__ beta, int L, int layer) {
    int c = blockIdx.x;
    int Bn = BATCH * L;
    double s = 0.0, s2 = 0.0;
    for (int i = threadIdx.x; i < Bn; i += blockDim.x) {
        int b = i / L, l = i - b*L;
        float v = buf[((size_t)b*C512 + c)*L + l];
        s += v; s2 += (double)v * v;
    }
    __shared__ double rs[256], rq[256];
    rs[threadIdx.x] = s; rq[threadIdx.x] = s2;
    __syncthreads();
    for (int o = 128; o > 0; o >>= 1) {
        if (threadIdx.x < o) { rs[threadIdx.x] += rs[threadIdx.x+o]; rq[threadIdx.x] += rq[threadIdx.x+o]; }
        __syncthreads();
    }
    if (threadIdx.x == 0) {
        double mean = rs[0] / Bn;
        double var  = rq[0] / Bn - mean*mean;
        double scd  = (double)gamma[c] / sqrt(var + 1e-5);
        g_scales[layer*C512 + c] = (float)scd;
        g_shifts[layer*C512 + c] = beta[c] - (float)(mean * scd);
    }
}

// ================= actcvt: bnrelu(fp32) -> padded bf16 hi/lo =================
__global__ void actcvt_kernel(const float* __restrict__ In, __nv_bfloat16* __restrict__ Oh,
                              __nv_bfloat16* __restrict__ Ol, int layer,
                              int L, int Lpad, int shift, int total2) {
    int idx = blockIdx.x*blockDim.x + threadIdx.x;
    if (idx >= total2) return;
    int base = idx*2;
    int q  = base % Lpad;
    int bc = base / Lpad;            // b*512 + c
    int c  = bc & 511;
    float sc = g_scales[layer*C512 + c];
    float sh = g_shifts[layer*C512 + c];
    const float* ip = In + (size_t)bc*L;
    __nv_bfloat162 h2, l2;
#pragma unroll
    for (int e = 0; e < 2; e++) {
        int p = q + e - shift;
        float v = 0.f;
        if (p >= 0 && p < L) v = fmaxf(ip[p]*sc + sh, 0.f);
        __nv_bfloat16 hb = __float2bfloat16(v);
        __nv_bfloat16 lb = __float2bfloat16(v - __bfloat162float(hb));
        if (e == 0) { h2.x = hb; l2.x = lb; } else { h2.y = hb; l2.y = lb; }
    }
    *(__nv_bfloat162*)(Oh + base) = h2;
    *(__nv_bfloat162*)(Ol + base) = l2;
}

// ================= mma.sync helpers =================
#define MMA16816(d, a, b) \
    asm volatile( \
        "mma.sync.aligned.m16n8k16.row.col.f32.bf16.bf16.f32 " \
        "{%0,%1,%2,%3}, {%4,%5,%6,%7}, {%8,%9}, {%0,%1,%2,%3};" \
        : "+f"((d)[0]), "+f"((d)[1]), "+f"((d)[2]), "+f"((d)[3]) \
        : "r"((a)[0]), "r"((a)[1]), "r"((a)[2]), "r"((a)[3]), \
          "r"((b)[0]), "r"((b)[1]))

static __device__ __forceinline__ void cpa4(uint32_t dst, const void* src, uint32_t sz) {
    asm volatile("cp.async.ca.shared.global [%0], [%1], 4, %2;"
                 :: "r"(dst), "l"(src), "r"(sz) : "memory");
}
static __device__ __forceinline__ void cpa16(uint32_t dst, const void* src) {
    asm volatile("cp.async.cg.shared.global [%0], [%1], 16;"
                 :: "r"(dst), "l"(src) : "memory");
}

// ================= pipelined bf16 conv-as-GEMM (cp.async, double-buffered) =================
// smem per stage (bf16 elems, stride 40): sBh 5120 | sBl 5120 | sAh 5120 | sAl 5120
#define STG_ELEMS 20480
#define DYN_SMEM  (2*STG_ELEMS*2)

template<int KW, int S, int P, int SHIFT>
__global__ void __launch_bounds__(256, 1) mmaconv_bf_kernel(
    const __nv_bfloat16* __restrict__ Inh, const __nv_bfloat16* __restrict__ Inl,
    const __nv_bfloat16* __restrict__ Wh,  const __nv_bfloat16* __restrict__ Wl,
    float* __restrict__ Out,
    int Lpad, int O, int Lout, int Kd, int Ntot)
{
    extern __shared__ __align__(16) __nv_bfloat16 dyn[];
    const int tid  = threadIdx.x;
    const int lane = tid & 31, w = tid >> 5;
    const int wm = (w >> 2) * 64, wn = (w & 3) * 32;
    const int m0 = blockIdx.x * 128, n0 = blockIdx.y * 128;
    const int g = lane >> 2, tig = lane & 3;
    const int C = Kd >> 5;

    // per-thread B gather coords
    const int ITS = 16 / KW;
    const int bnn = tid & 127;
    const int clbase = tid >> 7;       // 0 or 1
    int bq;                             // element base (without channel term)
    uint32_t bsz;
    {
        int n = n0 + bnn;
        bool vn = (n < Ntot);
        int nv = vn ? n : 0;
        int b = nv / Lout, t = nv - b*Lout;
        bsz = vn ? 4u : 0u;
        bq = (b*C512)*Lpad + S*t - P + SHIFT;
    }
    const int arow = tid >> 1, ahalf = tid & 1;

    auto load_chunk = [&](int c, int s) {
        __nv_bfloat16* stg = dyn + s*STG_ELEMS;
        const int k0 = c << 5;
        // A: 128 x 32 bf16 hi/lo
        {
            const __nv_bfloat16* srcH = Wh + (size_t)(m0 + arow)*Kd + k0 + ahalf*16;
            const __nv_bfloat16* srcL = Wl + (size_t)(m0 + arow)*Kd + k0 + ahalf*16;
            uint32_t dH = smem_u32(stg + 10240 + arow*40 + ahalf*16);
            uint32_t dL = smem_u32(stg + 15360 + arow*40 + ahalf*16);
            cpa16(dH, srcH);      cpa16(dH + 16, srcH + 8);
            cpa16(dL, srcL);      cpa16(dL + 16, srcL + 8);
        }
        // B: 128 x 32 bf16 hi/lo from padded act arrays
        {
            const int c0 = k0 / KW;
#pragma unroll
            for (int it = 0; it < ITS; it++) {
                int cl = it*2 + clbase;
                int srcbase = bq + (c0 + cl)*Lpad;
                uint32_t dH = smem_u32(stg +        bnn*40 + cl*KW);
                uint32_t dL = smem_u32(stg + 5120 + bnn*40 + cl*KW);
#pragma unroll
                for (int j = 0; j < KW/2; j++) {
                    cpa4(dH + j*4, Inh + srcbase + 2*j, bsz);
                    cpa4(dL + j*4, Inl + srcbase + 2*j, bsz);
                }
            }
        }
        asm volatile("cp.async.commit_group;" ::: "memory");
    };

    float acc[4][4][4];
#pragma unroll
    for (int i = 0; i < 4; i++)
#pragma unroll
        for (int j = 0; j < 4; j++)
#pragma unroll
            for (int q = 0; q < 4; q++) acc[i][j][q] = 0.f;

    load_chunk(0, 0);

    for (int c = 0; c < C; c++) {
        const int s = c & 1;
        if (c + 1 < C) {
            load_chunk(c + 1, s ^ 1);
            asm volatile("cp.async.wait_group 1;" ::: "memory");
        } else {
            asm volatile("cp.async.wait_group 0;" ::: "memory");
        }
        __syncthreads();

        const __nv_bfloat16* sB   = dyn + s*STG_ELEMS;
        const __nv_bfloat16* sBl_ = sB + 5120;
        const __nv_bfloat16* sA   = sB + 10240;
        const __nv_bfloat16* sAl_ = sB + 15360;

#pragma unroll
        for (int ks = 0; ks < 32; ks += 16) {
            const int cb = ks + tig*2;
            uint32_t ah[4][4], al[4][4], bh[4][2];
#pragma unroll
            for (int mt = 0; mt < 4; mt++) {
                int r = wm + mt*16 + g;
                ah[mt][0] = *(const uint32_t*)&sA[r*40 + cb];
                ah[mt][1] = *(const uint32_t*)&sA[(r+8)*40 + cb];
                ah[mt][2] = *(const uint32_t*)&sA[r*40 + cb + 8];
                ah[mt][3] = *(const uint32_t*)&sA[(r+8)*40 + cb + 8];
                al[mt][0] = *(const uint32_t*)&sAl_[r*40 + cb];
                al[mt][1] = *(const uint32_t*)&sAl_[(r+8)*40 + cb];
                al[mt][2] = *(const uint32_t*)&sAl_[r*40 + cb + 8];
                al[mt][3] = *(const uint32_t*)&sAl_[(r+8)*40 + cb + 8];
            }
#pragma unroll
            for (int nt = 0; nt < 4; nt++) {
                int rn = wn + nt*8 + g;
                bh[nt][0] = *(const uint32_t*)&sB[rn*40 + cb];
                bh[nt][1] = *(const uint32_t*)&sB[rn*40 + cb + 8];
            }
#pragma unroll
            for (int mt = 0; mt < 4; mt++)
#pragma unroll
                for (int nt = 0; nt < 4; nt++) MMA16816(acc[mt][nt], ah[mt], bh[nt]);
#pragma unroll
            for (int mt = 0; mt < 4; mt++)
#pragma unroll
                for (int nt = 0; nt < 4; nt++) MMA16816(acc[mt][nt], al[mt], bh[nt]);
            uint32_t bl[4][2];
#pragma unroll
            for (int nt = 0; nt < 4; nt++) {
                int rn = wn + nt*8 + g;
                bl[nt][0] = *(const uint32_t*)&sBl_[rn*40 + cb];
                bl[nt][1] = *(const uint32_t*)&sBl_[rn*40 + cb + 8];
            }
#pragma unroll
            for (int mt = 0; mt < 4; mt++)
#pragma unroll
                for (int nt = 0; nt < 4; nt++) MMA16816(acc[mt][nt], ah[mt], bl[nt]);
        }
        __syncthreads();
    }

    // ---- epilogue ----
#pragma unroll
    for (int mt = 0; mt < 4; mt++) {
        int r = m0 + wm + mt*16 + g;
#pragma unroll
        for (int nt = 0; nt < 4; nt++) {
            int cc = n0 + wn + nt*8 + tig*2;
#pragma unroll
            for (int q = 0; q < 4; q++) {
                int n  = cc + (q & 1);
                int rr = r + (q >> 1)*8;
                if (n < Ntot) {
                    int b = n / Lout, t = n - b*Lout;
                    Out[((size_t)(b*O + rr))*Lout + t] = acc[mt][nt][q];
                }
            }
        }
    }
}

// ================= old-path mmaconv for gi (KW=1, masked, transposed) =================
#define SMSTRIDE 34
__global__ void __launch_bounds__(256, 2) mmaconv_gi_kernel(
    const float* __restrict__ In, const __nv_bfloat16* __restrict__ Wh,
    const __nv_bfloat16* __restrict__ Wl, float* __restrict__ Out,
    const int* __restrict__ ts, int bnlayer,
    int Cin, int Lin, int O, int Lout, int Kd, int Ntot)
{
    __shared__ __nv_bfloat16 sAh[128][SMSTRIDE];
    __shared__ __nv_bfloat16 sAl[128][SMSTRIDE];
    __shared__ __nv_bfloat16 sBh[128][SMSTRIDE];
    __shared__ __nv_bfloat16 sBl[128][SMSTRIDE];
    const int tid  = threadIdx.x;
    const int lane = tid & 31, w = tid >> 5;
    const int wm = (w >> 2) * 64, wn = (w & 3) * 32;
    const int m0 = blockIdx.x * 128, n0 = blockIdx.y * 128;
    const float* __restrict__ scale = g_scales + bnlayer*C512;
    const float* __restrict__ shift = g_shifts + bnlayer*C512;
    const int g = lane >> 2, tig = lane & 3;
    const int arow = tid >> 1, ak0 = (tid & 1) * 16;
    const int nchunks = Kd >> 5;

    float acc[4][4][4];
#pragma unroll
    for (int i = 0; i < 4; i++)
#pragma unroll
        for (int j = 0; j < 4; j++)
#pragma unroll
            for (int q = 0; q < 4; q++) acc[i][j][q] = 0.f;

    for (int c = 0; c < nchunks; c++) {
        const int k0 = c << 5;
        {
            const size_t go = (size_t)(m0 + arow)*Kd + k0 + ak0;
            uint4 ha = *(const uint4*)(Wh + go);
            uint4 hb = *(const uint4*)(Wh + go + 8);
            uint4 la = *(const uint4*)(Wl + go);
            uint4 lb = *(const uint4*)(Wl + go + 8);
            uint32_t* dh = (uint32_t*)&sAh[arow][ak0];
            uint32_t* dl = (uint32_t*)&sAl[arow][ak0];
            dh[0]=ha.x; dh[1]=ha.y; dh[2]=ha.z; dh[3]=ha.w;
            dh[4]=hb.x; dh[5]=hb.y; dh[6]=hb.z; dh[7]=hb.w;
            dl[0]=la.x; dl[1]=la.y; dl[2]=la.z; dl[3]=la.w;
            dl[4]=lb.x; dl[5]=lb.y; dl[6]=lb.z; dl[7]=lb.w;
        }
        {
#pragma unroll
            for (int it = 0; it < 16; it++) {
                int idx = it*256 + tid;
                int nn = idx & 127;
                int cl = idx >> 7;
                int cch = k0 + cl;
                int n = n0 + nn;
                bool vn = (n < Ntot);
                int b = 0, t = 0;
                if (vn) { b = n / Lout; t = n - b*Lout; }
                float sc = __ldg(scale + cch), sh = __ldg(shift + cch);
                bool ok = vn && (t <= __ldg(ts + b));
                float v = 0.f;
                if (ok) v = fmaxf(__ldg(In + ((size_t)(b*Cin + cch))*Lin + t)*sc + sh, 0.f);
                __nv_bfloat16 hb16 = __float2bfloat16(v);
                sBh[nn][cl] = hb16;
                sBl[nn][cl] = __float2bfloat16(v - __bfloat162float(hb16));
            }
        }
        __syncthreads();
#pragma unroll
        for (int ks = 0; ks < 32; ks += 16) {
            const int cb = ks + tig*2;
            uint32_t ah[4][4], al[4][4], bh[4][2];
#pragma unroll
            for (int mt = 0; mt < 4; mt++) {
                int r = wm + mt*16 + g;
                ah[mt][0] = *(const uint32_t*)&sAh[r][cb];
                ah[mt][1] = *(const uint32_t*)&sAh[r+8][cb];
                ah[mt][2] = *(const uint32_t*)&sAh[r][cb+8];
                ah[mt][3] = *(const uint32_t*)&sAh[r+8][cb+8];
                al[mt][0] = *(const uint32_t*)&sAl[r][cb];
                al[mt][1] = *(const uint32_t*)&sAl[r+8][cb];
                al[mt][2] = *(const uint32_t*)&sAl[r][cb+8];
                al[mt][3] = *(const uint32_t*)&sAl[r+8][cb+8];
            }
#pragma unroll
            for (int nt = 0; nt < 4; nt++) {
                int rn = wn + nt*8 + g;
                bh[nt][0] = *(const uint32_t*)&sBh[rn][cb];
                bh[nt][1] = *(const uint32_t*)&sBh[rn][cb+8];
            }
#pragma unroll
            for (int mt = 0; mt < 4; mt++)
#pragma unroll
                for (int nt = 0; nt < 4; nt++) MMA16816(acc[mt][nt], ah[mt], bh[nt]);
#pragma unroll
            for (int mt = 0; mt < 4; mt++)
#pragma unroll
                for (int nt = 0; nt < 4; nt++) MMA16816(acc[mt][nt], al[mt], bh[nt]);
            uint32_t bl[4][2];
#pragma unroll
            for (int nt = 0; nt < 4; nt++) {
                int rn = wn + nt*8 + g;
                bl[nt][0] = *(const uint32_t*)&sBl[rn][cb];
                bl[nt][1] = *(const uint32_t*)&sBl[rn][cb+8];
            }
#pragma unroll
            for (int mt = 0; mt < 4; mt++)
#pragma unroll
                for (int nt = 0; nt < 4; nt++) MMA16816(acc[mt][nt], ah[mt], bl[nt]);
        }
        __syncthreads();
    }
#pragma unroll
    for (int mt = 0; mt < 4; mt++) {
        int r = m0 + wm + mt*16 + g;
#pragma unroll
        for (int nt = 0; nt < 4; nt++) {
            int cc = n0 + wn + nt*8 + tig*2;
#pragma unroll
            for (int q = 0; q < 4; q++) {
                int n  = cc + (q & 1);
                int rr = r + (q >> 1)*8;
                if (n < Ntot) {
                    int b = n / Lout, t = n - b*Lout;
                    Out[((size_t)b*Lout + t)*O + rr] = acc[mt][nt][q];
                }
            }
        }
    }
}

// ================= GRU: 8-CTA cluster per batch, DSMEM h exchange =================
static __device__ __forceinline__ void dsmem_store(uint32_t laddr, uint32_t rank, float v) {
    uint32_t dst;
    asm volatile("mapa.shared::cluster.u32 %0, %1, %2;" : "=r"(dst) : "r"(laddr), "r"(rank));
    asm volatile("st.shared::cluster.f32 [%0], %1;" :: "r"(dst), "f"(v) : "memory");
}
#define CLUSTER_SYNC() do { \
    asm volatile("barrier.cluster.arrive.aligned;" ::: "memory"); \
    asm volatile("barrier.cluster.wait.aligned;" ::: "memory"); } while(0)

__global__ void __cluster_dims__(8,1,1) gru_kernel(
    const float* __restrict__ gi, const float* __restrict__ whh,
    const float* __restrict__ bih, const float* __restrict__ bhh,
    const int* __restrict__ ts, const float* __restrict__ hidden,
    float* __restrict__ out)
{
    extern __shared__ float smg[];
    float* Ws   = smg;
    float* hs   = smg + 96*256;
    float* gh_s = hs + 512;
    uint32_t rank;
    asm("mov.u32 %0, %%cluster_ctarank;" : "=r"(rank));
    int b  = blockIdx.x >> 3;
    int j0 = rank * 32;
    int tid = threadIdx.x;
    int warp = tid >> 5, lane = tid & 31;

    for (int e = tid; e < 96*256; e += 128) {
        int gate = e >> 13;
        int rem  = e & 8191;
        int j    = rem >> 8;
        int k    = rem & 255;
        Ws[((gate*64 + (k>>2))*32 + j)*4 + (k&3)] = whh[((size_t)(gate*256 + j0 + j))*256 + k];
    }
    for (int e = tid; e < HID; e += 128) hs[e] = hidden[b*HID + e];
    int tsb = ts[b];
    float bihr=0.f,bihz=0.f,bihn=0.f,bhhr=0.f,bhhz=0.f,bhhn=0.f;
    if (warp == 0) {
        bihr = bih[j0+lane]; bihz = bih[256+j0+lane]; bihn = bih[512+j0+lane];
        bhhr = bhh[j0+lane]; bhhz = bhh[256+j0+lane]; bhhn = bhh[512+j0+lane];
    }
    __syncthreads();
    CLUSTER_SYNC();

    for (int t = 0; t < L5; t++) {
        const float* hcur = hs + (t & 1)*256;
        if (warp < 3) {
            const float4* wp = (const float4*)Ws + warp*2048 + lane;
            const float4* hp = (const float4*)hcur;
            float acc = 0.f;
#pragma unroll
            for (int k4 = 0; k4 < 64; k4++) {
                float4 w = wp[k4*32];
                float4 h = hp[k4];
                acc += w.x*h.x + w.y*h.y + w.z*h.z + w.w*h.w;
            }
            gh_s[warp*32 + lane] = acc;
        }
        __syncthreads();
        if (warp == 0) {
            int j = j0 + lane;
            const float* gb = gi + ((size_t)b*L5 + t)*G3;
            float gir = gb[j]       + bihr;
            float giz = gb[256 + j] + bihz;
            float gin = gb[512 + j] + bihn;
            float ghr = gh_s[lane]    + bhhr;
            float ghz = gh_s[32+lane] + bhhz;
            float ghn = gh_s[64+lane] + bhhn;
            float r   = 1.f/(1.f + expf(-(gir+ghr)));
            float zg  = 1.f/(1.f + expf(-(giz+ghz)));
            float n   = tanhf(gin + r*ghn);
            float hold = hcur[j];
            float hnew = (1.f - zg)*n + zg*hold;
            uint32_t laddr = smem_u32(hs + ((t+1)&1)*256 + j);
#pragma unroll
            for (int r2 = 0; r2 < 8; r2++) dsmem_store(laddr, (uint32_t)r2, hnew);
            if (t == tsb)   g_ct[b*HID + j] = hnew;
            if (t == L5-1)  out[2 + b*HID + j] = hnew;
        }
        CLUSTER_SYNC();
    }
}

// ================= head =================
__global__ void enc_kernel(const int* __restrict__ ts) {
    int idx = blockIdx.x*blockDim.x + threadIdx.x;
    if (idx >= KSTEP*BATCH*C512) return;
    int d = idx & 511;
    int b = (idx >> 9) & 15;
    int k = idx >> 13;
    int t = ts[b] + k + 1;
    float v = g_buf5[((size_t)b*C512 + d)*L5 + t];
    g_enc[idx] = fmaxf(v*g_scales[4*C512 + d] + g_shifts[4*C512 + d], 0.f);
}

__global__ void pred_kernel(const float* __restrict__ wkw, const float* __restrict__ wkb) {
    int k = blockIdx.x >> 4;
    int b = blockIdx.x & 15;
    __shared__ float cs[HID];
    if (threadIdx.x < HID) cs[threadIdx.x] = g_ct[b*HID + threadIdx.x];
    __syncthreads();
    int d = threadIdx.x;
    const float* wr = wkw + ((size_t)k*C512 + d)*HID;
    float acc = wkb[k*C512 + d];
#pragma unroll 8
    for (int h = 0; h < HID; h++) acc += cs[h]*wr[h];
    g_pred[(k*BATCH + b)*C512 + d] = acc;
}

__global__ void total_kernel() {
    int k = blockIdx.x >> 4;
    int b = blockIdx.x & 15;
    int c = threadIdx.x;
    if (c < BATCH) {
        const float* e = g_enc  + ((size_t)(k*BATCH + b))*C512;
        const float* p = g_pred + ((size_t)(k*BATCH + c))*C512;
        float acc = 0.f;
        for (int d = 0; d < C512; d++) acc += e[d]*p[d];
        g_total[(k*BATCH + b)*BATCH + c] = acc;
    }
}

__global__ void final_kernel(float* __restrict__ out) {
    __shared__ float red[192];
    __shared__ float lse11[16];
    __shared__ float corr[16];
    int tid = threadIdx.x;
    int k = tid >> 4, b = tid & 15;
    float contrib;
    {
        const float* row = g_total + tid*16;
        float mx = row[0];
        for (int c = 1; c < 16; c++) mx = fmaxf(mx, row[c]);
        float s = 0.f;
        for (int c = 0; c < 16; c++) s += expf(row[c]-mx);
        float lse = mx + logf(s);
        contrib = row[b] - lse;
        if (k == KSTEP-1) lse11[b] = lse;
    }
    red[tid] = contrib;
    __syncthreads();
    if (tid < 16) {
        int c = tid;
        const float* t11 = g_total + (KSTEP-1)*BATCH*BATCH;
        float best = -1e30f; int arg = -1;
        for (int bb = 0; bb < 16; bb++) {
            float v = expf(t11[bb*16 + c] - lse11[bb]);
            if (v > best) { best = v; arg = bb; }
        }
        corr[c] = (arg == c) ? 1.f : 0.f;
    }
    __syncthreads();
    if (tid == 0) {
        float s = 0.f;
        for (int i = 0; i < 192; i++) s += red[i];
        out[1] = s / (-1.f * BATCH * KSTEP);
        float a = 0.f;
        for (int i = 0; i < 16; i++) a += corr[i];
        out[0] = a / (float)BATCH;
    }
}

// ================= host =================
extern "C" void kernel_launch(void* const* d_in, const int* in_sizes, int n_in,
                              void* d_out, int out_size) {
    const float* x      = (const float*)d_in[0];
    const float* hidden = (const float*)d_in[1];
    const int*   ts     = (const int*)d_in[3];
    const float* w1     = (const float*)d_in[4];
    const float* w2     = (const float*)d_in[5];
    const float* w345   = (const float*)d_in[6];
    const float* gamma  = (const float*)d_in[7];
    const float* beta   = (const float*)d_in[8];
    const float* wih    = (const float*)d_in[9];
    const float* whh    = (const float*)d_in[10];
    const float* bih    = (const float*)d_in[11];
    const float* bhh    = (const float*)d_in[12];
    const float* wkw    = (const float*)d_in[13];
    const float* wkb    = (const float*)d_in[14];
    float* out = (float*)d_out;

    float *buf1, *buf2, *buf3, *buf4, *buf5, *gi;
    __nv_bfloat16 *wh, *wl, *a1h, *a1l, *a2h, *a2l, *a3h, *a3l, *a4h, *a4l;
    cudaGetSymbolAddress((void**)&buf1, g_buf1);
    cudaGetSymbolAddress((void**)&buf2, g_buf2);
    cudaGetSymbolAddress((void**)&buf3, g_buf3);
    cudaGetSymbolAddress((void**)&buf4, g_buf4);
    cudaGetSymbolAddress((void**)&buf5, g_buf5);
    cudaGetSymbolAddress((void**)&gi,   g_gi);
    cudaGetSymbolAddress((void**)&wh,   g_wh);
    cudaGetSymbolAddress((void**)&wl,   g_wl);
    cudaGetSymbolAddress((void**)&a1h,  g_a1h);
    cudaGetSymbolAddress((void**)&a1l,  g_a1l);
    cudaGetSymbolAddress((void**)&a2h,  g_a2h);
    cudaGetSymbolAddress((void**)&a2l,  g_a2l);
    cudaGetSymbolAddress((void**)&a3h,  g_a3h);
    cudaGetSymbolAddress((void**)&a3l,  g_a3l);
    cudaGetSymbolAddress((void**)&a4h,  g_a4h);
    cudaGetSymbolAddress((void**)&a4l,  g_a4l);

    cudaFuncSetAttribute(mmaconv_bf_kernel<8,4,2,2>, cudaFuncAttributeMaxDynamicSharedMemorySize, DYN_SMEM);
    cudaFuncSetAttribute(mmaconv_bf_kernel<4,2,1,1>, cudaFuncAttributeMaxDynamicSharedMemorySize, DYN_SMEM);

    // [0] prep (wcvt + conv1)
    prep_kernel<<<1024 + (WCVT_N + 255)/256, 256>>>(x, w1, w2, w345, wih);
    // [1] bn0 stats  [2] actcvt L1
    bnstats_kernel<<<C512, 256>>>(buf1, gamma + 0*C512, beta + 0*C512, L1, 0);
    actcvt_kernel<<<(BATCH*C512*L1P/2 + 255)/256, 256>>>(buf1, a1h, a1l, 0, L1, L1P, 2, BATCH*C512*L1P/2);
    // [3] conv2 (PROFILED)
    mmaconv_bf_kernel<8,4,2,2><<<dim3(4,500), 256, DYN_SMEM>>>(a1h, a1l, wh + WOFF2, wl + WOFF2, buf2, L1P, 512, L2, 4096, BATCH*L2);
    bnstats_kernel<<<C512, 256>>>(buf2, gamma + 1*C512, beta + 1*C512, L2, 1);
    actcvt_kernel<<<(BATCH*C512*L2P/2 + 255)/256, 256>>>(buf2, a2h, a2l, 1, L2, L2P, 1, BATCH*C512*L2P/2);

    mmaconv_bf_kernel<4,2,1,1><<<dim3(4,250), 256, DYN_SMEM>>>(a2h, a2l, wh + WOFF3, wl + WOFF3, buf3, L2P, 512, L3, 2048, BATCH*L3);
    bnstats_kernel<<<C512, 256>>>(buf3, gamma + 2*C512, beta + 2*C512, L3, 2);
    actcvt_kernel<<<(BATCH*C512*L3P/2 + 255)/256, 256>>>(buf3, a3h, a3l, 2, L3, L3P, 1, BATCH*C512*L3P/2);

    mmaconv_bf_kernel<4,2,1,1><<<dim3(4,125), 256, DYN_SMEM>>>(a3h, a3l, wh + WOFF4, wl + WOFF4, buf4, L3P, 512, L4, 2048, BATCH*L4);
    bnstats_kernel<<<C512, 256>>>(buf4, gamma + 3*C512, beta + 3*C512, L4, 3);
    actcvt_kernel<<<(BATCH*C512*L4P/2 + 255)/256, 256>>>(buf4, a4h, a4l, 3, L4, L4P, 1, BATCH*C512*L4P/2);

    mmaconv_bf_kernel<4,2,1,1><<<dim3(4,63), 256, DYN_SMEM>>>(a4h, a4l, wh + WOFF5, wl + WOFF5, buf5, L4P, 512, L5, 2048, BATCH*L5);
    bnstats_kernel<<<C512, 256>>>(buf5, gamma + 4*C512, beta + 4*C512, L5, 4);

    // gi = Wih . bnrelu(z)*mask  (old path, bn4+mask fused, [b][t][g] out)
    mmaconv_gi_kernel<<<dim3(6,63), 256>>>(buf5, wh + WOFFIH, wl + WOFFIH, gi, ts, 4, 512, L5, G3, L5, 512, BATCH*L5);

    // GRU
    int smg = (96*256 + 512 + 96) * (int)sizeof(float);
    cudaFuncSetAttribute(gru_kernel, cudaFuncAttributeMaxDynamicSharedMemorySize, smg);
    gru_kernel<<<128, 128, smg>>>(gi, whh, bih, bhh, ts, hidden, out);

    // head
    enc_kernel<<<(KSTEP*BATCH*C512 + 255)/256, 256>>>(ts);
    pred_kernel<<<KSTEP*BATCH, 512>>>(wkw, wkb);
    total_kernel<<<KSTEP*BATCH, 32>>>();
    final_kernel<<<1, 192>>>(out);
}

// round 8
// speedup vs baseline: 1.9532x; 1.0554x over previous
#include <cuda_runtime.h>
#include <cuda_bf16.h>
#include <math.h>
#include <stdint.h>

#define BATCH 16
#define C512  512
#define L0    80000
#define L1    16000
#define L2    4000
#define L3    2000
#define L4    1000
#define L5    500
#define KSTEP 12
#define HID   256
#define G3    768

// ---------------- scratch ----------------
__device__ float g_buf1[BATCH*C512*L1];
__device__ float g_buf2[BATCH*C512*L2];
__device__ float g_buf3[BATCH*C512*L3];
__device__ float g_buf4[BATCH*C512*L4];
__device__ float g_buf5[BATCH*C512*L5];
__device__ float g_gi  [BATCH*L5*G3];     // [b][t][g]
__device__ float g_scales[5*C512];
__device__ float g_shifts[5*C512];
__device__ float g_ct  [BATCH*HID];
__device__ float g_enc [KSTEP*BATCH*C512];
__device__ float g_pred[KSTEP*BATCH*C512];
__device__ float g_total[KSTEP*BATCH*BATCH];

// bf16 hi/lo weights (w2 @0, w345 @2M contiguous, wih @5M)
__device__ __nv_bfloat16 g_wh[6*1024*1024];
__device__ __nv_bfloat16 g_wl[6*1024*1024];
#define WOFF2   0
#define WOFF3   2097152
#define WOFF4   3145728
#define WOFF5   4194304
#define WOFFIH  5242880

// padded bf16 hi/lo activations
#define L1P (L1+4)
#define L2P (L2+2)
#define L3P (L3+2)
#define L4P (L4+2)
__device__ __nv_bfloat16 g_a1h[BATCH*C512*L1P];
__device__ __nv_bfloat16 g_a1l[BATCH*C512*L1P];
__device__ __nv_bfloat16 g_a2h[BATCH*C512*L2P];
__device__ __nv_bfloat16 g_a2l[BATCH*C512*L2P];
__device__ __nv_bfloat16 g_a3h[BATCH*C512*L3P];
__device__ __nv_bfloat16 g_a3l[BATCH*C512*L3P];
__device__ __nv_bfloat16 g_a4h[BATCH*C512*L4P];
__device__ __nv_bfloat16 g_a4l[BATCH*C512*L4P];

static __device__ __forceinline__ uint32_t smem_u32(const void* p) {
    return (uint32_t)__cvta_generic_to_shared(p);
}

// ================= prep: wcvt (all weights) + conv1 fused =================
#define C1_TCHUNK 250
#define WCVT_N 5636096
__global__ void prep_kernel(const float* __restrict__ x, const float* __restrict__ w1,
                            const float* __restrict__ w2, const float* __restrict__ w345,
                            const float* __restrict__ wih) {
    int bx = blockIdx.x;
    int tid = threadIdx.x;
    if (bx < 1024) {
        __shared__ float xs[C1_TCHUNK*5 + 10];
        __shared__ float ws[512*10];
        int b  = bx >> 6;
        int t0 = (bx & 63) * C1_TCHUNK;
        const float* xb = x + (size_t)b*L0;
        int pbase = 5*t0 - 3;
        for (int i = tid; i < C1_TCHUNK*5 + 10; i += 256) {
            int p = pbase + i;
            xs[i] = (p >= 0 && p < L0) ? xb[p] : 0.f;
        }
        for (int i = tid; i < 5120; i += 256) ws[i] = w1[i];
        __syncthreads();
        if (tid < C1_TCHUNK) {
            float* ob = g_buf1 + ((size_t)b*C512)*L1 + t0 + tid;
            const float* xp = xs + 5*tid;
            float xr[10];
#pragma unroll
            for (int k = 0; k < 10; k++) xr[k] = xp[k];
            for (int o = 0; o < 512; o++) {
                const float* wr = ws + o*10;
                float s = 0.f;
#pragma unroll
                for (int k = 0; k < 10; k++) s += xr[k]*wr[k];
                ob[(size_t)o*L1] = s;
            }
        }
    } else {
        int i = (bx - 1024)*256 + tid;
        if (i < WCVT_N) {
            float v = (i < 2097152) ? w2[i]
                    : (i < 5242880) ? w345[i - 2097152]
                                    : wih[i - 5242880];
            __nv_bfloat16 h = __float2bfloat16(v);
            g_wh[i] = h;
            g_wl[i] = __float2bfloat16(v - __bfloat162float(h));
        }
    }
}

// ================= BN stats (fp64, exact) =================
__global__ void bnstats_kernel(const float* __restrict__ buf, const float* __restrict__ gamma,
                               const float* __restrict__ beta, int L, int layer) {
    int c = blockIdx.x;
    int Bn = BATCH * L;
    double s = 0.0, s2 = 0.0;
    for (int i = threadIdx.x; i < Bn; i += blockDim.x) {
        int b = i / L, l = i - b*L;
        float v = buf[((size_t)b*C512 + c)*L + l];
        s += v; s2 += (double)v * v;
    }
    __shared__ double rs[256], rq[256];
    rs[threadIdx.x] = s; rq[threadIdx.x] = s2;
    __syncthreads();
    for (int o = 128; o > 0; o >>= 1) {
        if (threadIdx.x < o) { rs[threadIdx.x] += rs[threadIdx.x+o]; rq[threadIdx.x] += rq[threadIdx.x+o]; }
        __syncthreads();
    }
    if (threadIdx.x == 0) {
        double mean = rs[0] / Bn;
        double var  = rq[0] / Bn - mean*mean;
        double scd  = (double)gamma[c] / sqrt(var + 1e-5);
        g_scales[layer*C512 + c] = (float)scd;
        g_shifts[layer*C512 + c] = beta[c] - (float)(mean * scd);
    }
}

// ================= actcvt: bnrelu(fp32) -> padded bf16 hi/lo =================
__global__ void actcvt_kernel(const float* __restrict__ In, __nv_bfloat16* __restrict__ Oh,
                              __nv_bfloat16* __restrict__ Ol, int layer,
                              int L, int Lpad, int shift, int total2) {
    int idx = blockIdx.x*blockDim.x + threadIdx.x;
    if (idx >= total2) return;
    int base = idx*2;
    int q  = base % Lpad;
    int bc = base / Lpad;
    int c  = bc & 511;
    float sc = g_scales[layer*C512 + c];
    float sh = g_shifts[layer*C512 + c];
    const float* ip = In + (size_t)bc*L;
    __nv_bfloat162 h2, l2;
#pragma unroll
    for (int e = 0; e < 2; e++) {
        int p = q + e - shift;
        float v = 0.f;
        if (p >= 0 && p < L) v = fmaxf(ip[p]*sc + sh, 0.f);
        __nv_bfloat16 hb = __float2bfloat16(v);
        __nv_bfloat16 lb = __float2bfloat16(v - __bfloat162float(hb));
        if (e == 0) { h2.x = hb; l2.x = lb; } else { h2.y = hb; l2.y = lb; }
    }
    *(__nv_bfloat162*)(Oh + base) = h2;
    *(__nv_bfloat162*)(Ol + base) = l2;
}

// ================= mma.sync / ldmatrix helpers =================
#define MMA16816(d, a, b) \
    asm volatile( \
        "mma.sync.aligned.m16n8k16.row.col.f32.bf16.bf16.f32 " \
        "{%0,%1,%2,%3}, {%4,%5,%6,%7}, {%8,%9}, {%0,%1,%2,%3};" \
        : "+f"((d)[0]), "+f"((d)[1]), "+f"((d)[2]), "+f"((d)[3]) \
        : "r"((a)[0]), "r"((a)[1]), "r"((a)[2]), "r"((a)[3]), \
          "r"((b)[0]), "r"((b)[1]))

#define LDSM4(r0, r1, r2, r3, addr) \
    asm volatile("ldmatrix.sync.aligned.m8n8.x4.shared.b16 {%0,%1,%2,%3}, [%4];" \
        : "=r"(r0), "=r"(r1), "=r"(r2), "=r"(r3) : "r"(addr))

static __device__ __forceinline__ void cpa4(uint32_t dst, const void* src, uint32_t sz) {
    asm volatile("cp.async.ca.shared.global [%0], [%1], 4, %2;"
                 :: "r"(dst), "l"(src), "r"(sz) : "memory");
}
static __device__ __forceinline__ void cpa8(uint32_t dst, const void* src, uint32_t sz) {
    asm volatile("cp.async.ca.shared.global [%0], [%1], 8, %2;"
                 :: "r"(dst), "l"(src), "r"(sz) : "memory");
}
static __device__ __forceinline__ void cpa16(uint32_t dst, const void* src) {
    asm volatile("cp.async.cg.shared.global [%0], [%1], 16;"
                 :: "r"(dst), "l"(src) : "memory");
}

// ================= pipelined bf16 conv-as-GEMM (cp.async + ldmatrix) =================
// smem per stage (bf16 elems, stride 40): sBh 5120 | sBl 5120 | sAh 5120 | sAl 5120
#define STG_ELEMS 20480
#define DYN_SMEM  (2*STG_ELEMS*2)

template<int KW, int S, int P, int SHIFT>
__global__ void __launch_bounds__(256, 1) mmaconv_bf_kernel(
    const __nv_bfloat16* __restrict__ Inh, const __nv_bfloat16* __restrict__ Inl,
    const __nv_bfloat16* __restrict__ Wh,  const __nv_bfloat16* __restrict__ Wl,
    float* __restrict__ Out,
    int Lpad, int O, int Lout, int Kd, int Ntot)
{
    extern __shared__ __align__(16) __nv_bfloat16 dyn[];
    const int tid  = threadIdx.x;
    const int lane = tid & 31, w = tid >> 5;
    const int wm = (w >> 2) * 64, wn = (w & 3) * 32;
    const int m0 = blockIdx.x * 128, n0 = blockIdx.y * 128;
    const int g = lane >> 2, tig = lane & 3;
    const int C = Kd >> 5;

    // ldmatrix per-lane offsets (elements)
    const int lq = lane >> 3, lr = lane & 7;
    const int a_loff = ((lq & 1)*8 + lr)*40 + (lq >> 1)*8;
    const int b_loff = ((lq >> 1)*8 + lr)*40 + (lq & 1)*8;

    // per-thread B gather coords
    const int ITS = 16 / KW;
    const int bnn = tid & 127;
    const int clbase = tid >> 7;
    int bq;
    uint32_t bsz4, bsz8;
    {
        int n = n0 + bnn;
        bool vn = (n < Ntot);
        int nv = vn ? n : 0;
        int b = nv / Lout, t = nv - b*Lout;
        bsz4 = vn ? 4u : 0u;
        bsz8 = vn ? 8u : 0u;
        bq = (b*C512)*Lpad + S*t - P + SHIFT;
    }
    const int arow = tid >> 1, ahalf = tid & 1;

    auto load_chunk = [&](int c, int s) {
        __nv_bfloat16* stg = dyn + s*STG_ELEMS;
        const int k0 = c << 5;
        // A: 128 x 32 bf16 hi/lo
        {
            const __nv_bfloat16* srcH = Wh + (size_t)(m0 + arow)*Kd + k0 + ahalf*16;
            const __nv_bfloat16* srcL = Wl + (size_t)(m0 + arow)*Kd + k0 + ahalf*16;
            uint32_t dH = smem_u32(stg + 10240 + arow*40 + ahalf*16);
            uint32_t dL = smem_u32(stg + 15360 + arow*40 + ahalf*16);
            cpa16(dH, srcH);      cpa16(dH + 16, srcH + 8);
            cpa16(dL, srcL);      cpa16(dL + 16, srcL + 8);
        }
        // B: 128 x 32 bf16 hi/lo
        {
            const int c0 = k0 / KW;
#pragma unroll
            for (int it = 0; it < ITS; it++) {
                int cl = it*2 + clbase;
                int srcbase = bq + (c0 + cl)*Lpad;
                uint32_t dH = smem_u32(stg +        bnn*40 + cl*KW);
                uint32_t dL = smem_u32(stg + 5120 + bnn*40 + cl*KW);
                if (KW == 8) {
                    cpa8(dH,     Inh + srcbase,     bsz8);
                    cpa8(dH + 8, Inh + srcbase + 4, bsz8);
                    cpa8(dL,     Inl + srcbase,     bsz8);
                    cpa8(dL + 8, Inl + srcbase + 4, bsz8);
                } else {
#pragma unroll
                    for (int j = 0; j < KW/2; j++) {
                        cpa4(dH + j*4, Inh + srcbase + 2*j, bsz4);
                        cpa4(dL + j*4, Inl + srcbase + 2*j, bsz4);
                    }
                }
            }
        }
        asm volatile("cp.async.commit_group;" ::: "memory");
    };

    float acc[4][4][4];
#pragma unroll
    for (int i = 0; i < 4; i++)
#pragma unroll
        for (int j = 0; j < 4; j++)
#pragma unroll
            for (int q = 0; q < 4; q++) acc[i][j][q] = 0.f;

    load_chunk(0, 0);

    for (int c = 0; c < C; c++) {
        const int s = c & 1;
        if (c + 1 < C) {
            load_chunk(c + 1, s ^ 1);
            asm volatile("cp.async.wait_group 1;" ::: "memory");
        } else {
            asm volatile("cp.async.wait_group 0;" ::: "memory");
        }
        __syncthreads();

        const __nv_bfloat16* stg = dyn + s*STG_ELEMS;
        const uint32_t uBh = smem_u32(stg)         + (wn*40 + b_loff)*2;
        const uint32_t uBl = smem_u32(stg + 5120)  + (wn*40 + b_loff)*2;
        const uint32_t uAh = smem_u32(stg + 10240) + (wm*40 + a_loff)*2;
        const uint32_t uAl = smem_u32(stg + 15360) + (wm*40 + a_loff)*2;

#pragma unroll
        for (int ks = 0; ks < 32; ks += 16) {
            uint32_t ah[4][4], al[4][4], bh[4][2], bl[4][2];
#pragma unroll
            for (int mt = 0; mt < 4; mt++) {
                LDSM4(ah[mt][0], ah[mt][1], ah[mt][2], ah[mt][3], uAh + (mt*640 + ks)*2);
                LDSM4(al[mt][0], al[mt][1], al[mt][2], al[mt][3], uAl + (mt*640 + ks)*2);
            }
            LDSM4(bh[0][0], bh[0][1], bh[1][0], bh[1][1], uBh + ks*2);
            LDSM4(bh[2][0], bh[2][1], bh[3][0], bh[3][1], uBh + (640 + ks)*2);
#pragma unroll
            for (int mt = 0; mt < 4; mt++)
#pragma unroll
                for (int nt = 0; nt < 4; nt++) MMA16816(acc[mt][nt], ah[mt], bh[nt]);
#pragma unroll
            for (int mt = 0; mt < 4; mt++)
#pragma unroll
                for (int nt = 0; nt < 4; nt++) MMA16816(acc[mt][nt], al[mt], bh[nt]);
            LDSM4(bl[0][0], bl[0][1], bl[1][0], bl[1][1], uBl + ks*2);
            LDSM4(bl[2][0], bl[2][1], bl[3][0], bl[3][1], uBl + (640 + ks)*2);
#pragma unroll
            for (int mt = 0; mt < 4; mt++)
#pragma unroll
                for (int nt = 0; nt < 4; nt++) MMA16816(acc[mt][nt], ah[mt], bl[nt]);
        }
        __syncthreads();
    }

    // ---- epilogue ----
#pragma unroll
    for (int mt = 0; mt < 4; mt++) {
        int r = m0 + wm + mt*16 + g;
#pragma unroll
        for (int nt = 0; nt < 4; nt++) {
            int cc = n0 + wn + nt*8 + tig*2;
#pragma unroll
            for (int q = 0; q < 4; q++) {
                int n  = cc + (q & 1);
                int rr = r + (q >> 1)*8;
                if (n < Ntot) {
                    int b = n / Lout, t = n - b*Lout;
                    Out[((size_t)(b*O + rr))*Lout + t] = acc[mt][nt][q];
                }
            }
        }
    }
}

// ================= old-path mmaconv for gi (KW=1, masked, transposed) =================
#define SMSTRIDE 34
__global__ void __launch_bounds__(256, 2) mmaconv_gi_kernel(
    const float* __restrict__ In, const __nv_bfloat16* __restrict__ Wh,
    const __nv_bfloat16* __restrict__ Wl, float* __restrict__ Out,
    const int* __restrict__ ts, int bnlayer,
    int Cin, int Lin, int O, int Lout, int Kd, int Ntot)
{
    __shared__ __nv_bfloat16 sAh[128][SMSTRIDE];
    __shared__ __nv_bfloat16 sAl[128][SMSTRIDE];
    __shared__ __nv_bfloat16 sBh[128][SMSTRIDE];
    __shared__ __nv_bfloat16 sBl[128][SMSTRIDE];
    const int tid  = threadIdx.x;
    const int lane = tid & 31, w = tid >> 5;
    const int wm = (w >> 2) * 64, wn = (w & 3) * 32;
    const int m0 = blockIdx.x * 128, n0 = blockIdx.y * 128;
    const float* __restrict__ scale = g_scales + bnlayer*C512;
    const float* __restrict__ shift = g_shifts + bnlayer*C512;
    const int g = lane >> 2, tig = lane & 3;
    const int arow = tid >> 1, ak0 = (tid & 1) * 16;
    const int nchunks = Kd >> 5;

    float acc[4][4][4];
#pragma unroll
    for (int i = 0; i < 4; i++)
#pragma unroll
        for (int j = 0; j < 4; j++)
#pragma unroll
            for (int q = 0; q < 4; q++) acc[i][j][q] = 0.f;

    for (int c = 0; c < nchunks; c++) {
        const int k0 = c << 5;
        {
            const size_t go = (size_t)(m0 + arow)*Kd + k0 + ak0;
            uint4 ha = *(const uint4*)(Wh + go);
            uint4 hb = *(const uint4*)(Wh + go + 8);
            uint4 la = *(const uint4*)(Wl + go);
            uint4 lb = *(const uint4*)(Wl + go + 8);
            uint32_t* dh = (uint32_t*)&sAh[arow][ak0];
            uint32_t* dl = (uint32_t*)&sAl[arow][ak0];
            dh[0]=ha.x; dh[1]=ha.y; dh[2]=ha.z; dh[3]=ha.w;
            dh[4]=hb.x; dh[5]=hb.y; dh[6]=hb.z; dh[7]=hb.w;
            dl[0]=la.x; dl[1]=la.y; dl[2]=la.z; dl[3]=la.w;
            dl[4]=lb.x; dl[5]=lb.y; dl[6]=lb.z; dl[7]=lb.w;
        }
        {
#pragma unroll
            for (int it = 0; it < 16; it++) {
                int idx = it*256 + tid;
                int nn = idx & 127;
                int cl = idx >> 7;
                int cch = k0 + cl;
                int n = n0 + nn;
                bool vn = (n < Ntot);
                int b = 0, t = 0;
                if (vn) { b = n / Lout; t = n - b*Lout; }
                float sc = __ldg(scale + cch), sh = __ldg(shift + cch);
                bool ok = vn && (t <= __ldg(ts + b));
                float v = 0.f;
                if (ok) v = fmaxf(__ldg(In + ((size_t)(b*Cin + cch))*Lin + t)*sc + sh, 0.f);
                __nv_bfloat16 hb16 = __float2bfloat16(v);
                sBh[nn][cl] = hb16;
                sBl[nn][cl] = __float2bfloat16(v - __bfloat162float(hb16));
            }
        }
        __syncthreads();
#pragma unroll
        for (int ks = 0; ks < 32; ks += 16) {
            const int cb = ks + tig*2;
            uint32_t ah[4][4], al[4][4], bh[4][2];
#pragma unroll
            for (int mt = 0; mt < 4; mt++) {
                int r = wm + mt*16 + g;
                ah[mt][0] = *(const uint32_t*)&sAh[r][cb];
                ah[mt][1] = *(const uint32_t*)&sAh[r+8][cb];
                ah[mt][2] = *(const uint32_t*)&sAh[r][cb+8];
                ah[mt][3] = *(const uint32_t*)&sAh[r+8][cb+8];
                al[mt][0] = *(const uint32_t*)&sAl[r][cb];
                al[mt][1] = *(const uint32_t*)&sAl[r+8][cb];
                al[mt][2] = *(const uint32_t*)&sAl[r][cb+8];
                al[mt][3] = *(const uint32_t*)&sAl[r+8][cb+8];
            }
#pragma unroll
            for (int nt = 0; nt < 4; nt++) {
                int rn = wn + nt*8 + g;
                bh[nt][0] = *(const uint32_t*)&sBh[rn][cb];
                bh[nt][1] = *(const uint32_t*)&sBh[rn][cb+8];
            }
#pragma unroll
            for (int mt = 0; mt < 4; mt++)
#pragma unroll
                for (int nt = 0; nt < 4; nt++) MMA16816(acc[mt][nt], ah[mt], bh[nt]);
#pragma unroll
            for (int mt = 0; mt < 4; mt++)
#pragma unroll
                for (int nt = 0; nt < 4; nt++) MMA16816(acc[mt][nt], al[mt], bh[nt]);
            uint32_t bl[4][2];
#pragma unroll
            for (int nt = 0; nt < 4; nt++) {
                int rn = wn + nt*8 + g;
                bl[nt][0] = *(const uint32_t*)&sBl[rn][cb];
                bl[nt][1] = *(const uint32_t*)&sBl[rn][cb+8];
            }
#pragma unroll
            for (int mt = 0; mt < 4; mt++)
#pragma unroll
                for (int nt = 0; nt < 4; nt++) MMA16816(acc[mt][nt], ah[mt], bl[nt]);
        }
        __syncthreads();
    }
#pragma unroll
    for (int mt = 0; mt < 4; mt++) {
        int r = m0 + wm + mt*16 + g;
#pragma unroll
        for (int nt = 0; nt < 4; nt++) {
            int cc = n0 + wn + nt*8 + tig*2;
#pragma unroll
            for (int q = 0; q < 4; q++) {
                int n  = cc + (q & 1);
                int rr = r + (q >> 1)*8;
                if (n < Ntot) {
                    int b = n / Lout, t = n - b*Lout;
                    Out[((size_t)b*Lout + t)*O + rr] = acc[mt][nt][q];
                }
            }
        }
    }
}

// ================= GRU: 8-CTA cluster per batch, DSMEM h exchange =================
static __device__ __forceinline__ void dsmem_store(uint32_t laddr, uint32_t rank, float v) {
    uint32_t dst;
    asm volatile("mapa.shared::cluster.u32 %0, %1, %2;" : "=r"(dst) : "r"(laddr), "r"(rank));
    asm volatile("st.shared::cluster.f32 [%0], %1;" :: "r"(dst), "f"(v) : "memory");
}
#define CLUSTER_SYNC() do { \
    asm volatile("barrier.cluster.arrive.aligned;" ::: "memory"); \
    asm volatile("barrier.cluster.wait.aligned;" ::: "memory"); } while(0)

__global__ void __cluster_dims__(8,1,1) gru_kernel(
    const float* __restrict__ gi, const float* __restrict__ whh,
    const float* __restrict__ bih, const float* __restrict__ bhh,
    const int* __restrict__ ts, const float* __restrict__ hidden,
    float* __restrict__ out)
{
    extern __shared__ float smg[];
    float* Ws   = smg;
    float* hs   = smg + 96*256;
    float* gh_s = hs + 512;
    uint32_t rank;
    asm("mov.u32 %0, %%cluster_ctarank;" : "=r"(rank));
    int b  = blockIdx.x >> 3;
    int j0 = rank * 32;
    int tid = threadIdx.x;
    int warp = tid >> 5, lane = tid & 31;

    for (int e = tid; e < 96*256; e += 128) {
        int gate = e >> 13;
        int rem  = e & 8191;
        int j    = rem >> 8;
        int k    = rem & 255;
        Ws[((gate*64 + (k>>2))*32 + j)*4 + (k&3)] = whh[((size_t)(gate*256 + j0 + j))*256 + k];
    }
    for (int e = tid; e < HID; e += 128) hs[e] = hidden[b*HID + e];
    int tsb = ts[b];
    float bihr=0.f,bihz=0.f,bihn=0.f,bhhr=0.f,bhhz=0.f,bhhn=0.f;
    if (warp == 0) {
        bihr = bih[j0+lane]; bihz = bih[256+j0+lane]; bihn = bih[512+j0+lane];
        bhhr = bhh[j0+lane]; bhhz = bhh[256+j0+lane]; bhhn = bhh[512+j0+lane];
    }
    __syncthreads();
    CLUSTER_SYNC();

    for (int t = 0; t < L5; t++) {
        const float* hcur = hs + (t & 1)*256;
        if (warp < 3) {
            const float4* wp = (const float4*)Ws + warp*2048 + lane;
            const float4* hp = (const float4*)hcur;
            float acc = 0.f;
#pragma unroll
            for (int k4 = 0; k4 < 64; k4++) {
                float4 w = wp[k4*32];
                float4 h = hp[k4];
                acc += w.x*h.x + w.y*h.y + w.z*h.z + w.w*h.w;
            }
            gh_s[warp*32 + lane] = acc;
        }
        __syncthreads();
        if (warp == 0) {
            int j = j0 + lane;
            const float* gb = gi + ((size_t)b*L5 + t)*G3;
            float gir = gb[j]       + bihr;
            float giz = gb[256 + j] + bihz;
            float gin = gb[512 + j] + bihn;
            float ghr = gh_s[lane]    + bhhr;
            float ghz = gh_s[32+lane] + bhhz;
            float ghn = gh_s[64+lane] + bhhn;
            float r   = 1.f/(1.f + expf(-(gir+ghr)));
            float zg  = 1.f/(1.f + expf(-(giz+ghz)));
            float n   = tanhf(gin + r*ghn);
            float hold = hcur[j];
            float hnew = (1.f - zg)*n + zg*hold;
            uint32_t laddr = smem_u32(hs + ((t+1)&1)*256 + j);
#pragma unroll
            for (int r2 = 0; r2 < 8; r2++) dsmem_store(laddr, (uint32_t)r2, hnew);
            if (t == tsb)   g_ct[b*HID + j] = hnew;
            if (t == L5-1)  out[2 + b*HID + j] = hnew;
        }
        CLUSTER_SYNC();
    }
}

// ================= head =================
__global__ void enc_kernel(const int* __restrict__ ts) {
    int idx = blockIdx.x*blockDim.x + threadIdx.x;
    if (idx >= KSTEP*BATCH*C512) return;
    int d = idx & 511;
    int b = (idx >> 9) & 15;
    int k = idx >> 13;
    int t = ts[b] + k + 1;
    float v = g_buf5[((size_t)b*C512 + d)*L5 + t];
    g_enc[idx] = fmaxf(v*g_scales[4*C512 + d] + g_shifts[4*C512 + d], 0.f);
}

__global__ void pred_kernel(const float* __restrict__ wkw, const float* __restrict__ wkb) {
    int k = blockIdx.x >> 4;
    int b = blockIdx.x & 15;
    __shared__ float cs[HID];
    if (threadIdx.x < HID) cs[threadIdx.x] = g_ct[b*HID + threadIdx.x];
    __syncthreads();
    int d = threadIdx.x;
    const float* wr = wkw + ((size_t)k*C512 + d)*HID;
    float acc = wkb[k*C512 + d];
#pragma unroll 8
    for (int h = 0; h < HID; h++) acc += cs[h]*wr[h];
    g_pred[(k*BATCH + b)*C512 + d] = acc;
}

__global__ void total_kernel() {
    int k = blockIdx.x >> 4;
    int b = blockIdx.x & 15;
    int c = threadIdx.x;
    if (c < BATCH) {
        const float* e = g_enc  + ((size_t)(k*BATCH + b))*C512;
        const float* p = g_pred + ((size_t)(k*BATCH + c))*C512;
        float acc = 0.f;
        for (int d = 0; d < C512; d++) acc += e[d]*p[d];
        g_total[(k*BATCH + b)*BATCH + c] = acc;
    }
}

__global__ void final_kernel(float* __restrict__ out) {
    __shared__ float red[192];
    __shared__ float lse11[16];
    __shared__ float corr[16];
    int tid = threadIdx.x;
    int k = tid >> 4, b = tid & 15;
    float contrib;
    {
        const float* row = g_total + tid*16;
        float mx = row[0];
        for (int c = 1; c < 16; c++) mx = fmaxf(mx, row[c]);
        float s = 0.f;
        for (int c = 0; c < 16; c++) s += expf(row[c]-mx);
        float lse = mx + logf(s);
        contrib = row[b] - lse;
        if (k == KSTEP-1) lse11[b] = lse;
    }
    red[tid] = contrib;
    __syncthreads();
    if (tid < 16) {
        int c = tid;
        const float* t11 = g_total + (KSTEP-1)*BATCH*BATCH;
        float best = -1e30f; int arg = -1;
        for (int bb = 0; bb < 16; bb++) {
            float v = expf(t11[bb*16 + c] - lse11[bb]);
            if (v > best) { best = v; arg = bb; }
        }
        corr[c] = (arg == c) ? 1.f : 0.f;
    }
    __syncthreads();
    if (tid == 0) {
        float s = 0.f;
        for (int i = 0; i < 192; i++) s += red[i];
        out[1] = s / (-1.f * BATCH * KSTEP);
        float a = 0.f;
        for (int i = 0; i < 16; i++) a += corr[i];
        out[0] = a / (float)BATCH;
    }
}

// ================= host =================
extern "C" void kernel_launch(void* const* d_in, const int* in_sizes, int n_in,
                              void* d_out, int out_size) {
    const float* x      = (const float*)d_in[0];
    const float* hidden = (const float*)d_in[1];
    const int*   ts     = (const int*)d_in[3];
    const float* w1     = (const float*)d_in[4];
    const float* w2     = (const float*)d_in[5];
    const float* w345   = (const float*)d_in[6];
    const float* gamma  = (const float*)d_in[7];
    const float* beta   = (const float*)d_in[8];
    const float* wih    = (const float*)d_in[9];
    const float* whh    = (const float*)d_in[10];
    const float* bih    = (const float*)d_in[11];
    const float* bhh    = (const float*)d_in[12];
    const float* wkw    = (const float*)d_in[13];
    const float* wkb    = (const float*)d_in[14];
    float* out = (float*)d_out;

    float *buf1, *buf2, *buf3, *buf4, *buf5, *gi;
    __nv_bfloat16 *wh, *wl, *a1h, *a1l, *a2h, *a2l, *a3h, *a3l, *a4h, *a4l;
    cudaGetSymbolAddress((void**)&buf1, g_buf1);
    cudaGetSymbolAddress((void**)&buf2, g_buf2);
    cudaGetSymbolAddress((void**)&buf3, g_buf3);
    cudaGetSymbolAddress((void**)&buf4, g_buf4);
    cudaGetSymbolAddress((void**)&buf5, g_buf5);
    cudaGetSymbolAddress((void**)&gi,   g_gi);
    cudaGetSymbolAddress((void**)&wh,   g_wh);
    cudaGetSymbolAddress((void**)&wl,   g_wl);
    cudaGetSymbolAddress((void**)&a1h,  g_a1h);
    cudaGetSymbolAddress((void**)&a1l,  g_a1l);
    cudaGetSymbolAddress((void**)&a2h,  g_a2h);
    cudaGetSymbolAddress((void**)&a2l,  g_a2l);
    cudaGetSymbolAddress((void**)&a3h,  g_a3h);
    cudaGetSymbolAddress((void**)&a3l,  g_a3l);
    cudaGetSymbolAddress((void**)&a4h,  g_a4h);
    cudaGetSymbolAddress((void**)&a4l,  g_a4l);

    cudaFuncSetAttribute(mmaconv_bf_kernel<8,4,2,2>, cudaFuncAttributeMaxDynamicSharedMemorySize, DYN_SMEM);
    cudaFuncSetAttribute(mmaconv_bf_kernel<4,2,1,1>, cudaFuncAttributeMaxDynamicSharedMemorySize, DYN_SMEM);

    // [0] prep (wcvt + conv1)
    prep_kernel<<<1024 + (WCVT_N + 255)/256, 256>>>(x, w1, w2, w345, wih);
    // [1] bn0 stats  [2] actcvt L1
    bnstats_kernel<<<C512, 256>>>(buf1, gamma + 0*C512, beta + 0*C512, L1, 0);
    actcvt_kernel<<<(BATCH*C512*L1P/2 + 255)/256, 256>>>(buf1, a1h, a1l, 0, L1, L1P, 2, BATCH*C512*L1P/2);
    // [3] conv2 (PROFILED)
    mmaconv_bf_kernel<8,4,2,2><<<dim3(4,500), 256, DYN_SMEM>>>(a1h, a1l, wh + WOFF2, wl + WOFF2, buf2, L1P, 512, L2, 4096, BATCH*L2);
    bnstats_kernel<<<C512, 256>>>(buf2, gamma + 1*C512, beta + 1*C512, L2, 1);
    actcvt_kernel<<<(BATCH*C512*L2P/2 + 255)/256, 256>>>(buf2, a2h, a2l, 1, L2, L2P, 1, BATCH*C512*L2P/2);

    mmaconv_bf_kernel<4,2,1,1><<<dim3(4,250), 256, DYN_SMEM>>>(a2h, a2l, wh + WOFF3, wl + WOFF3, buf3, L2P, 512, L3, 2048, BATCH*L3);
    bnstats_kernel<<<C512, 256>>>(buf3, gamma + 2*C512, beta + 2*C512, L3, 2);
    actcvt_kernel<<<(BATCH*C512*L3P/2 + 255)/256, 256>>>(buf3, a3h, a3l, 2, L3, L3P, 1, BATCH*C512*L3P/2);

    mmaconv_bf_kernel<4,2,1,1><<<dim3(4,125), 256, DYN_SMEM>>>(a3h, a3l, wh + WOFF4, wl + WOFF4, buf4, L3P, 512, L4, 2048, BATCH*L4);
    bnstats_kernel<<<C512, 256>>>(buf4, gamma + 3*C512, beta + 3*C512, L4, 3);
    actcvt_kernel<<<(BATCH*C512*L4P/2 + 255)/256, 256>>>(buf4, a4h, a4l, 3, L4, L4P, 1, BATCH*C512*L4P/2);

    mmaconv_bf_kernel<4,2,1,1><<<dim3(4,63), 256, DYN_SMEM>>>(a4h, a4l, wh + WOFF5, wl + WOFF5, buf5, L4P, 512, L5, 2048, BATCH*L5);
    bnstats_kernel<<<C512, 256>>>(buf5, gamma + 4*C512, beta + 4*C512, L5, 4);

    // gi = Wih . bnrelu(z)*mask  (bn4+mask fused, [b][t][g] out)
    mmaconv_gi_kernel<<<dim3(6,63), 256>>>(buf5, wh + WOFFIH, wl + WOFFIH, gi, ts, 4, 512, L5, G3, L5, 512, BATCH*L5);

    // GRU
    int smg = (96*256 + 512 + 96) * (int)sizeof(float);
    cudaFuncSetAttribute(gru_kernel, cudaFuncAttributeMaxDynamicSharedMemorySize, smg);
    gru_kernel<<<128, 128, smg>>>(gi, whh, bih, bhh, ts, hidden, out);

    // head
    enc_kernel<<<(KSTEP*BATCH*C512 + 255)/256, 256>>>(ts);
    pred_kernel<<<KSTEP*BATCH, 512>>>(wkw, wkb);
    total_kernel<<<KSTEP*BATCH, 32>>>();
    final_kernel<<<1, 192>>>(out);
}

// round 9
// speedup vs baseline: 2.2656x; 1.1599x over previous
#include <cuda_runtime.h>
#include <cuda_bf16.h>
#include <math.h>
#include <stdint.h>

#define BATCH 16
#define C512  512
#define L0    80000
#define L1    16000
#define L2    4000
#define L3    2000
#define L4    1000
#define L5    500
#define KSTEP 12
#define HID   256
#define G3    768

// ---------------- scratch ----------------
__device__ float g_buf1[BATCH*C512*L1];
__device__ float g_buf2[BATCH*C512*L2];
__device__ float g_buf3[BATCH*C512*L3];
__device__ float g_buf4[BATCH*C512*L4];
__device__ float g_buf5[BATCH*C512*L5];
__device__ float g_gi  [BATCH*L5*G3];     // [b][t][g]
__device__ float g_scales[5*C512];
__device__ float g_shifts[5*C512];
__device__ float g_ct  [BATCH*HID];
__device__ float g_enc [KSTEP*BATCH*C512];
__device__ float g_pred[KSTEP*BATCH*C512];
__device__ float g_total[KSTEP*BATCH*BATCH];

// bf16 hi/lo weights (w2 @0, w345 @2M contiguous, wih @5M)
__device__ __nv_bfloat16 g_wh[6*1024*1024];
__device__ __nv_bfloat16 g_wl[6*1024*1024];
#define WOFF2   0
#define WOFF3   2097152
#define WOFF4   3145728
#define WOFF5   4194304
#define WOFFIH  5242880

// padded bf16 hi/lo activations
#define L1P (L1+4)
#define L2P (L2+2)
#define L3P (L3+2)
#define L4P (L4+2)
__device__ __nv_bfloat16 g_a1h[BATCH*C512*L1P];
__device__ __nv_bfloat16 g_a1l[BATCH*C512*L1P];
__device__ __nv_bfloat16 g_a2h[BATCH*C512*L2P];
__device__ __nv_bfloat16 g_a2l[BATCH*C512*L2P];
__device__ __nv_bfloat16 g_a3h[BATCH*C512*L3P];
__device__ __nv_bfloat16 g_a3l[BATCH*C512*L3P];
__device__ __nv_bfloat16 g_a4h[BATCH*C512*L4P];
__device__ __nv_bfloat16 g_a4l[BATCH*C512*L4P];

static __device__ __forceinline__ uint32_t smem_u32(const void* p) {
    return (uint32_t)__cvta_generic_to_shared(p);
}

// ================= prep: wcvt (all weights) + conv1 fused =================
#define C1_TCHUNK 250
#define WCVT_N 5636096
__global__ void prep_kernel(const float* __restrict__ x, const float* __restrict__ w1,
                            const float* __restrict__ w2, const float* __restrict__ w345,
                            const float* __restrict__ wih) {
    int bx = blockIdx.x;
    int tid = threadIdx.x;
    if (bx < 1024) {
        __shared__ float xs[C1_TCHUNK*5 + 10];
        __shared__ float ws[512*10];
        int b  = bx >> 6;
        int t0 = (bx & 63) * C1_TCHUNK;
        const float* xb = x + (size_t)b*L0;
        int pbase = 5*t0 - 3;
        for (int i = tid; i < C1_TCHUNK*5 + 10; i += 256) {
            int p = pbase + i;
            xs[i] = (p >= 0 && p < L0) ? xb[p] : 0.f;
        }
        for (int i = tid; i < 5120; i += 256) ws[i] = w1[i];
        __syncthreads();
        if (tid < C1_TCHUNK) {
            float* ob = g_buf1 + ((size_t)b*C512)*L1 + t0 + tid;
            const float* xp = xs + 5*tid;
            float xr[10];
#pragma unroll
            for (int k = 0; k < 10; k++) xr[k] = xp[k];
            for (int o = 0; o < 512; o++) {
                const float* wr = ws + o*10;
                float s = 0.f;
#pragma unroll
                for (int k = 0; k < 10; k++) s += xr[k]*wr[k];
                ob[(size_t)o*L1] = s;
            }
        }
    } else {
        int i = (bx - 1024)*256 + tid;
        if (i < WCVT_N) {
            float v = (i < 2097152) ? w2[i]
                    : (i < 5242880) ? w345[i - 2097152]
                                    : wih[i - 5242880];
            __nv_bfloat16 h = __float2bfloat16(v);
            g_wh[i] = h;
            g_wl[i] = __float2bfloat16(v - __bfloat162float(h));
        }
    }
}

// ================= BN stats (fp64, exact) =================
__global__ void bnstats_kernel(const float* __restrict__ buf, const float* __restrict__ gamma,
                               const float* __restrict__ beta, int L, int layer) {
    int c = blockIdx.x;
    int Bn = BATCH * L;
    double s = 0.0, s2 = 0.0;
    for (int i = threadIdx.x; i < Bn; i += blockDim.x) {
        int b = i / L, l = i - b*L;
        float v = buf[((size_t)b*C512 + c)*L + l];
        s += v; s2 += (double)v * v;
    }
    __shared__ double rs[256], rq[256];
    rs[threadIdx.x] = s; rq[threadIdx.x] = s2;
    __syncthreads();
    for (int o = 128; o > 0; o >>= 1) {
        if (threadIdx.x < o) { rs[threadIdx.x] += rs[threadIdx.x+o]; rq[threadIdx.x] += rq[threadIdx.x+o]; }
        __syncthreads();
    }
    if (threadIdx.x == 0) {
        double mean = rs[0] / Bn;
        double var  = rq[0] / Bn - mean*mean;
        double scd  = (double)gamma[c] / sqrt(var + 1e-5);
        g_scales[layer*C512 + c] = (float)scd;
        g_shifts[layer*C512 + c] = beta[c] - (float)(mean * scd);
    }
}

// ================= actcvt: bnrelu(fp32) -> padded bf16 hi/lo =================
__global__ void actcvt_kernel(const float* __restrict__ In, __nv_bfloat16* __restrict__ Oh,
                              __nv_bfloat16* __restrict__ Ol, int layer,
                              int L, int Lpad, int shift, int total2) {
    int idx = blockIdx.x*blockDim.x + threadIdx.x;
    if (idx >= total2) return;
    int base = idx*2;
    int q  = base % Lpad;
    int bc = base / Lpad;
    int c  = bc & 511;
    float sc = g_scales[layer*C512 + c];
    float sh = g_shifts[layer*C512 + c];
    const float* ip = In + (size_t)bc*L;
    __nv_bfloat162 h2, l2;
#pragma unroll
    for (int e = 0; e < 2; e++) {
        int p = q + e - shift;
        float v = 0.f;
        if (p >= 0 && p < L) v = fmaxf(ip[p]*sc + sh, 0.f);
        __nv_bfloat16 hb = __float2bfloat16(v);
        __nv_bfloat16 lb = __float2bfloat16(v - __bfloat162float(hb));
        if (e == 0) { h2.x = hb; l2.x = lb; } else { h2.y = hb; l2.y = lb; }
    }
    *(__nv_bfloat162*)(Oh + base) = h2;
    *(__nv_bfloat162*)(Ol + base) = l2;
}

// ================= mma.sync / ldmatrix helpers =================
#define MMA16816(d, a, b) \
    asm volatile( \
        "mma.sync.aligned.m16n8k16.row.col.f32.bf16.bf16.f32 " \
        "{%0,%1,%2,%3}, {%4,%5,%6,%7}, {%8,%9}, {%0,%1,%2,%3};" \
        : "+f"((d)[0]), "+f"((d)[1]), "+f"((d)[2]), "+f"((d)[3]) \
        : "r"((a)[0]), "r"((a)[1]), "r"((a)[2]), "r"((a)[3]), \
          "r"((b)[0]), "r"((b)[1]))

#define LDSM4(r0, r1, r2, r3, addr) \
    asm volatile("ldmatrix.sync.aligned.m8n8.x4.shared.b16 {%0,%1,%2,%3}, [%4];" \
        : "=r"(r0), "=r"(r1), "=r"(r2), "=r"(r3) : "r"(addr))

static __device__ __forceinline__ void cpa4(uint32_t dst, const void* src, uint32_t sz) {
    asm volatile("cp.async.ca.shared.global [%0], [%1], 4, %2;"
                 :: "r"(dst), "l"(src), "r"(sz) : "memory");
}
static __device__ __forceinline__ void cpa8(uint32_t dst, const void* src, uint32_t sz) {
    asm volatile("cp.async.ca.shared.global [%0], [%1], 8, %2;"
                 :: "r"(dst), "l"(src), "r"(sz) : "memory");
}
static __device__ __forceinline__ void cpa16(uint32_t dst, const void* src) {
    asm volatile("cp.async.cg.shared.global [%0], [%1], 16;"
                 :: "r"(dst), "l"(src) : "memory");
}

// ================= pipelined bf16 conv-as-GEMM (cp.async + ldmatrix, 2 CTAs/SM) =================
// smem per stage (bf16 elems, stride 40): sBh 5120 | sBl 5120 | sAh 5120 | sAl 5120
#define STG_ELEMS 20480
#define DYN_SMEM  (2*STG_ELEMS*2)

template<int KW, int S, int P, int SHIFT>
__global__ void __launch_bounds__(256, 2) mmaconv_bf_kernel(
    const __nv_bfloat16* __restrict__ Inh, const __nv_bfloat16* __restrict__ Inl,
    const __nv_bfloat16* __restrict__ Wh,  const __nv_bfloat16* __restrict__ Wl,
    float* __restrict__ Out,
    int Lpad, int O, int Lout, int Kd, int Ntot)
{
    extern __shared__ __align__(16) __nv_bfloat16 dyn[];
    const int tid  = threadIdx.x;
    const int lane = tid & 31, w = tid >> 5;
    const int wm = (w >> 2) * 64, wn = (w & 3) * 32;
    const int m0 = blockIdx.x * 128, n0 = blockIdx.y * 128;
    const int g = lane >> 2, tig = lane & 3;
    const int C = Kd >> 5;

    // ldmatrix per-lane offsets (elements)
    const int lq = lane >> 3, lr = lane & 7;
    const int a_loff = ((lq & 1)*8 + lr)*40 + (lq >> 1)*8;
    const int b_loff = ((lq >> 1)*8 + lr)*40 + (lq & 1)*8;

    // per-thread B gather coords
    const int ITS = 16 / KW;
    const int bnn = tid & 127;
    const int clbase = tid >> 7;
    int bq;
    uint32_t bsz4, bsz8;
    {
        int n = n0 + bnn;
        bool vn = (n < Ntot);
        int nv = vn ? n : 0;
        int b = nv / Lout, t = nv - b*Lout;
        bsz4 = vn ? 4u : 0u;
        bsz8 = vn ? 8u : 0u;
        bq = (b*C512)*Lpad + S*t - P + SHIFT;
    }
    const int arow = tid >> 1, ahalf = tid & 1;

    auto load_chunk = [&](int c, int s) {
        __nv_bfloat16* stg = dyn + s*STG_ELEMS;
        const int k0 = c << 5;
        // A: 128 x 32 bf16 hi/lo
        {
            const __nv_bfloat16* srcH = Wh + (size_t)(m0 + arow)*Kd + k0 + ahalf*16;
            const __nv_bfloat16* srcL = Wl + (size_t)(m0 + arow)*Kd + k0 + ahalf*16;
            uint32_t dH = smem_u32(stg + 10240 + arow*40 + ahalf*16);
            uint32_t dL = smem_u32(stg + 15360 + arow*40 + ahalf*16);
            cpa16(dH, srcH);      cpa16(dH + 16, srcH + 8);
            cpa16(dL, srcL);      cpa16(dL + 16, srcL + 8);
        }
        // B: 128 x 32 bf16 hi/lo
        {
            const int c0 = k0 / KW;
#pragma unroll
            for (int it = 0; it < ITS; it++) {
                int cl = it*2 + clbase;
                int srcbase = bq + (c0 + cl)*Lpad;
                uint32_t dH = smem_u32(stg +        bnn*40 + cl*KW);
                uint32_t dL = smem_u32(stg + 5120 + bnn*40 + cl*KW);
                if (KW == 8) {
                    cpa8(dH,     Inh + srcbase,     bsz8);
                    cpa8(dH + 8, Inh + srcbase + 4, bsz8);
                    cpa8(dL,     Inl + srcbase,     bsz8);
                    cpa8(dL + 8, Inl + srcbase + 4, bsz8);
                } else {
#pragma unroll
                    for (int j = 0; j < KW/2; j++) {
                        cpa4(dH + j*4, Inh + srcbase + 2*j, bsz4);
                        cpa4(dL + j*4, Inl + srcbase + 2*j, bsz4);
                    }
                }
            }
        }
        asm volatile("cp.async.commit_group;" ::: "memory");
    };

    float acc[4][4][4];
#pragma unroll
    for (int i = 0; i < 4; i++)
#pragma unroll
        for (int j = 0; j < 4; j++)
#pragma unroll
            for (int q = 0; q < 4; q++) acc[i][j][q] = 0.f;

    load_chunk(0, 0);

    for (int c = 0; c < C; c++) {
        const int s = c & 1;
        if (c + 1 < C) {
            load_chunk(c + 1, s ^ 1);
            asm volatile("cp.async.wait_group 1;" ::: "memory");
        } else {
            asm volatile("cp.async.wait_group 0;" ::: "memory");
        }
        __syncthreads();

        const __nv_bfloat16* stg = dyn + s*STG_ELEMS;
        const uint32_t uBh = smem_u32(stg)         + (wn*40 + b_loff)*2;
        const uint32_t uBl = smem_u32(stg + 5120)  + (wn*40 + b_loff)*2;
        const uint32_t uAh = smem_u32(stg + 10240) + (wm*40 + a_loff)*2;
        const uint32_t uAl = smem_u32(stg + 15360) + (wm*40 + a_loff)*2;

#pragma unroll
        for (int ks = 0; ks < 32; ks += 16) {
            uint32_t ah[4][4], al[4][4], bh[4][2], bl[4][2];
#pragma unroll
            for (int mt = 0; mt < 4; mt++) {
                LDSM4(ah[mt][0], ah[mt][1], ah[mt][2], ah[mt][3], uAh + (mt*640 + ks)*2);
                LDSM4(al[mt][0], al[mt][1], al[mt][2], al[mt][3], uAl + (mt*640 + ks)*2);
            }
            LDSM4(bh[0][0], bh[0][1], bh[1][0], bh[1][1], uBh + ks*2);
            LDSM4(bh[2][0], bh[2][1], bh[3][0], bh[3][1], uBh + (640 + ks)*2);
#pragma unroll
            for (int mt = 0; mt < 4; mt++)
#pragma unroll
                for (int nt = 0; nt < 4; nt++) MMA16816(acc[mt][nt], ah[mt], bh[nt]);
#pragma unroll
            for (int mt = 0; mt < 4; mt++)
#pragma unroll
                for (int nt = 0; nt < 4; nt++) MMA16816(acc[mt][nt], al[mt], bh[nt]);
            LDSM4(bl[0][0], bl[0][1], bl[1][0], bl[1][1], uBl + ks*2);
            LDSM4(bl[2][0], bl[2][1], bl[3][0], bl[3][1], uBl + (640 + ks)*2);
#pragma unroll
            for (int mt = 0; mt < 4; mt++)
#pragma unroll
                for (int nt = 0; nt < 4; nt++) MMA16816(acc[mt][nt], ah[mt], bl[nt]);
        }
        __syncthreads();
    }

    // ---- epilogue ----
#pragma unroll
    for (int mt = 0; mt < 4; mt++) {
        int r = m0 + wm + mt*16 + g;
#pragma unroll
        for (int nt = 0; nt < 4; nt++) {
            int cc = n0 + wn + nt*8 + tig*2;
#pragma unroll
            for (int q = 0; q < 4; q++) {
                int n  = cc + (q & 1);
                int rr = r + (q >> 1)*8;
                if (n < Ntot) {
                    int b = n / Lout, t = n - b*Lout;
                    Out[((size_t)(b*O + rr))*Lout + t] = acc[mt][nt][q];
                }
            }
        }
    }
}

// ================= old-path mmaconv for gi (KW=1, masked, transposed) =================
#define SMSTRIDE 34
__global__ void __launch_bounds__(256, 2) mmaconv_gi_kernel(
    const float* __restrict__ In, const __nv_bfloat16* __restrict__ Wh,
    const __nv_bfloat16* __restrict__ Wl, float* __restrict__ Out,
    const int* __restrict__ ts, int bnlayer,
    int Cin, int Lin, int O, int Lout, int Kd, int Ntot)
{
    __shared__ __nv_bfloat16 sAh[128][SMSTRIDE];
    __shared__ __nv_bfloat16 sAl[128][SMSTRIDE];
    __shared__ __nv_bfloat16 sBh[128][SMSTRIDE];
    __shared__ __nv_bfloat16 sBl[128][SMSTRIDE];
    const int tid  = threadIdx.x;
    const int lane = tid & 31, w = tid >> 5;
    const int wm = (w >> 2) * 64, wn = (w & 3) * 32;
    const int m0 = blockIdx.x * 128, n0 = blockIdx.y * 128;
    const float* __restrict__ scale = g_scales + bnlayer*C512;
    const float* __restrict__ shift = g_shifts + bnlayer*C512;
    const int g = lane >> 2, tig = lane & 3;
    const int arow = tid >> 1, ak0 = (tid & 1) * 16;
    const int nchunks = Kd >> 5;

    float acc[4][4][4];
#pragma unroll
    for (int i = 0; i < 4; i++)
#pragma unroll
        for (int j = 0; j < 4; j++)
#pragma unroll
            for (int q = 0; q < 4; q++) acc[i][j][q] = 0.f;

    for (int c = 0; c < nchunks; c++) {
        const int k0 = c << 5;
        {
            const size_t go = (size_t)(m0 + arow)*Kd + k0 + ak0;
            uint4 ha = *(const uint4*)(Wh + go);
            uint4 hb = *(const uint4*)(Wh + go + 8);
            uint4 la = *(const uint4*)(Wl + go);
            uint4 lb = *(const uint4*)(Wl + go + 8);
            uint32_t* dh = (uint32_t*)&sAh[arow][ak0];
            uint32_t* dl = (uint32_t*)&sAl[arow][ak0];
            dh[0]=ha.x; dh[1]=ha.y; dh[2]=ha.z; dh[3]=ha.w;
            dh[4]=hb.x; dh[5]=hb.y; dh[6]=hb.z; dh[7]=hb.w;
            dl[0]=la.x; dl[1]=la.y; dl[2]=la.z; dl[3]=la.w;
            dl[4]=lb.x; dl[5]=lb.y; dl[6]=lb.z; dl[7]=lb.w;
        }
        {
#pragma unroll
            for (int it = 0; it < 16; it++) {
                int idx = it*256 + tid;
                int nn = idx & 127;
                int cl = idx >> 7;
                int cch = k0 + cl;
                int n = n0 + nn;
                bool vn = (n < Ntot);
                int b = 0, t = 0;
                if (vn) { b = n / Lout; t = n - b*Lout; }
                float sc = __ldg(scale + cch), sh = __ldg(shift + cch);
                bool ok = vn && (t <= __ldg(ts + b));
                float v = 0.f;
                if (ok) v = fmaxf(__ldg(In + ((size_t)(b*Cin + cch))*Lin + t)*sc + sh, 0.f);
                __nv_bfloat16 hb16 = __float2bfloat16(v);
                sBh[nn][cl] = hb16;
                sBl[nn][cl] = __float2bfloat16(v - __bfloat162float(hb16));
            }
        }
        __syncthreads();
#pragma unroll
        for (int ks = 0; ks < 32; ks += 16) {
            const int cb = ks + tig*2;
            uint32_t ah[4][4], al[4][4], bh[4][2];
#pragma unroll
            for (int mt = 0; mt < 4; mt++) {
                int r = wm + mt*16 + g;
                ah[mt][0] = *(const uint32_t*)&sAh[r][cb];
                ah[mt][1] = *(const uint32_t*)&sAh[r+8][cb];
                ah[mt][2] = *(const uint32_t*)&sAh[r][cb+8];
                ah[mt][3] = *(const uint32_t*)&sAh[r+8][cb+8];
                al[mt][0] = *(const uint32_t*)&sAl[r][cb];
                al[mt][1] = *(const uint32_t*)&sAl[r+8][cb];
                al[mt][2] = *(const uint32_t*)&sAl[r][cb+8];
                al[mt][3] = *(const uint32_t*)&sAl[r+8][cb+8];
            }
#pragma unroll
            for (int nt = 0; nt < 4; nt++) {
                int rn = wn + nt*8 + g;
                bh[nt][0] = *(const uint32_t*)&sBh[rn][cb];
                bh[nt][1] = *(const uint32_t*)&sBh[rn][cb+8];
            }
#pragma unroll
            for (int mt = 0; mt < 4; mt++)
#pragma unroll
                for (int nt = 0; nt < 4; nt++) MMA16816(acc[mt][nt], ah[mt], bh[nt]);
#pragma unroll
            for (int mt = 0; mt < 4; mt++)
#pragma unroll
                for (int nt = 0; nt < 4; nt++) MMA16816(acc[mt][nt], al[mt], bh[nt]);
            uint32_t bl[4][2];
#pragma unroll
            for (int nt = 0; nt < 4; nt++) {
                int rn = wn + nt*8 + g;
                bl[nt][0] = *(const uint32_t*)&sBl[rn][cb];
                bl[nt][1] = *(const uint32_t*)&sBl[rn][cb+8];
            }
#pragma unroll
            for (int mt = 0; mt < 4; mt++)
#pragma unroll
                for (int nt = 0; nt < 4; nt++) MMA16816(acc[mt][nt], ah[mt], bl[nt]);
        }
        __syncthreads();
    }
#pragma unroll
    for (int mt = 0; mt < 4; mt++) {
        int r = m0 + wm + mt*16 + g;
#pragma unroll
        for (int nt = 0; nt < 4; nt++) {
            int cc = n0 + wn + nt*8 + tig*2;
#pragma unroll
            for (int q = 0; q < 4; q++) {
                int n  = cc + (q & 1);
                int rr = r + (q >> 1)*8;
                if (n < Ntot) {
                    int b = n / Lout, t = n - b*Lout;
                    Out[((size_t)b*Lout + t)*O + rr] = acc[mt][nt][q];
                }
            }
        }
    }
}

// ================= GRU: 8-CTA cluster per batch, DSMEM h exchange =================
static __device__ __forceinline__ void dsmem_store(uint32_t laddr, uint32_t rank, float v) {
    uint32_t dst;
    asm volatile("mapa.shared::cluster.u32 %0, %1, %2;" : "=r"(dst) : "r"(laddr), "r"(rank));
    asm volatile("st.shared::cluster.f32 [%0], %1;" :: "r"(dst), "f"(v) : "memory");
}
#define CLUSTER_SYNC() do { \
    asm volatile("barrier.cluster.arrive.aligned;" ::: "memory"); \
    asm volatile("barrier.cluster.wait.aligned;" ::: "memory"); } while(0)

__global__ void __cluster_dims__(8,1,1) gru_kernel(
    const float* __restrict__ gi, const float* __restrict__ whh,
    const float* __restrict__ bih, const float* __restrict__ bhh,
    const int* __restrict__ ts, const float* __restrict__ hidden,
    float* __restrict__ out)
{
    extern __shared__ float smg[];
    float* Ws   = smg;
    float* hs   = smg + 96*256;
    float* gh_s = hs + 512;
    uint32_t rank;
    asm("mov.u32 %0, %%cluster_ctarank;" : "=r"(rank));
    int b  = blockIdx.x >> 3;
    int j0 = rank * 32;
    int tid = threadIdx.x;
    int warp = tid >> 5, lane = tid & 31;

    for (int e = tid; e < 96*256; e += 128) {
        int gate = e >> 13;
        int rem  = e & 8191;
        int j    = rem >> 8;
        int k    = rem & 255;
        Ws[((gate*64 + (k>>2))*32 + j)*4 + (k&3)] = whh[((size_t)(gate*256 + j0 + j))*256 + k];
    }
    for (int e = tid; e < HID; e += 128) hs[e] = hidden[b*HID + e];
    int tsb = ts[b];
    float bihr=0.f,bihz=0.f,bihn=0.f,bhhr=0.f,bhhz=0.f,bhhn=0.f;
    if (warp == 0) {
        bihr = bih[j0+lane]; bihz = bih[256+j0+lane]; bihn = bih[512+j0+lane];
        bhhr = bhh[j0+lane]; bhhz = bhh[256+j0+lane]; bhhn = bhh[512+j0+lane];
    }
    __syncthreads();
    CLUSTER_SYNC();

    for (int t = 0; t < L5; t++) {
        const float* hcur = hs + (t & 1)*256;
        if (warp < 3) {
            const float4* wp = (const float4*)Ws + warp*2048 + lane;
            const float4* hp = (const float4*)hcur;
            float acc = 0.f;
#pragma unroll
            for (int k4 = 0; k4 < 64; k4++) {
                float4 w = wp[k4*32];
                float4 h = hp[k4];
                acc += w.x*h.x + w.y*h.y + w.z*h.z + w.w*h.w;
            }
            gh_s[warp*32 + lane] = acc;
        }
        __syncthreads();
        if (warp == 0) {
            int j = j0 + lane;
            const float* gb = gi + ((size_t)b*L5 + t)*G3;
            float gir = gb[j]       + bihr;
            float giz = gb[256 + j] + bihz;
            float gin = gb[512 + j] + bihn;
            float ghr = gh_s[lane]    + bhhr;
            float ghz = gh_s[32+lane] + bhhz;
            float ghn = gh_s[64+lane] + bhhn;
            float r   = 1.f/(1.f + expf(-(gir+ghr)));
            float zg  = 1.f/(1.f + expf(-(giz+ghz)));
            float n   = tanhf(gin + r*ghn);
            float hold = hcur[j];
            float hnew = (1.f - zg)*n + zg*hold;
            uint32_t laddr = smem_u32(hs + ((t+1)&1)*256 + j);
#pragma unroll
            for (int r2 = 0; r2 < 8; r2++) dsmem_store(laddr, (uint32_t)r2, hnew);
            if (t == tsb)   g_ct[b*HID + j] = hnew;
            if (t == L5-1)  out[2 + b*HID + j] = hnew;
        }
        CLUSTER_SYNC();
    }
}

// ================= head =================
__global__ void enc_kernel(const int* __restrict__ ts) {
    int idx = blockIdx.x*blockDim.x + threadIdx.x;
    if (idx >= KSTEP*BATCH*C512) return;
    int d = idx & 511;
    int b = (idx >> 9) & 15;
    int k = idx >> 13;
    int t = ts[b] + k + 1;
    float v = g_buf5[((size_t)b*C512 + d)*L5 + t];
    g_enc[idx] = fmaxf(v*g_scales[4*C512 + d] + g_shifts[4*C512 + d], 0.f);
}

__global__ void pred_kernel(const float* __restrict__ wkw, const float* __restrict__ wkb) {
    int k = blockIdx.x >> 4;
    int b = blockIdx.x & 15;
    __shared__ float cs[HID];
    if (threadIdx.x < HID) cs[threadIdx.x] = g_ct[b*HID + threadIdx.x];
    __syncthreads();
    int d = threadIdx.x;
    const float* wr = wkw + ((size_t)k*C512 + d)*HID;
    float acc = wkb[k*C512 + d];
#pragma unroll 8
    for (int h = 0; h < HID; h++) acc += cs[h]*wr[h];
    g_pred[(k*BATCH + b)*C512 + d] = acc;
}

__global__ void total_kernel() {
    int k = blockIdx.x >> 4;
    int b = blockIdx.x & 15;
    int c = threadIdx.x;
    if (c < BATCH) {
        const float* e = g_enc  + ((size_t)(k*BATCH + b))*C512;
        const float* p = g_pred + ((size_t)(k*BATCH + c))*C512;
        float acc = 0.f;
        for (int d = 0; d < C512; d++) acc += e[d]*p[d];
        g_total[(k*BATCH + b)*BATCH + c] = acc;
    }
}

__global__ void final_kernel(float* __restrict__ out) {
    __shared__ float red[192];
    __shared__ float lse11[16];
    __shared__ float corr[16];
    int tid = threadIdx.x;
    int k = tid >> 4, b = tid & 15;
    float contrib;
    {
        const float* row = g_total + tid*16;
        float mx = row[0];
        for (int c = 1; c < 16; c++) mx = fmaxf(mx, row[c]);
        float s = 0.f;
        for (int c = 0; c < 16; c++) s += expf(row[c]-mx);
        float lse = mx + logf(s);
        contrib = row[b] - lse;
        if (k == KSTEP-1) lse11[b] = lse;
    }
    red[tid] = contrib;
    __syncthreads();
    if (tid < 16) {
        int c = tid;
        const float* t11 = g_total + (KSTEP-1)*BATCH*BATCH;
        float best = -1e30f; int arg = -1;
        for (int bb = 0; bb < 16; bb++) {
            float v = expf(t11[bb*16 + c] - lse11[bb]);
            if (v > best) { best = v; arg = bb; }
        }
        corr[c] = (arg == c) ? 1.f : 0.f;
    }
    __syncthreads();
    if (tid == 0) {
        float s = 0.f;
        for (int i = 0; i < 192; i++) s += red[i];
        out[1] = s / (-1.f * BATCH * KSTEP);
        float a = 0.f;
        for (int i = 0; i < 16; i++) a += corr[i];
        out[0] = a / (float)BATCH;
    }
}

// ================= host =================
extern "C" void kernel_launch(void* const* d_in, const int* in_sizes, int n_in,
                              void* d_out, int out_size) {
    const float* x      = (const float*)d_in[0];
    const float* hidden = (const float*)d_in[1];
    const int*   ts     = (const int*)d_in[3];
    const float* w1     = (const float*)d_in[4];
    const float* w2     = (const float*)d_in[5];
    const float* w345   = (const float*)d_in[6];
    const float* gamma  = (const float*)d_in[7];
    const float* beta   = (const float*)d_in[8];
    const float* wih    = (const float*)d_in[9];
    const float* whh    = (const float*)d_in[10];
    const float* bih    = (const float*)d_in[11];
    const float* bhh    = (const float*)d_in[12];
    const float* wkw    = (const float*)d_in[13];
    const float* wkb    = (const float*)d_in[14];
    float* out = (float*)d_out;

    float *buf1, *buf2, *buf3, *buf4, *buf5, *gi;
    __nv_bfloat16 *wh, *wl, *a1h, *a1l, *a2h, *a2l, *a3h, *a3l, *a4h, *a4l;
    cudaGetSymbolAddress((void**)&buf1, g_buf1);
    cudaGetSymbolAddress((void**)&buf2, g_buf2);
    cudaGetSymbolAddress((void**)&buf3, g_buf3);
    cudaGetSymbolAddress((void**)&buf4, g_buf4);
    cudaGetSymbolAddress((void**)&buf5, g_buf5);
    cudaGetSymbolAddress((void**)&gi,   g_gi);
    cudaGetSymbolAddress((void**)&wh,   g_wh);
    cudaGetSymbolAddress((void**)&wl,   g_wl);
    cudaGetSymbolAddress((void**)&a1h,  g_a1h);
    cudaGetSymbolAddress((void**)&a1l,  g_a1l);
    cudaGetSymbolAddress((void**)&a2h,  g_a2h);
    cudaGetSymbolAddress((void**)&a2l,  g_a2l);
    cudaGetSymbolAddress((void**)&a3h,  g_a3h);
    cudaGetSymbolAddress((void**)&a3l,  g_a3l);
    cudaGetSymbolAddress((void**)&a4h,  g_a4h);
    cudaGetSymbolAddress((void**)&a4l,  g_a4l);

    cudaFuncSetAttribute(mmaconv_bf_kernel<8,4,2,2>, cudaFuncAttributeMaxDynamicSharedMemorySize, DYN_SMEM);
    cudaFuncSetAttribute(mmaconv_bf_kernel<4,2,1,1>, cudaFuncAttributeMaxDynamicSharedMemorySize, DYN_SMEM);

    // [0] prep (wcvt + conv1)
    prep_kernel<<<1024 + (WCVT_N + 255)/256, 256>>>(x, w1, w2, w345, wih);
    // [1] bn0 stats  [2] actcvt L1
    bnstats_kernel<<<C512, 256>>>(buf1, gamma + 0*C512, beta + 0*C512, L1, 0);
    actcvt_kernel<<<(BATCH*C512*L1P/2 + 255)/256, 256>>>(buf1, a1h, a1l, 0, L1, L1P, 2, BATCH*C512*L1P/2);
    // [3] conv2 (PROFILED)
    mmaconv_bf_kernel<8,4,2,2><<<dim3(4,500), 256, DYN_SMEM>>>(a1h, a1l, wh + WOFF2, wl + WOFF2, buf2, L1P, 512, L2, 4096, BATCH*L2);
    bnstats_kernel<<<C512, 256>>>(buf2, gamma + 1*C512, beta + 1*C512, L2, 1);
    actcvt_kernel<<<(BATCH*C512*L2P/2 + 255)/256, 256>>>(buf2, a2h, a2l, 1, L2, L2P, 1, BATCH*C512*L2P/2);

    mmaconv_bf_kernel<4,2,1,1><<<dim3(4,250), 256, DYN_SMEM>>>(a2h, a2l, wh + WOFF3, wl + WOFF3, buf3, L2P, 512, L3, 2048, BATCH*L3);
    bnstats_kernel<<<C512, 256>>>(buf3, gamma + 2*C512, beta + 2*C512, L3, 2);
    actcvt_kernel<<<(BATCH*C512*L3P/2 + 255)/256, 256>>>(buf3, a3h, a3l, 2, L3, L3P, 1, BATCH*C512*L3P/2);

    mmaconv_bf_kernel<4,2,1,1><<<dim3(4,125), 256, DYN_SMEM>>>(a3h, a3l, wh + WOFF4, wl + WOFF4, buf4, L3P, 512, L4, 2048, BATCH*L4);
    bnstats_kernel<<<C512, 256>>>(buf4, gamma + 3*C512, beta + 3*C512, L4, 3);
    actcvt_kernel<<<(BATCH*C512*L4P/2 + 255)/256, 256>>>(buf4, a4h, a4l, 3, L4, L4P, 1, BATCH*C512*L4P/2);

    mmaconv_bf_kernel<4,2,1,1><<<dim3(4,63), 256, DYN_SMEM>>>(a4h, a4l, wh + WOFF5, wl + WOFF5, buf5, L4P, 512, L5, 2048, BATCH*L5);
    bnstats_kernel<<<C512, 256>>>(buf5, gamma + 4*C512, beta + 4*C512, L5, 4);

    // gi = Wih . bnrelu(z)*mask  (bn4+mask fused, [b][t][g] out)
    mmaconv_gi_kernel<<<dim3(6,63), 256>>>(buf5, wh + WOFFIH, wl + WOFFIH, gi, ts, 4, 512, L5, G3, L5, 512, BATCH*L5);

    // GRU
    int smg = (96*256 + 512 + 96) * (int)sizeof(float);
    cudaFuncSetAttribute(gru_kernel, cudaFuncAttributeMaxDynamicSharedMemorySize, smg);
    gru_kernel<<<128, 128, smg>>>(gi, whh, bih, bhh, ts, hidden, out);

    // head
    enc_kernel<<<(KSTEP*BATCH*C512 + 255)/256, 256>>>(ts);
    pred_kernel<<<KSTEP*BATCH, 512>>>(wkw, wkb);
    total_kernel<<<KSTEP*BATCH, 32>>>();
    final_kernel<<<1, 192>>>(out);
}

// round 11
// speedup vs baseline: 2.4410x; 1.0774x over previous
#include <cuda_runtime.h>
#include <cuda_bf16.h>
#include <math.h>
#include <stdint.h>

#define BATCH 16
#define C512  512
#define L0    80000
#define L1    16000
#define L2    4000
#define L3    2000
#define L4    1000
#define L5    500
#define KSTEP 12
#define HID   256
#define G3    768

// ---------------- scratch ----------------
__device__ float g_buf1[BATCH*C512*L1];
__device__ float g_buf2[BATCH*C512*L2];
__device__ float g_buf3[BATCH*C512*L3];
__device__ float g_buf4[BATCH*C512*L4];
__device__ float g_buf5[BATCH*C512*L5];
__device__ float g_gi  [BATCH*L5*G3];     // [b][t][g]
__device__ float g_scales[5*C512];
__device__ float g_shifts[5*C512];
__device__ float g_ct  [BATCH*HID];
__device__ float g_enc [KSTEP*BATCH*C512];
__device__ float g_pred[KSTEP*BATCH*C512];
__device__ float g_total[KSTEP*BATCH*BATCH];

// BN partial sums
__device__ float g_psum[512*C512];        // [y][ch]
__device__ float g_psq [512*C512];
__device__ float g_bn0ps[BATCH*C512];     // [b][ch]
__device__ float g_bn0pq[BATCH*C512];

// bf16 hi/lo weights (w2 @0, w345 @2M contiguous, wih @5M)
__device__ __nv_bfloat16 g_wh[6*1024*1024];
__device__ __nv_bfloat16 g_wl[6*1024*1024];
#define WOFF2   0
#define WOFF3   2097152
#define WOFF4   3145728
#define WOFF5   4194304
#define WOFFIH  5242880

// padded bf16 hi/lo activations
#define L1P (L1+4)
#define L2P (L2+2)
#define L3P (L3+2)
#define L4P (L4+2)
__device__ __nv_bfloat16 g_a1h[BATCH*C512*L1P];
__device__ __nv_bfloat16 g_a1l[BATCH*C512*L1P];
__device__ __nv_bfloat16 g_a2h[BATCH*C512*L2P];
__device__ __nv_bfloat16 g_a2l[BATCH*C512*L2P];
__device__ __nv_bfloat16 g_a3h[BATCH*C512*L3P];
__device__ __nv_bfloat16 g_a3l[BATCH*C512*L3P];
__device__ __nv_bfloat16 g_a4h[BATCH*C512*L4P];
__device__ __nv_bfloat16 g_a4l[BATCH*C512*L4P];
__device__ __nv_bfloat16 g_a5h[BATCH*C512*L5];  // masked z (for gi)
__device__ __nv_bfloat16 g_a5l[BATCH*C512*L5];

static __device__ __forceinline__ uint32_t smem_u32(const void* p) {
    return (uint32_t)__cvta_generic_to_shared(p);
}

// ================= prep: conv1 (with bn0 partials) + wcvt =================
#define WCVT_N 5636096
__global__ void prep_kernel(const float* __restrict__ x, const float* __restrict__ w1,
                            const float* __restrict__ w2, const float* __restrict__ w345,
                            const float* __restrict__ wih) {
    int bx = blockIdx.x;
    int tid = threadIdx.x;
    if (bx < 512) {
        __shared__ float ws[160];
        __shared__ float red[256];
        int b  = bx >> 5;
        int o0 = (bx & 31) * 16;
        if (tid < 160) ws[tid] = w1[o0*10 + tid];
        __syncthreads();
        float ps[16], pq[16];
#pragma unroll
        for (int o = 0; o < 16; o++) { ps[o] = 0.f; pq[o] = 0.f; }
        const float* xb = x + (size_t)b*L0;
        float* ob = g_buf1 + ((size_t)(b*C512 + o0))*L1;
        for (int t = tid; t < L1; t += 256) {
            float xr[10];
            int p0 = 5*t - 3;
#pragma unroll
            for (int k = 0; k < 10; k++) {
                int p = p0 + k;
                xr[k] = (p >= 0 && p < L0) ? __ldg(xb + p) : 0.f;
            }
#pragma unroll
            for (int o = 0; o < 16; o++) {
                const float* wr = ws + o*10;
                float s = 0.f;
#pragma unroll
                for (int k = 0; k < 10; k++) s += xr[k]*wr[k];
                ob[(size_t)o*L1 + t] = s;
                ps[o] += s; pq[o] += s*s;
            }
        }
        for (int o = 0; o < 16; o++) {
            red[tid] = ps[o]; __syncthreads();
            for (int off = 128; off > 0; off >>= 1) {
                if (tid < off) red[tid] += red[tid + off];
                __syncthreads();
            }
            if (tid == 0) g_bn0ps[b*C512 + o0 + o] = red[0];
            __syncthreads();
            red[tid] = pq[o]; __syncthreads();
            for (int off = 128; off > 0; off >>= 1) {
                if (tid < off) red[tid] += red[tid + off];
                __syncthreads();
            }
            if (tid == 0) g_bn0pq[b*C512 + o0 + o] = red[0];
            __syncthreads();
        }
    } else {
        int i = (bx - 512)*256 + tid;
        if (i < WCVT_N) {
            float v = (i < 2097152) ? w2[i]
                    : (i < 5242880) ? w345[i - 2097152]
                                    : wih[i - 5242880];
            __nv_bfloat16 h = __float2bfloat16(v);
            g_wh[i] = h;
            g_wl[i] = __float2bfloat16(v - __bfloat162float(h));
        }
    }
}

// ================= bn0 reduce (tiny) =================
__global__ void bn0reduce_kernel(const float* __restrict__ gamma, const float* __restrict__ beta) {
    int c = blockIdx.x*256 + threadIdx.x;
    if (c >= C512) return;
    double s = 0.0, q = 0.0;
    for (int b = 0; b < BATCH; b++) { s += (double)g_bn0ps[b*C512 + c]; q += (double)g_bn0pq[b*C512 + c]; }
    double Bn = (double)BATCH * L1;
    double mean = s / Bn;
    double var  = q / Bn - mean*mean;
    double scd  = (double)gamma[c] / sqrt(var + 1e-5);
    g_scales[c] = (float)scd;
    g_shifts[c] = beta[c] - (float)(mean * scd);
}

// ================= actcvt (layer 1 only) =================
__global__ void actcvt_kernel(const float* __restrict__ In, __nv_bfloat16* __restrict__ Oh,
                              __nv_bfloat16* __restrict__ Ol, int layer,
                              int L, int Lpad, int shift, int total2) {
    int idx = blockIdx.x*blockDim.x + threadIdx.x;
    if (idx >= total2) return;
    int base = idx*2;
    int q  = base % Lpad;
    int bc = base / Lpad;
    int c  = bc & 511;
    float sc = g_scales[layer*C512 + c];
    float sh = g_shifts[layer*C512 + c];
    const float* ip = In + (size_t)bc*L;
    __nv_bfloat162 h2, l2;
#pragma unroll
    for (int e = 0; e < 2; e++) {
        int p = q + e - shift;
        float v = 0.f;
        if (p >= 0 && p < L) v = fmaxf(ip[p]*sc + sh, 0.f);
        __nv_bfloat16 hb = __float2bfloat16(v);
        __nv_bfloat16 lb = __float2bfloat16(v - __bfloat162float(hb));
        if (e == 0) { h2.x = hb; l2.x = lb; } else { h2.y = hb; l2.y = lb; }
    }
    *(__nv_bfloat162*)(Oh + base) = h2;
    *(__nv_bfloat162*)(Ol + base) = l2;
}

// ================= bncvt: reduce partials -> scales, then convert channel ==========
template<bool MASK>
__global__ void bncvt_kernel(const float* __restrict__ buf, __nv_bfloat16* __restrict__ Oh,
                             __nv_bfloat16* __restrict__ Ol,
                             const float* __restrict__ gamma, const float* __restrict__ beta,
                             int layer, int L, int Lpad, int shift, int Y,
                             const int* __restrict__ ts) {
    __shared__ double rs[256], rq[256];
    __shared__ float sscale, sshift;
    int c = blockIdx.x;
    int tid = threadIdx.x;
    double s = 0.0, q = 0.0;
    for (int y = tid; y < Y; y += 256) {
        s += (double)g_psum[y*C512 + c];
        q += (double)g_psq [y*C512 + c];
    }
    rs[tid] = s; rq[tid] = q;
    __syncthreads();
    for (int off = 128; off > 0; off >>= 1) {
        if (tid < off) { rs[tid] += rs[tid+off]; rq[tid] += rq[tid+off]; }
        __syncthreads();
    }
    if (tid == 0) {
        double Bn = (double)BATCH * L;
        double mean = rs[0] / Bn;
        double var  = rq[0] / Bn - mean*mean;
        double scd  = (double)gamma[c] / sqrt(var + 1e-5);
        g_scales[layer*C512 + c] = (float)scd;
        g_shifts[layer*C512 + c] = beta[c] - (float)(mean * scd);
        sscale = (float)scd;
        sshift = beta[c] - (float)(mean * scd);
    }
    __syncthreads();
    float sc = sscale, sh = sshift;
    for (int b = 0; b < BATCH; b++) {
        const float* ip = buf + ((size_t)(b*C512 + c))*L;
        __nv_bfloat16* oh = Oh + ((size_t)(b*C512 + c))*Lpad;
        __nv_bfloat16* ol = Ol + ((size_t)(b*C512 + c))*Lpad;
        int tsb = MASK ? __ldg(ts + b) : 0;
        for (int qq = tid; qq < Lpad; qq += 256) {
            int p = qq - shift;
            float v = 0.f;
            if (p >= 0 && p < L) {
                bool ok = !MASK || (p <= tsb);
                if (ok) v = fmaxf(ip[p]*sc + sh, 0.f);
            }
            __nv_bfloat16 hb = __float2bfloat16(v);
            oh[qq] = hb;
            ol[qq] = __float2bfloat16(v - __bfloat162float(hb));
        }
    }
}

// ================= mma.sync / ldmatrix helpers =================
#define MMA16816(d, a, b) \
    asm volatile( \
        "mma.sync.aligned.m16n8k16.row.col.f32.bf16.bf16.f32 " \
        "{%0,%1,%2,%3}, {%4,%5,%6,%7}, {%8,%9}, {%0,%1,%2,%3};" \
        : "+f"((d)[0]), "+f"((d)[1]), "+f"((d)[2]), "+f"((d)[3]) \
        : "r"((a)[0]), "r"((a)[1]), "r"((a)[2]), "r"((a)[3]), \
          "r"((b)[0]), "r"((b)[1]))

#define LDSM4(r0, r1, r2, r3, addr) \
    asm volatile("ldmatrix.sync.aligned.m8n8.x4.shared.b16 {%0,%1,%2,%3}, [%4];" \
        : "=r"(r0), "=r"(r1), "=r"(r2), "=r"(r3) : "r"(addr))

static __device__ __forceinline__ void cpa4(uint32_t dst, const void* src, uint32_t sz) {
    asm volatile("cp.async.ca.shared.global [%0], [%1], 4, %2;"
                 :: "r"(dst), "l"(src), "r"(sz) : "memory");
}
static __device__ __forceinline__ void cpa8(uint32_t dst, const void* src, uint32_t sz) {
    asm volatile("cp.async.ca.shared.global [%0], [%1], 8, %2;"
                 :: "r"(dst), "l"(src), "r"(sz) : "memory");
}
static __device__ __forceinline__ void cpa16(uint32_t dst, const void* src) {
    asm volatile("cp.async.cg.shared.global [%0], [%1], 16;"
                 :: "r"(dst), "l"(src) : "memory");
}

// ================= pipelined bf16 conv-as-GEMM (cp.async + ldmatrix, 2 CTAs/SM) ======
#define STG_ELEMS 20480
#define DYN_SMEM  (2*STG_ELEMS*2)

template<int KW, int S, int P, int SHIFT>
__global__ void __launch_bounds__(256, 2) mmaconv_bf_kernel(
    const __nv_bfloat16* __restrict__ Inh, const __nv_bfloat16* __restrict__ Inl,
    const __nv_bfloat16* __restrict__ Wh,  const __nv_bfloat16* __restrict__ Wl,
    float* __restrict__ Out,
    int Lpad, int O, int Lout, int Kd, int Ntot)
{
    extern __shared__ __align__(16) __nv_bfloat16 dyn[];
    const int tid  = threadIdx.x;
    const int lane = tid & 31, w = tid >> 5;
    const int wm = (w >> 2) * 64, wn = (w & 3) * 32;
    const int m0 = blockIdx.x * 128, n0 = blockIdx.y * 128;
    const int g = lane >> 2, tig = lane & 3;
    const int C = Kd >> 5;

    const int lq = lane >> 3, lr = lane & 7;
    const int a_loff = ((lq & 1)*8 + lr)*40 + (lq >> 1)*8;
    const int b_loff = ((lq >> 1)*8 + lr)*40 + (lq & 1)*8;

    const int ITS = 16 / KW;
    const int bnn = tid & 127;
    const int clbase = tid >> 7;
    int bq;
    uint32_t bsz4, bsz8;
    {
        int n = n0 + bnn;
        bool vn = (n < Ntot);
        int nv = vn ? n : 0;
        int b = nv / Lout, t = nv - b*Lout;
        bsz4 = vn ? 4u : 0u;
        bsz8 = vn ? 8u : 0u;
        bq = (b*C512)*Lpad + S*t - P + SHIFT;
    }
    const int arow = tid >> 1, ahalf = tid & 1;

    auto load_chunk = [&](int c, int s) {
        __nv_bfloat16* stg = dyn + s*STG_ELEMS;
        const int k0 = c << 5;
        {
            const __nv_bfloat16* srcH = Wh + (size_t)(m0 + arow)*Kd + k0 + ahalf*16;
            const __nv_bfloat16* srcL = Wl + (size_t)(m0 + arow)*Kd + k0 + ahalf*16;
            uint32_t dH = smem_u32(stg + 10240 + arow*40 + ahalf*16);
            uint32_t dL = smem_u32(stg + 15360 + arow*40 + ahalf*16);
            cpa16(dH, srcH);      cpa16(dH + 16, srcH + 8);
            cpa16(dL, srcL);      cpa16(dL + 16, srcL + 8);
        }
        {
            const int c0 = k0 / KW;
#pragma unroll
            for (int it = 0; it < ITS; it++) {
                int cl = it*2 + clbase;
                int srcbase = bq + (c0 + cl)*Lpad;
                uint32_t dH = smem_u32(stg +        bnn*40 + cl*KW);
                uint32_t dL = smem_u32(stg + 5120 + bnn*40 + cl*KW);
                if (KW == 8) {
                    cpa8(dH,     Inh + srcbase,     bsz8);
                    cpa8(dH + 8, Inh + srcbase + 4, bsz8);
                    cpa8(dL,     Inl + srcbase,     bsz8);
                    cpa8(dL + 8, Inl + srcbase + 4, bsz8);
                } else {
#pragma unroll
                    for (int j = 0; j < KW/2; j++) {
                        cpa4(dH + j*4, Inh + srcbase + 2*j, bsz4);
                        cpa4(dL + j*4, Inl + srcbase + 2*j, bsz4);
                    }
                }
            }
        }
        asm volatile("cp.async.commit_group;" ::: "memory");
    };

    float acc[4][4][4];
#pragma unroll
    for (int i = 0; i < 4; i++)
#pragma unroll
        for (int j = 0; j < 4; j++)
#pragma unroll
            for (int q = 0; q < 4; q++) acc[i][j][q] = 0.f;

    load_chunk(0, 0);

    for (int c = 0; c < C; c++) {
        const int s = c & 1;
        if (c + 1 < C) {
            load_chunk(c + 1, s ^ 1);
            asm volatile("cp.async.wait_group 1;" ::: "memory");
        } else {
            asm volatile("cp.async.wait_group 0;" ::: "memory");
        }
        __syncthreads();

        const __nv_bfloat16* stg = dyn + s*STG_ELEMS;
        const uint32_t uBh = smem_u32(stg)         + (wn*40 + b_loff)*2;
        const uint32_t uBl = smem_u32(stg + 5120)  + (wn*40 + b_loff)*2;
        const uint32_t uAh = smem_u32(stg + 10240) + (wm*40 + a_loff)*2;
        const uint32_t uAl = smem_u32(stg + 15360) + (wm*40 + a_loff)*2;

#pragma unroll
        for (int ks = 0; ks < 32; ks += 16) {
            uint32_t ah[4][4], al[4][4], bh[4][2], bl[4][2];
#pragma unroll
            for (int mt = 0; mt < 4; mt++) {
                LDSM4(ah[mt][0], ah[mt][1], ah[mt][2], ah[mt][3], uAh + (mt*640 + ks)*2);
                LDSM4(al[mt][0], al[mt][1], al[mt][2], al[mt][3], uAl + (mt*640 + ks)*2);
            }
            LDSM4(bh[0][0], bh[0][1], bh[1][0], bh[1][1], uBh + ks*2);
            LDSM4(bh[2][0], bh[2][1], bh[3][0], bh[3][1], uBh + (640 + ks)*2);
            LDSM4(bl[0][0], bl[0][1], bl[1][0], bl[1][1], uBl + ks*2);
            LDSM4(bl[2][0], bl[2][1], bl[3][0], bl[3][1], uBl + (640 + ks)*2);
#pragma unroll
            for (int mt = 0; mt < 4; mt++)
#pragma unroll
                for (int nt = 0; nt < 4; nt++) MMA16816(acc[mt][nt], ah[mt], bh[nt]);
#pragma unroll
            for (int mt = 0; mt < 4; mt++)
#pragma unroll
                for (int nt = 0; nt < 4; nt++) MMA16816(acc[mt][nt], al[mt], bh[nt]);
#pragma unroll
            for (int mt = 0; mt < 4; mt++)
#pragma unroll
                for (int nt = 0; nt < 4; nt++) MMA16816(acc[mt][nt], ah[mt], bl[nt]);
        }
        __syncthreads();
    }

    // ---- epilogue: global stores ----
#pragma unroll
    for (int mt = 0; mt < 4; mt++) {
        int r = m0 + wm + mt*16 + g;
#pragma unroll
        for (int nt = 0; nt < 4; nt++) {
            int cc = n0 + wn + nt*8 + tig*2;
#pragma unroll
            for (int q = 0; q < 4; q++) {
                int n  = cc + (q & 1);
                int rr = r + (q >> 1)*8;
                if (n < Ntot) {
                    int b = n / Lout, t = n - b*Lout;
                    Out[((size_t)(b*O + rr))*Lout + t] = acc[mt][nt][q];
                }
            }
        }
    }

    // ---- epilogue: BN partial sums (invalid-n accs are exact zeros) ----
    {
        float s1[8], s2[8];
#pragma unroll
        for (int i = 0; i < 8; i++) { s1[i] = 0.f; s2[i] = 0.f; }
#pragma unroll
        for (int mt = 0; mt < 4; mt++)
#pragma unroll
            for (int nt = 0; nt < 4; nt++)
#pragma unroll
                for (int q = 0; q < 4; q++) {
                    int ri = mt*2 + (q >> 1);
                    float v = acc[mt][nt][q];
                    s1[ri] += v;
                    s2[ri] += v*v;
                }
#pragma unroll
        for (int i = 0; i < 8; i++) {
            s1[i] += __shfl_xor_sync(0xffffffffu, s1[i], 1);
            s1[i] += __shfl_xor_sync(0xffffffffu, s1[i], 2);
            s2[i] += __shfl_xor_sync(0xffffffffu, s2[i], 1);
            s2[i] += __shfl_xor_sync(0xffffffffu, s2[i], 2);
        }
        float* sp = (float*)dyn;   // [128][4] sums | [128][4] sq = 4KB
        if (tig == 0) {
#pragma unroll
            for (int mt = 0; mt < 4; mt++)
#pragma unroll
                for (int h = 0; h < 2; h++) {
                    int row = wm + mt*16 + g + h*8;
                    sp[row*4 + (w & 3)]       = s1[mt*2 + h];
                    sp[512 + row*4 + (w & 3)] = s2[mt*2 + h];
                }
        }
        __syncthreads();
        if (tid < 128) {
            float a = sp[tid*4] + sp[tid*4+1] + sp[tid*4+2] + sp[tid*4+3];
            float b = sp[512 + tid*4] + sp[512 + tid*4+1] + sp[512 + tid*4+2] + sp[512 + tid*4+3];
            g_psum[blockIdx.y*C512 + m0 + tid] = a;
            g_psq [blockIdx.y*C512 + m0 + tid] = b;
        }
    }
}

// ================= mmaconv for gi (KW=1, reads pre-masked bf16) =================
#define SMSTRIDE 34
__global__ void __launch_bounds__(256, 2) mmaconv_gi_kernel(
    const __nv_bfloat16* __restrict__ Inh, const __nv_bfloat16* __restrict__ Inl,
    const __nv_bfloat16* __restrict__ Wh,  const __nv_bfloat16* __restrict__ Wl,
    float* __restrict__ Out,
    int Cin, int Lin, int O, int Lout, int Kd, int Ntot)
{
    __shared__ __nv_bfloat16 sAh[128][SMSTRIDE];
    __shared__ __nv_bfloat16 sAl[128][SMSTRIDE];
    __shared__ __nv_bfloat16 sBh[128][SMSTRIDE];
    __shared__ __nv_bfloat16 sBl[128][SMSTRIDE];
    const int tid  = threadIdx.x;
    const int lane = tid & 31, w = tid >> 5;
    const int wm = (w >> 2) * 64, wn = (w & 3) * 32;
    const int m0 = blockIdx.x * 128, n0 = blockIdx.y * 128;
    const int g = lane >> 2, tig = lane & 3;
    const int arow = tid >> 1, ak0 = (tid & 1) * 16;
    const int nchunks = Kd >> 5;

    float acc[4][4][4];
#pragma unroll
    for (int i = 0; i < 4; i++)
#pragma unroll
        for (int j = 0; j < 4; j++)
#pragma unroll
            for (int q = 0; q < 4; q++) acc[i][j][q] = 0.f;

    for (int c = 0; c < nchunks; c++) {
        const int k0 = c << 5;
        {
            const size_t go = (size_t)(m0 + arow)*Kd + k0 + ak0;
            uint4 ha = *(const uint4*)(Wh + go);
            uint4 hb = *(const uint4*)(Wh + go + 8);
            uint4 la = *(const uint4*)(Wl + go);
            uint4 lb = *(const uint4*)(Wl + go + 8);
            uint32_t* dh = (uint32_t*)&sAh[arow][ak0];
            uint32_t* dl = (uint32_t*)&sAl[arow][ak0];
            dh[0]=ha.x; dh[1]=ha.y; dh[2]=ha.z; dh[3]=ha.w;
            dh[4]=hb.x; dh[5]=hb.y; dh[6]=hb.z; dh[7]=hb.w;
            dl[0]=la.x; dl[1]=la.y; dl[2]=la.z; dl[3]=la.w;
            dl[4]=lb.x; dl[5]=lb.y; dl[6]=lb.z; dl[7]=lb.w;
        }
        {
#pragma unroll
            for (int it = 0; it < 16; it++) {
                int idx = it*256 + tid;
                int nn = idx & 127;
                int cl = idx >> 7;
                int cch = k0 + cl;
                int n = n0 + nn;
                bool vn = (n < Ntot);
                __nv_bfloat16 hv, lv;
                *(uint16_t*)&hv = 0; *(uint16_t*)&lv = 0;
                if (vn) {
                    int b = n / Lout, t = n - b*Lout;
                    size_t off = ((size_t)(b*Cin + cch))*Lin + t;
                    hv = __ldg(Inh + off);
                    lv = __ldg(Inl + off);
                }
                sBh[nn][cl] = hv;
                sBl[nn][cl] = lv;
            }
        }
        __syncthreads();
#pragma unroll
        for (int ks = 0; ks < 32; ks += 16) {
            const int cb = ks + tig*2;
            uint32_t ah[4][4], al[4][4], bh[4][2];
#pragma unroll
            for (int mt = 0; mt < 4; mt++) {
                int r = wm + mt*16 + g;
                ah[mt][0] = *(const uint32_t*)&sAh[r][cb];
                ah[mt][1] = *(const uint32_t*)&sAh[r+8][cb];
                ah[mt][2] = *(const uint32_t*)&sAh[r][cb+8];
                ah[mt][3] = *(const uint32_t*)&sAh[r+8][cb+8];
                al[mt][0] = *(const uint32_t*)&sAl[r][cb];
                al[mt][1] = *(const uint32_t*)&sAl[r+8][cb];
                al[mt][2] = *(const uint32_t*)&sAl[r][cb+8];
                al[mt][3] = *(const uint32_t*)&sAl[r+8][cb+8];
            }
#pragma unroll
            for (int nt = 0; nt < 4; nt++) {
                int rn = wn + nt*8 + g;
                bh[nt][0] = *(const uint32_t*)&sBh[rn][cb];
                bh[nt][1] = *(const uint32_t*)&sBh[rn][cb+8];
            }
#pragma unroll
            for (int mt = 0; mt < 4; mt++)
#pragma unroll
                for (int nt = 0; nt < 4; nt++) MMA16816(acc[mt][nt], ah[mt], bh[nt]);
#pragma unroll
            for (int mt = 0; mt < 4; mt++)
#pragma unroll
                for (int nt = 0; nt < 4; nt++) MMA16816(acc[mt][nt], al[mt], bh[nt]);
            uint32_t bl[4][2];
#pragma unroll
            for (int nt = 0; nt < 4; nt++) {
                int rn = wn + nt*8 + g;
                bl[nt][0] = *(const uint32_t*)&sBl[rn][cb];
                bl[nt][1] = *(const uint32_t*)&sBl[rn][cb+8];
            }
#pragma unroll
            for (int mt = 0; mt < 4; mt++)
#pragma unroll
                for (int nt = 0; nt < 4; nt++) MMA16816(acc[mt][nt], ah[mt], bl[nt]);
        }
        __syncthreads();
    }
#pragma unroll
    for (int mt = 0; mt < 4; mt++) {
        int r = m0 + wm + mt*16 + g;
#pragma unroll
        for (int nt = 0; nt < 4; nt++) {
            int cc = n0 + wn + nt*8 + tig*2;
#pragma unroll
            for (int q = 0; q < 4; q++) {
                int n  = cc + (q & 1);
                int rr = r + (q >> 1)*8;
                if (n < Ntot) {
                    int b = n / Lout, t = n - b*Lout;
                    Out[((size_t)b*Lout + t)*O + rr] = acc[mt][nt][q];
                }
            }
        }
    }
}

// ================= GRU: 8-CTA cluster per batch, DSMEM h exchange =================
static __device__ __forceinline__ void dsmem_store(uint32_t laddr, uint32_t rank, float v) {
    uint32_t dst;
    asm volatile("mapa.shared::cluster.u32 %0, %1, %2;" : "=r"(dst) : "r"(laddr), "r"(rank));
    asm volatile("st.shared::cluster.f32 [%0], %1;" :: "r"(dst), "f"(v) : "memory");
}
#define CLUSTER_SYNC() do { \
    asm volatile("barrier.cluster.arrive.aligned;" ::: "memory"); \
    asm volatile("barrier.cluster.wait.aligned;" ::: "memory"); } while(0)

__global__ void __cluster_dims__(8,1,1) gru_kernel(
    const float* __restrict__ gi, const float* __restrict__ whh,
    const float* __restrict__ bih, const float* __restrict__ bhh,
    const int* __restrict__ ts, const float* __restrict__ hidden,
    float* __restrict__ out)
{
    extern __shared__ float smg[];
    float* Ws   = smg;
    float* hs   = smg + 96*256;
    float* gh_s = hs + 512;
    uint32_t rank;
    asm("mov.u32 %0, %%cluster_ctarank;" : "=r"(rank));
    int b  = blockIdx.x >> 3;
    int j0 = rank * 32;
    int tid = threadIdx.x;
    int warp = tid >> 5, lane = tid & 31;

    for (int e = tid; e < 96*256; e += 128) {
        int gate = e >> 13;
        int rem  = e & 8191;
        int j    = rem >> 8;
        int k    = rem & 255;
        Ws[((gate*64 + (k>>2))*32 + j)*4 + (k&3)] = whh[((size_t)(gate*256 + j0 + j))*256 + k];
    }
    for (int e = tid; e < HID; e += 128) hs[e] = hidden[b*HID + e];
    int tsb = ts[b];
    float bihr=0.f,bihz=0.f,bihn=0.f,bhhr=0.f,bhhz=0.f,bhhn=0.f;
    if (warp == 0) {
        bihr = bih[j0+lane]; bihz = bih[256+j0+lane]; bihn = bih[512+j0+lane];
        bhhr = bhh[j0+lane]; bhhz = bhh[256+j0+lane]; bhhn = bhh[512+j0+lane];
    }
    __syncthreads();
    CLUSTER_SYNC();

    for (int t = 0; t < L5; t++) {
        const float* hcur = hs + (t & 1)*256;
        if (warp < 3) {
            const float4* wp = (const float4*)Ws + warp*2048 + lane;
            const float4* hp = (const float4*)hcur;
            float acc = 0.f;
#pragma unroll
            for (int k4 = 0; k4 < 64; k4++) {
                float4 w = wp[k4*32];
                float4 h = hp[k4];
                acc += w.x*h.x + w.y*h.y + w.z*h.z + w.w*h.w;
            }
            gh_s[warp*32 + lane] = acc;
        }
        __syncthreads();
        if (warp == 0) {
            int j = j0 + lane;
            const float* gb = gi + ((size_t)b*L5 + t)*G3;
            float gir = gb[j]       + bihr;
            float giz = gb[256 + j] + bihz;
            float gin = gb[512 + j] + bihn;
            float ghr = gh_s[lane]    + bhhr;
            float ghz = gh_s[32+lane] + bhhz;
            float ghn = gh_s[64+lane] + bhhn;
            float r   = 1.f/(1.f + expf(-(gir+ghr)));
            float zg  = 1.f/(1.f + expf(-(giz+ghz)));
            float n   = tanhf(gin + r*ghn);
            float hold = hcur[j];
            float hnew = (1.f - zg)*n + zg*hold;
            uint32_t laddr = smem_u32(hs + ((t+1)&1)*256 + j);
#pragma unroll
            for (int r2 = 0; r2 < 8; r2++) dsmem_store(laddr, (uint32_t)r2, hnew);
            if (t == tsb)   g_ct[b*HID + j] = hnew;
            if (t == L5-1)  out[2 + b*HID + j] = hnew;
        }
        CLUSTER_SYNC();
    }
}

// ================= head =================
__global__ void enc_kernel(const int* __restrict__ ts) {
    int idx = blockIdx.x*blockDim.x + threadIdx.x;
    if (idx >= KSTEP*BATCH*C512) return;
    int d = idx & 511;
    int b = (idx >> 9) & 15;
    int k = idx >> 13;
    int t = ts[b] + k + 1;
    float v = g_buf5[((size_t)b*C512 + d)*L5 + t];
    g_enc[idx] = fmaxf(v*g_scales[4*C512 + d] + g_shifts[4*C512 + d], 0.f);
}

__global__ void pred_kernel(const float* __restrict__ wkw, const float* __restrict__ wkb) {
    int k = blockIdx.x >> 4;
    int b = blockIdx.x & 15;
    __shared__ float cs[HID];
    if (threadIdx.x < HID) cs[threadIdx.x] = g_ct[b*HID + threadIdx.x];
    __syncthreads();
    int d = threadIdx.x;
    const float* wr = wkw + ((size_t)k*C512 + d)*HID;
    float acc = wkb[k*C512 + d];
#pragma unroll 8
    for (int h = 0; h < HID; h++) acc += cs[h]*wr[h];
    g_pred[(k*BATCH + b)*C512 + d] = acc;
}

__global__ void total_kernel() {
    int k = blockIdx.x >> 4;
    int b = blockIdx.x & 15;
    int c = threadIdx.x;
    if (c < BATCH) {
        const float* e = g_enc  + ((size_t)(k*BATCH + b))*C512;
        const float* p = g_pred + ((size_t)(k*BATCH + c))*C512;
        float acc = 0.f;
        for (int d = 0; d < C512; d++) acc += e[d]*p[d];
        g_total[(k*BATCH + b)*BATCH + c] = acc;
    }
}

__global__ void final_kernel(float* __restrict__ out) {
    __shared__ float red[192];
    __shared__ float lse11[16];
    __shared__ float corr[16];
    int tid = threadIdx.x;
    int k = tid >> 4, b = tid & 15;
    float contrib;
    {
        const float* row = g_total + tid*16;
        float mx = row[0];
        for (int c = 1; c < 16; c++) mx = fmaxf(mx, row[c]);
        float s = 0.f;
        for (int c = 0; c < 16; c++) s += expf(row[c]-mx);
        float lse = mx + logf(s);
        contrib = row[b] - lse;
        if (k == KSTEP-1) lse11[b] = lse;
    }
    red[tid] = contrib;
    __syncthreads();
    if (tid < 16) {
        int c = tid;
        const float* t11 = g_total + (KSTEP-1)*BATCH*BATCH;
        float best = -1e30f; int arg = -1;
        for (int bb = 0; bb < 16; bb++) {
            float v = expf(t11[bb*16 + c] - lse11[bb]);
            if (v > best) { best = v; arg = bb; }
        }
        corr[c] = (arg == c) ? 1.f : 0.f;
    }
    __syncthreads();
    if (tid == 0) {
        float s = 0.f;
        for (int i = 0; i < 192; i++) s += red[i];
        out[1] = s / (-1.f * BATCH * KSTEP);
        float a = 0.f;
        for (int i = 0; i < 16; i++) a += corr[i];
        out[0] = a / (float)BATCH;
    }
}

// ================= host =================
extern "C" void kernel_launch(void* const* d_in, const int* in_sizes, int n_in,
                              void* d_out, int out_size) {
    const float* x      = (const float*)d_in[0];
    const float* hidden = (const float*)d_in[1];
    const int*   ts     = (const int*)d_in[3];
    const float* w1     = (const float*)d_in[4];
    const float* w2     = (const float*)d_in[5];
    const float* w345   = (const float*)d_in[6];
    const float* gamma  = (const float*)d_in[7];
    const float* beta   = (const float*)d_in[8];
    const float* wih    = (const float*)d_in[9];
    const float* whh    = (const float*)d_in[10];
    const float* bih    = (const float*)d_in[11];
    const float* bhh    = (const float*)d_in[12];
    const float* wkw    = (const float*)d_in[13];
    const float* wkb    = (const float*)d_in[14];
    float* out = (float*)d_out;

    float *buf1, *buf2, *buf3, *buf4, *buf5, *gi;
    __nv_bfloat16 *wh, *wl, *a1h, *a1l, *a2h, *a2l, *a3h, *a3l, *a4h, *a4l, *a5h, *a5l;
    cudaGetSymbolAddress((void**)&buf1, g_buf1);
    cudaGetSymbolAddress((void**)&buf2, g_buf2);
    cudaGetSymbolAddress((void**)&buf3, g_buf3);
    cudaGetSymbolAddress((void**)&buf4, g_buf4);
    cudaGetSymbolAddress((void**)&buf5, g_buf5);
    cudaGetSymbolAddress((void**)&gi,   g_gi);
    cudaGetSymbolAddress((void**)&wh,   g_wh);
    cudaGetSymbolAddress((void**)&wl,   g_wl);
    cudaGetSymbolAddress((void**)&a1h,  g_a1h);
    cudaGetSymbolAddress((void**)&a1l,  g_a1l);
    cudaGetSymbolAddress((void**)&a2h,  g_a2h);
    cudaGetSymbolAddress((void**)&a2l,  g_a2l);
    cudaGetSymbolAddress((void**)&a3h,  g_a3h);
    cudaGetSymbolAddress((void**)&a3l,  g_a3l);
    cudaGetSymbolAddress((void**)&a4h,  g_a4h);
    cudaGetSymbolAddress((void**)&a4l,  g_a4l);
    cudaGetSymbolAddress((void**)&a5h,  g_a5h);
    cudaGetSymbolAddress((void**)&a5l,  g_a5l);

    cudaFuncSetAttribute(mmaconv_bf_kernel<8,4,2,2>, cudaFuncAttributeMaxDynamicSharedMemorySize, DYN_SMEM);
    cudaFuncSetAttribute(mmaconv_bf_kernel<4,2,1,1>, cudaFuncAttributeMaxDynamicSharedMemorySize, DYN_SMEM);

    // [0] prep (conv1 with bn0 partials + wcvt)
    prep_kernel<<<512 + (WCVT_N + 255)/256, 256>>>(x, w1, w2, w345, wih);
    // [1] bn0 reduce  [2] actcvt L1
    bn0reduce_kernel<<<2, 256>>>(gamma, beta);
    actcvt_kernel<<<(BATCH*C512*L1P/2 + 255)/256, 256>>>(buf1, a1h, a1l, 0, L1, L1P, 2, BATCH*C512*L1P/2);
    // [3] conv2 (PROFILED)
    mmaconv_bf_kernel<8,4,2,2><<<dim3(4,500), 256, DYN_SMEM>>>(a1h, a1l, wh + WOFF2, wl + WOFF2, buf2, L1P, 512, L2, 4096, BATCH*L2);
    bncvt_kernel<false><<<C512, 256>>>(buf2, a2h, a2l, gamma + 1*C512, beta + 1*C512, 1, L2, L2P, 1, 500, ts);

    mmaconv_bf_kernel<4,2,1,1><<<dim3(4,250), 256, DYN_SMEM>>>(a2h, a2l, wh + WOFF3, wl + WOFF3, buf3, L2P, 512, L3, 2048, BATCH*L3);
    bncvt_kernel<false><<<C512, 256>>>(buf3, a3h, a3l, gamma + 2*C512, beta + 2*C512, 2, L3, L3P, 1, 250, ts);

    mmaconv_bf_kernel<4,2,1,1><<<dim3(4,125), 256, DYN_SMEM>>>(a3h, a3l, wh + WOFF4, wl + WOFF4, buf4, L3P, 512, L4, 2048, BATCH*L4);
    bncvt_kernel<false><<<C512, 256>>>(buf4, a4h, a4l, gamma + 3*C512, beta + 3*C512, 3, L4, L4P, 1, 125, ts);

    mmaconv_bf_kernel<4,2,1,1><<<dim3(4,63), 256, DYN_SMEM>>>(a4h, a4l, wh + WOFF5, wl + WOFF5, buf5, L4P, 512, L5, 2048, BATCH*L5);
    // bn4 stats + masked z for gi (no pad, shift 0)
    bncvt_kernel<true><<<C512, 256>>>(buf5, a5h, a5l, gamma + 4*C512, beta + 4*C512, 4, L5, L5, 0, 63, ts);

    // gi = Wih . masked z  (pre-split bf16 path, [b][t][g] out)
    mmaconv_gi_kernel<<<dim3(6,63), 256>>>(a5h, a5l, wh + WOFFIH, wl + WOFFIH, gi, 512, L5, G3, L5, 512, BATCH*L5);

    // GRU
    int smg = (96*256 + 512 + 96) * (int)sizeof(float);
    cudaFuncSetAttribute(gru_kernel, cudaFuncAttributeMaxDynamicSharedMemorySize, smg);
    gru_kernel<<<128, 128, smg>>>(gi, whh, bih, bhh, ts, hidden, out);

    // head
    enc_kernel<<<(KSTEP*BATCH*C512 + 255)/256, 256>>>(ts);
    pred_kernel<<<KSTEP*BATCH, 512>>>(wkw, wkb);
    total_kernel<<<KSTEP*BATCH, 32>>>();
    final_kernel<<<1, 192>>>(out);
}